// round 4
// baseline (speedup 1.0000x reference)
#include <cuda_runtime.h>
#include <math.h>

// ---------------- scratch (device globals; no runtime allocation) ----------------
static __device__ float g_x1[4096 * 64];          //  1 MB
static __device__ float g_x2[4096 * 256];         //  4 MB
static __device__ float g_x3[4096 * 1024];        // 16 MB
static __device__ float g_x4[4096 * 4096];        // 64 MB  == (B, C=64, N=64)
static __device__ float g_t1[4096 * 128 * 64];    // 128 MB
static __device__ float g_t2[4096 * 256 * 64];    // 256 MB

__device__ __forceinline__ float leaky(float v) { return v > 0.f ? v : 0.01f * v; }

// ---------------- MLP GEMM: C = leaky(A(M,K) * W(N,K)^T + bias) ----------------
// BM=128, BN=64, BK=16, thread tile 8x8, 128 threads. M=4096, K%16==0, N%64==0.
__global__ void __launch_bounds__(128)
gemm_bias_leaky(const float* __restrict__ A, const float* __restrict__ W,
                const float* __restrict__ bias, float* __restrict__ C,
                int K, int N)
{
    __shared__ float As[16][128];
    __shared__ float Ws[16][64];

    const int tid = threadIdx.x;
    const int mt = tid & 15;      // 0..15 -> m tile (8 rows)
    const int nt = tid >> 4;      // 0..7  -> n tile (8 cols)

    const float* Ab = A + (size_t)blockIdx.x * 128 * K;
    const float* Wb = W + (size_t)blockIdx.y * 64 * K;

    float acc[8][8] = {};

    for (int k0 = 0; k0 < K; k0 += 16) {
        // load A tile (128 x 16), transposed into As[k][m]
        #pragma unroll
        for (int i = 0; i < 4; i++) {
            int lin = tid + i * 128;
            int r = lin >> 2, c4 = lin & 3;
            float4 v = *(const float4*)(Ab + (size_t)r * K + k0 + c4 * 4);
            As[c4 * 4 + 0][r] = v.x;
            As[c4 * 4 + 1][r] = v.y;
            As[c4 * 4 + 2][r] = v.z;
            As[c4 * 4 + 3][r] = v.w;
        }
        // load W tile (64 x 16), transposed into Ws[k][n]
        #pragma unroll
        for (int i = 0; i < 2; i++) {
            int lin = tid + i * 128;
            int r = lin >> 2, c4 = lin & 3;
            float4 v = *(const float4*)(Wb + (size_t)r * K + k0 + c4 * 4);
            Ws[c4 * 4 + 0][r] = v.x;
            Ws[c4 * 4 + 1][r] = v.y;
            Ws[c4 * 4 + 2][r] = v.z;
            Ws[c4 * 4 + 3][r] = v.w;
        }
        __syncthreads();

        #pragma unroll
        for (int kk = 0; kk < 16; kk++) {
            float a[8], w[8];
            *(float4*)&a[0] = *(const float4*)&As[kk][mt * 8];
            *(float4*)&a[4] = *(const float4*)&As[kk][mt * 8 + 4];
            *(float4*)&w[0] = *(const float4*)&Ws[kk][nt * 8];
            *(float4*)&w[4] = *(const float4*)&Ws[kk][nt * 8 + 4];
            #pragma unroll
            for (int i = 0; i < 8; i++)
                #pragma unroll
                for (int j = 0; j < 8; j++)
                    acc[i][j] = fmaf(a[i], w[j], acc[i][j]);
        }
        __syncthreads();
    }

    float bv[8];
    #pragma unroll
    for (int j = 0; j < 8; j++) bv[j] = __ldg(&bias[blockIdx.y * 64 + nt * 8 + j]);

    #pragma unroll
    for (int i = 0; i < 8; i++) {
        size_t row = (size_t)(blockIdx.x * 128 + mt * 8 + i) * N + blockIdx.y * 64 + nt * 8;
        float4 o0, o1;
        o0.x = leaky(acc[i][0] + bv[0]); o0.y = leaky(acc[i][1] + bv[1]);
        o0.z = leaky(acc[i][2] + bv[2]); o0.w = leaky(acc[i][3] + bv[3]);
        o1.x = leaky(acc[i][4] + bv[4]); o1.y = leaky(acc[i][5] + bv[5]);
        o1.z = leaky(acc[i][6] + bv[6]); o1.w = leaky(acc[i][7] + bv[7]);
        *(float4*)&C[row]     = o0;
        *(float4*)&C[row + 4] = o1;
    }
}

// ---------------- fused tree_conv + bias + LayerNorm + LeakyReLU ----------------
// One CTA per sample. THREADS == O. Thread tile: 8 outputs (o strided by OT) x 8 nodes.
// smem: xs[C*64] | ws[24*O] (8-channel W chunk) | idxs[192] | red[64]
template <int C, int O>
__global__ void __launch_bounds__(O, 1)
conv_ln(const float* __restrict__ xin, const int* __restrict__ idxg,
        const float* __restrict__ w, const float* __restrict__ bias,
        float* __restrict__ out)
{
    constexpr int OT = O / 8;
    extern __shared__ float sm[];
    float* xs   = sm;                       // C*64 floats
    float* ws   = xs + C * 64;              // 24*O floats
    int*   idxs = (int*)(ws + 24 * O);      // 192 ints
    float* red  = (float*)(idxs + 192);     // 64 floats

    const int tid = threadIdx.x;
    const int b   = blockIdx.x;
    const int ot  = tid % OT;
    const int nt  = tid / OT;

    for (int i = tid; i < 189; i += O) idxs[i] = idxg[(size_t)b * 189 + i];
    {
        const float4* xi = (const float4*)(xin + (size_t)b * (C * 64));
        float4* xd = (float4*)xs;
        for (int i = tid; i < C * 16; i += O) xd[i] = xi[i];
    }
    __syncthreads();

    // per-thread gather indices for its 8 nodes (node 63 is a pad lane)
    int off[3][8];
    #pragma unroll
    for (int j = 0; j < 8; j++) {
        int node = nt * 8 + j;
        int base = (node < 63) ? 3 * node : 0;
        off[0][j] = idxs[base];
        off[1][j] = idxs[base + 1];
        off[2][j] = idxs[base + 2];
    }

    float acc[8][8] = {};

    const float4* wg = (const float4*)(w + (size_t)tid * (3 * C)); // row o = tid
    for (int c0 = 0; c0 < C; c0 += 8) {
        __syncthreads();
        // stage W chunk: channels [c0, c0+8), all O rows -> ws[(cc*3+kk)][o]
        #pragma unroll
        for (int q = 0; q < 6; q++) {
            float4 v = wg[(c0 * 3) / 4 + q];
            int l = q * 4;
            ws[(l + 0) * O + tid] = v.x;
            ws[(l + 1) * O + tid] = v.y;
            ws[(l + 2) * O + tid] = v.z;
            ws[(l + 3) * O + tid] = v.w;
        }
        __syncthreads();

        #pragma unroll 2
        for (int cc = 0; cc < 8; cc++) {
            int cb = (c0 + cc) * 64;
            #pragma unroll
            for (int kk = 0; kk < 3; kk++) {
                const float* wr = ws + (cc * 3 + kk) * O + ot;
                float wv[8], ev[8];
                #pragma unroll
                for (int i = 0; i < 8; i++) wv[i] = wr[i * OT];      // conflict-free LDS
                #pragma unroll
                for (int j = 0; j < 8; j++) ev[j] = xs[cb + off[kk][j]]; // warp broadcast
                #pragma unroll
                for (int i = 0; i < 8; i++)
                    #pragma unroll
                    for (int j = 0; j < 8; j++)
                        acc[i][j] = fmaf(wv[i], ev[j], acc[i][j]);
            }
        }
    }

    // bias + local LN stats (zero column 0 contributes nothing to sums)
    float bv[8];
    #pragma unroll
    for (int i = 0; i < 8; i++) bv[i] = __ldg(&bias[ot + i * OT]);

    float s = 0.f, ss = 0.f;
    #pragma unroll
    for (int i = 0; i < 8; i++)
        #pragma unroll
        for (int j = 0; j < 8; j++) {
            float v = acc[i][j] + bv[i];
            acc[i][j] = v;
            if (nt * 8 + j < 63) { s += v; ss += v * v; }
        }

    const int lane = tid & 31, warp = tid >> 5;
    #pragma unroll
    for (int sh = 16; sh; sh >>= 1) {
        s  += __shfl_down_sync(0xffffffffu, s,  sh);
        ss += __shfl_down_sync(0xffffffffu, ss, sh);
    }
    if (lane == 0) { red[2 * warp] = s; red[2 * warp + 1] = ss; }
    __syncthreads();
    if (tid == 0) {
        float S = 0.f, SS = 0.f;
        for (int wi = 0; wi < O / 32; wi++) { S += red[2 * wi]; SS += red[2 * wi + 1]; }
        const float nn = (float)(O * 64);
        float mean = S / nn;
        float var = (SS - nn * mean * mean) / (nn - 1.f);
        var = fmaxf(var, 0.f);
        float scale = 1.f / (sqrtf(var) + 1e-5f);
        red[0] = mean; red[1] = scale;
    }
    __syncthreads();
    const float mean = red[0], scale = red[1];
    const float z0 = leaky((0.f - mean) * scale);

    float* po = out + (size_t)b * (O * 64);
    #pragma unroll
    for (int i = 0; i < 8; i++) {
        float* row = po + (ot + i * OT) * 64;
        if (nt == 0) row[0] = z0;
        #pragma unroll
        for (int j = 0; j < 8; j++) {
            int node = nt * 8 + j;
            if (node < 63) row[node + 1] = leaky((acc[i][j] - mean) * scale);
        }
    }
}

// ---------------- host launch ----------------
static constexpr size_t SMEM1 = (64 * 64  + 24 * 128 + 192 + 64) * 4;  // ~29.7 KB
static constexpr size_t SMEM2 = (128 * 64 + 24 * 256 + 192 + 64) * 4;  // ~58.4 KB
static constexpr size_t SMEM3 = (256 * 64 + 24 * 512 + 192 + 64) * 4;  // ~115.7 KB

extern "C" void kernel_launch(void* const* d_in, const int* in_sizes, int n_in,
                              void* d_out, int out_size)
{
    const float* trees   = (const float*)d_in[0];
    const int*   indexes = (const int*)  d_in[1];
    const float* W1 = (const float*)d_in[2];  const float* b1 = (const float*)d_in[3];
    const float* W2 = (const float*)d_in[4];  const float* b2 = (const float*)d_in[5];
    const float* W3 = (const float*)d_in[6];  const float* b3 = (const float*)d_in[7];
    const float* W4 = (const float*)d_in[8];  const float* b4 = (const float*)d_in[9];
    const float* cw1 = (const float*)d_in[10]; const float* cb1 = (const float*)d_in[11];
    const float* cw2 = (const float*)d_in[12]; const float* cb2 = (const float*)d_in[13];
    const float* cw3 = (const float*)d_in[14]; const float* cb3 = (const float*)d_in[15];

    float *x1, *x2, *x3, *x4, *t1, *t2;
    cudaGetSymbolAddress((void**)&x1, g_x1);
    cudaGetSymbolAddress((void**)&x2, g_x2);
    cudaGetSymbolAddress((void**)&x3, g_x3);
    cudaGetSymbolAddress((void**)&x4, g_x4);
    cudaGetSymbolAddress((void**)&t1, g_t1);
    cudaGetSymbolAddress((void**)&t2, g_t2);

    cudaFuncSetAttribute(conv_ln<64, 128>,  cudaFuncAttributeMaxDynamicSharedMemorySize, (int)SMEM1);
    cudaFuncSetAttribute(conv_ln<128, 256>, cudaFuncAttributeMaxDynamicSharedMemorySize, (int)SMEM2);
    cudaFuncSetAttribute(conv_ln<256, 512>, cudaFuncAttributeMaxDynamicSharedMemorySize, (int)SMEM3);

    // MLP: 16 -> 64 -> 256 -> 1024 -> 4096 (leaky after each)
    gemm_bias_leaky<<<dim3(32, 1),  128>>>(trees, W1, b1, x1, 16,   64);
    gemm_bias_leaky<<<dim3(32, 4),  128>>>(x1,    W2, b2, x2, 64,   256);
    gemm_bias_leaky<<<dim3(32, 16), 128>>>(x2,    W3, b3, x3, 256,  1024);
    gemm_bias_leaky<<<dim3(32, 64), 128>>>(x3,    W4, b4, x4, 1024, 4096);

    // Fused conv + LN + leaky blocks (one CTA per sample)
    conv_ln<64, 128> <<<4096, 128, SMEM1>>>(x4, indexes, cw1, cb1, t1);
    conv_ln<128, 256><<<4096, 256, SMEM2>>>(t1, indexes, cw2, cb2, t2);
    conv_ln<256, 512><<<4096, 512, SMEM3>>>(t2, indexes, cw3, cb3, (float*)d_out);
}

// round 7
// speedup vs baseline: 2.2739x; 2.2739x over previous
#include <cuda_runtime.h>
#include <cuda_bf16.h>
#include <stdint.h>
#include <math.h>

// ------------------------------ scratch ------------------------------------
static __device__ __align__(16) float g_x1[4096 * 64];
static __device__ __align__(16) float g_x2[4096 * 256];
static __device__ __align__(16) float g_x3[4096 * 1024];
static __device__ __align__(16) float g_x4[4096 * 4096];
static __device__ __align__(16) float g_pre[4096 * 512 * 64];        // conv pre-LN output (reused)
static __device__ __align__(16) __nv_bfloat16 g_xh[4096 * 64 * 256]; // transposed activations hi
static __device__ __align__(16) __nv_bfloat16 g_xl[4096 * 64 * 256]; // transposed activations lo
static __device__ __align__(16) __nv_bfloat16 g_w1h[128 * 192], g_w1l[128 * 192];
static __device__ __align__(16) __nv_bfloat16 g_w2h[256 * 384], g_w2l[256 * 384];
static __device__ __align__(16) __nv_bfloat16 g_w3h[512 * 768], g_w3l[512 * 768];

__device__ __forceinline__ float leaky(float v) { return v > 0.f ? v : 0.01f * v; }

// ------------------------------ MLP GEMM (fp32) ----------------------------
__global__ void __launch_bounds__(128)
gemm_bias_leaky(const float* __restrict__ A, const float* __restrict__ W,
                const float* __restrict__ bias, float* __restrict__ C, int K, int N)
{
    __shared__ __align__(16) float As[16][128];
    __shared__ __align__(16) float Ws[16][64];
    const int tid = threadIdx.x, mt = tid & 15, nt = tid >> 4;
    const float* Ab = A + (size_t)blockIdx.x * 128 * K;
    const float* Wb = W + (size_t)blockIdx.y * 64 * K;
    float acc[8][8] = {};
    for (int k0 = 0; k0 < K; k0 += 16) {
        #pragma unroll
        for (int i = 0; i < 4; i++) {
            int lin = tid + i * 128, r = lin >> 2, c4 = lin & 3;
            float4 v = *(const float4*)(Ab + (size_t)r * K + k0 + c4 * 4);
            As[c4*4+0][r]=v.x; As[c4*4+1][r]=v.y; As[c4*4+2][r]=v.z; As[c4*4+3][r]=v.w;
        }
        #pragma unroll
        for (int i = 0; i < 2; i++) {
            int lin = tid + i * 128, r = lin >> 2, c4 = lin & 3;
            float4 v = *(const float4*)(Wb + (size_t)r * K + k0 + c4 * 4);
            Ws[c4*4+0][r]=v.x; Ws[c4*4+1][r]=v.y; Ws[c4*4+2][r]=v.z; Ws[c4*4+3][r]=v.w;
        }
        __syncthreads();
        #pragma unroll
        for (int kk = 0; kk < 16; kk++) {
            float a[8], w[8];
            *(float4*)&a[0] = *(const float4*)&As[kk][mt*8];
            *(float4*)&a[4] = *(const float4*)&As[kk][mt*8+4];
            *(float4*)&w[0] = *(const float4*)&Ws[kk][nt*8];
            *(float4*)&w[4] = *(const float4*)&Ws[kk][nt*8+4];
            #pragma unroll
            for (int i = 0; i < 8; i++)
                #pragma unroll
                for (int j = 0; j < 8; j++) acc[i][j] = fmaf(a[i], w[j], acc[i][j]);
        }
        __syncthreads();
    }
    float bv[8];
    #pragma unroll
    for (int j = 0; j < 8; j++) bv[j] = __ldg(&bias[blockIdx.y * 64 + nt * 8 + j]);
    #pragma unroll
    for (int i = 0; i < 8; i++) {
        size_t row = (size_t)(blockIdx.x*128 + mt*8 + i) * N + blockIdx.y*64 + nt*8;
        float4 o0, o1;
        o0.x=leaky(acc[i][0]+bv[0]); o0.y=leaky(acc[i][1]+bv[1]);
        o0.z=leaky(acc[i][2]+bv[2]); o0.w=leaky(acc[i][3]+bv[3]);
        o1.x=leaky(acc[i][4]+bv[4]); o1.y=leaky(acc[i][5]+bv[5]);
        o1.z=leaky(acc[i][6]+bv[6]); o1.w=leaky(acc[i][7]+bv[7]);
        *(float4*)&C[row] = o0; *(float4*)&C[row+4] = o1;
    }
}

// ---- W prep: w[o][c][kk] -> wA[o][kk*C+c], split into hi/lo bf16 ----------
__global__ void wsplit(const float* __restrict__ w, __nv_bfloat16* __restrict__ hi,
                       __nv_bfloat16* __restrict__ lo, int C, int O)
{
    int i = blockIdx.x * 256 + threadIdx.x;
    int K3 = 3 * C;
    if (i >= O * K3) return;
    int o = i / K3, rem = i % K3, c = rem / 3, kk = rem % 3;
    float v = w[i];
    __nv_bfloat16 h = __float2bfloat16(v);
    hi[o * K3 + kk * C + c] = h;
    lo[o * K3 + kk * C + c] = __float2bfloat16(v - __bfloat162float(h));
}

// ---- MLP out transpose+split: x4[b][c][n] -> xT[b][n][c] hi/lo (C=64) -----
__global__ void __launch_bounds__(64)
tsplit64(const float* __restrict__ x, __nv_bfloat16* __restrict__ hi,
         __nv_bfloat16* __restrict__ lo)
{
    __shared__ __align__(16) float s[64 * 64];
    const int b = blockIdx.x, t = threadIdx.x;
    const float4* src = (const float4*)(x + (size_t)b * 4096);
    float4* d4 = (float4*)s;
    for (int i = t; i < 1024; i += 64) d4[i] = src[i];
    __syncthreads();
    __align__(16) __nv_bfloat16 rh[64], rl[64];
    #pragma unroll
    for (int c = 0; c < 64; c++) {
        float v = s[c * 64 + t];
        rh[c] = __float2bfloat16(v);
        rl[c] = __float2bfloat16(v - __bfloat162float(rh[c]));
    }
    uint4* dh = (uint4*)(hi + (size_t)b * 4096 + t * 64);
    uint4* dl = (uint4*)(lo + (size_t)b * 4096 + t * 64);
    #pragma unroll
    for (int q = 0; q < 8; q++) { dh[q] = ((uint4*)rh)[q]; dl[q] = ((uint4*)rl)[q]; }
}

// --------------------- conv via mma.sync bf16 hi/lo split ------------------
// D[b][o][n] = sum_k W[o,k] * E[n,k], n=0 row is zero slot (output already padded).
// CTA: 128-row M-tile x 2 samples, 8 warps; warp s=wid>>2, wm=wid&3 -> 32x64 tile.
#define MMA16816(d, a, b0_, b1_) \
    asm volatile("mma.sync.aligned.m16n8k16.row.col.f32.bf16.bf16.f32 " \
        "{%0,%1,%2,%3}, {%4,%5,%6,%7}, {%8,%9}, {%0,%1,%2,%3};" \
        : "+f"(d[0]), "+f"(d[1]), "+f"(d[2]), "+f"(d[3]) \
        : "r"(a[0]), "r"(a[1]), "r"(a[2]), "r"(a[3]), "r"(b0_), "r"(b1_))

template <int C, int O>
__global__ void __launch_bounds__(256, 2)
conv_hmma(const __nv_bfloat16* __restrict__ xhi, const __nv_bfloat16* __restrict__ xlo,
          const __nv_bfloat16* __restrict__ whi, const __nv_bfloat16* __restrict__ wlo,
          const int* __restrict__ idxg, const float* __restrict__ bias,
          float* __restrict__ pre)
{
    constexpr int K3 = 3 * C, NCH = K3 / 64, CB = C / 64;
    // smem (halves): Ah[128*72] | Al[128*72] | B[4][64*72] | idx[2*192 ints]
    constexpr int AOFF = 9216, BOFF = 18432, BBLK = 4608;
    extern __shared__ __align__(16) __nv_bfloat16 smh[];
    int* idxs = (int*)(smh + BOFF + 4 * BBLK);

    const int tid = threadIdx.x, wid = tid >> 5, lane = tid & 31;
    const int g = lane >> 2, t = lane & 3;
    const int b0 = blockIdx.y * 2, obase = blockIdx.x * 128;
    const int s = wid >> 2, wm = wid & 3;

    for (int i = tid; i < 2 * 192; i += 256) {
        int s2 = i / 192, j = i % 192;
        idxs[i] = (j < 189) ? idxg[(size_t)(b0 + s2) * 189 + j] : 0;
    }

    float acc[2][8][4] = {};

    for (int ci = 0; ci < NCH; ci++) {
        __syncthreads();
        // A (weights) hi/lo: 128 rows x 64 halves each split
        #pragma unroll
        for (int it = 0; it < 8; it++) {
            int u = tid + it * 256;
            int sp = u >> 10, r = (u >> 3) & 127, q = u & 7;
            const __nv_bfloat16* src = (sp ? wlo : whi) + (size_t)(obase + r) * K3 + ci * 64 + q * 8;
            *(uint4*)(smh + sp * AOFF + r * 72 + q * 8) = *(const uint4*)src;
        }
        // B (gathered activations): row n==0 -> zeros
        const int kk = ci / CB, c0 = (ci % CB) * 64;
        #pragma unroll
        for (int it = 0; it < 8; it++) {
            int u = tid + it * 256;
            int sp = u >> 10, ss = (u >> 9) & 1, n = (u >> 3) & 63, q = u & 7;
            uint4 v = make_uint4(0, 0, 0, 0);
            if (n > 0) {
                int slot = idxs[ss * 192 + (n - 1) * 3 + kk];
                v = *(const uint4*)((sp ? xlo : xhi)
                    + ((size_t)(b0 + ss) * 64 + slot) * C + c0 + q * 8);
            }
            *(uint4*)(smh + BOFF + (ss * 2 + sp) * BBLK + n * 72 + q * 8) = v;
        }
        __syncthreads();

        const __nv_bfloat16* AH = smh;
        const __nv_bfloat16* AL = smh + AOFF;
        const __nv_bfloat16* BH = smh + BOFF + (s * 2) * BBLK;
        const __nv_bfloat16* BL = BH + BBLK;

        #pragma unroll
        for (int ks = 0; ks < 4; ks++) {
            uint32_t ah[2][4], al[2][4];
            const int koff = ks * 16 + 2 * t;
            #pragma unroll
            for (int mt = 0; mt < 2; mt++) {
                int r0 = wm * 32 + mt * 16 + g;
                ah[mt][0] = *(const uint32_t*)&AH[r0 * 72 + koff];
                ah[mt][1] = *(const uint32_t*)&AH[(r0 + 8) * 72 + koff];
                ah[mt][2] = *(const uint32_t*)&AH[r0 * 72 + koff + 8];
                ah[mt][3] = *(const uint32_t*)&AH[(r0 + 8) * 72 + koff + 8];
                al[mt][0] = *(const uint32_t*)&AL[r0 * 72 + koff];
                al[mt][1] = *(const uint32_t*)&AL[(r0 + 8) * 72 + koff];
                al[mt][2] = *(const uint32_t*)&AL[r0 * 72 + koff + 8];
                al[mt][3] = *(const uint32_t*)&AL[(r0 + 8) * 72 + koff + 8];
            }
            #pragma unroll
            for (int nt = 0; nt < 8; nt++) {
                int nrow = (nt * 8 + g) * 72 + koff;
                uint32_t bh0 = *(const uint32_t*)&BH[nrow];
                uint32_t bh1 = *(const uint32_t*)&BH[nrow + 8];
                uint32_t bl0 = *(const uint32_t*)&BL[nrow];
                uint32_t bl1 = *(const uint32_t*)&BL[nrow + 8];
                #pragma unroll
                for (int mt = 0; mt < 2; mt++) {
                    MMA16816(acc[mt][nt], ah[mt], bh0, bh1);
                    MMA16816(acc[mt][nt], ah[mt], bl0, bl1);
                    MMA16816(acc[mt][nt], al[mt], bh0, bh1);
                }
            }
        }
    }

    // epilogue: add bias (skip the zero-slot col 0), store padded node space
    #pragma unroll
    for (int mt = 0; mt < 2; mt++) {
        int o0 = obase + wm * 32 + mt * 16 + g;
        float bv0 = __ldg(&bias[o0]), bv1 = __ldg(&bias[o0 + 8]);
        float* base0 = pre + ((size_t)(b0 + s) * O + o0) * 64;
        float* base1 = base0 + 8 * 64;
        #pragma unroll
        for (int nt = 0; nt < 8; nt++) {
            int n0 = nt * 8 + 2 * t;
            float m0 = (n0 == 0) ? 0.f : bv0;
            float m1 = (n0 == 0) ? 0.f : bv1;
            float2 v0 = make_float2(acc[mt][nt][0] + m0, acc[mt][nt][1] + bv0);
            float2 v1 = make_float2(acc[mt][nt][2] + m1, acc[mt][nt][3] + bv1);
            *(float2*)(base0 + n0) = v0;
            *(float2*)(base1 + n0) = v1;
        }
    }
}

// ------------- block reduce for LN: returns via smem red[18] ---------------
__device__ __forceinline__ void ln_stats(float s, float ss, float* red, int tid, float nn)
{
    const int lane = tid & 31, warp = tid >> 5;
    #pragma unroll
    for (int sh = 16; sh; sh >>= 1) {
        s  += __shfl_down_sync(0xffffffffu, s,  sh);
        ss += __shfl_down_sync(0xffffffffu, ss, sh);
    }
    if (lane == 0) { red[2 * warp] = s; red[2 * warp + 1] = ss; }
    __syncthreads();
    if (tid == 0) {
        float S = 0.f, SS = 0.f;
        for (int w = 0; w < 8; w++) { S += red[2 * w]; SS += red[2 * w + 1]; }
        float mean = S / nn;
        float var = fmaxf((SS - nn * mean * mean) / (nn - 1.f), 0.f);
        red[16] = mean; red[17] = 1.f / (sqrtf(var) + 1e-5f);
    }
    __syncthreads();
}

// -------- LN + leaky + transpose + split for next conv (O = next C) --------
template <int O>
__global__ void __launch_bounds__(256)
ln_split(const float* __restrict__ pre, __nv_bfloat16* __restrict__ xh,
         __nv_bfloat16* __restrict__ xl)
{
    __shared__ float red[18];
    __shared__ __align__(16) __nv_bfloat16 sh[4096], sl[4096];
    const int b = blockIdx.x, tid = threadIdx.x;
    const float4* p4 = (const float4*)(pre + (size_t)b * O * 64);
    float s = 0.f, ss = 0.f;
    for (int i = tid; i < O * 16; i += 256) {
        float4 v = p4[i];
        s += v.x + v.y + v.z + v.w;
        ss += v.x*v.x + v.y*v.y + v.z*v.z + v.w*v.w;
    }
    ln_stats(s, ss, red, tid, (float)(O * 64));
    const float mean = red[16], scale = red[17];
    for (int ot = 0; ot < O / 64; ot++) {
        #pragma unroll 1
        for (int k = 0; k < 4; k++) {
            int u = tid + k * 256;
            int ol = u >> 4, n4 = u & 15;
            float4 v = p4[(ot * 64 + ol) * 16 + n4];
            float y[4] = { leaky((v.x - mean) * scale), leaky((v.y - mean) * scale),
                           leaky((v.z - mean) * scale), leaky((v.w - mean) * scale) };
            #pragma unroll
            for (int j = 0; j < 4; j++) {
                int n = n4 * 4 + j;
                __nv_bfloat16 h = __float2bfloat16(y[j]);
                sh[n * 64 + ol] = h;
                sl[n * 64 + ol] = __float2bfloat16(y[j] - __bfloat162float(h));
            }
        }
        __syncthreads();
        #pragma unroll 1
        for (int k = 0; k < 2; k++) {
            int u = tid + k * 256;
            int n = u >> 3, q = u & 7;
            size_t base = (size_t)b * 64 * O + (size_t)n * O + ot * 64 + q * 8;
            *(uint4*)(xh + base) = *(uint4*)(sh + n * 64 + q * 8);
            *(uint4*)(xl + base) = *(uint4*)(sl + n * 64 + q * 8);
        }
        __syncthreads();
    }
}

// ---------------- final LN + leaky -> d_out (fp32, [b][o][n]) --------------
__global__ void __launch_bounds__(256)
ln_final(const float* __restrict__ pre, float* __restrict__ out)
{
    constexpr int O = 512;
    __shared__ float red[18];
    const int b = blockIdx.x, tid = threadIdx.x;
    const float4* p4 = (const float4*)(pre + (size_t)b * O * 64);
    float4* o4 = (float4*)(out + (size_t)b * O * 64);
    float s = 0.f, ss = 0.f;
    for (int i = tid; i < O * 16; i += 256) {
        float4 v = p4[i];
        s += v.x + v.y + v.z + v.w;
        ss += v.x*v.x + v.y*v.y + v.z*v.z + v.w*v.w;
    }
    ln_stats(s, ss, red, tid, (float)(O * 64));
    const float mean = red[16], scale = red[17];
    for (int i = tid; i < O * 16; i += 256) {
        float4 v = p4[i];
        o4[i] = make_float4(leaky((v.x - mean) * scale), leaky((v.y - mean) * scale),
                            leaky((v.z - mean) * scale), leaky((v.w - mean) * scale));
    }
}

// ------------------------------ host launch --------------------------------
static constexpr int SMEM_CONV = (9216 * 2 + 4608 * 4) * 2 + 2 * 192 * 4;  // 75264 B

extern "C" void kernel_launch(void* const* d_in, const int* in_sizes, int n_in,
                              void* d_out, int out_size)
{
    const float* trees   = (const float*)d_in[0];
    const int*   indexes = (const int*)  d_in[1];
    const float* W1 = (const float*)d_in[2];  const float* b1 = (const float*)d_in[3];
    const float* W2 = (const float*)d_in[4];  const float* b2 = (const float*)d_in[5];
    const float* W3 = (const float*)d_in[6];  const float* b3 = (const float*)d_in[7];
    const float* W4 = (const float*)d_in[8];  const float* b4 = (const float*)d_in[9];
    const float* cw1 = (const float*)d_in[10]; const float* cb1 = (const float*)d_in[11];
    const float* cw2 = (const float*)d_in[12]; const float* cb2 = (const float*)d_in[13];
    const float* cw3 = (const float*)d_in[14]; const float* cb3 = (const float*)d_in[15];

    float *x1, *x2, *x3, *x4, *pre;
    __nv_bfloat16 *xh, *xl, *w1h, *w1l, *w2h, *w2l, *w3h, *w3l;
    cudaGetSymbolAddress((void**)&x1, g_x1);
    cudaGetSymbolAddress((void**)&x2, g_x2);
    cudaGetSymbolAddress((void**)&x3, g_x3);
    cudaGetSymbolAddress((void**)&x4, g_x4);
    cudaGetSymbolAddress((void**)&pre, g_pre);
    cudaGetSymbolAddress((void**)&xh, g_xh);
    cudaGetSymbolAddress((void**)&xl, g_xl);
    cudaGetSymbolAddress((void**)&w1h, g_w1h); cudaGetSymbolAddress((void**)&w1l, g_w1l);
    cudaGetSymbolAddress((void**)&w2h, g_w2h); cudaGetSymbolAddress((void**)&w2l, g_w2l);
    cudaGetSymbolAddress((void**)&w3h, g_w3h); cudaGetSymbolAddress((void**)&w3l, g_w3l);

    cudaFuncSetAttribute(conv_hmma<64, 128>,  cudaFuncAttributeMaxDynamicSharedMemorySize, SMEM_CONV);
    cudaFuncSetAttribute(conv_hmma<128, 256>, cudaFuncAttributeMaxDynamicSharedMemorySize, SMEM_CONV);
    cudaFuncSetAttribute(conv_hmma<256, 512>, cudaFuncAttributeMaxDynamicSharedMemorySize, SMEM_CONV);

    // weight reorder+split (tiny)
    wsplit<<<96,   256>>>(cw1, w1h, w1l, 64, 128);
    wsplit<<<384,  256>>>(cw2, w2h, w2l, 128, 256);
    wsplit<<<1536, 256>>>(cw3, w3h, w3l, 256, 512);

    // MLP (fp32)
    gemm_bias_leaky<<<dim3(32, 1),  128>>>(trees, W1, b1, x1, 16,   64);
    gemm_bias_leaky<<<dim3(32, 4),  128>>>(x1,    W2, b2, x2, 64,   256);
    gemm_bias_leaky<<<dim3(32, 16), 128>>>(x2,    W3, b3, x3, 256,  1024);
    gemm_bias_leaky<<<dim3(32, 64), 128>>>(x3,    W4, b4, x4, 1024, 4096);

    // transpose+split MLP output -> xT (C=64)
    tsplit64<<<4096, 64>>>(x4, xh, xl);

    // conv1 -> LN -> conv2 -> LN -> conv3 -> LN(final)
    conv_hmma<64, 128> <<<dim3(1, 2048), 256, SMEM_CONV>>>(xh, xl, w1h, w1l, indexes, cb1, pre);
    ln_split<128><<<4096, 256>>>(pre, xh, xl);
    conv_hmma<128, 256><<<dim3(2, 2048), 256, SMEM_CONV>>>(xh, xl, w2h, w2l, indexes, cb2, pre);
    ln_split<256><<<4096, 256>>>(pre, xh, xl);
    conv_hmma<256, 512><<<dim3(4, 2048), 256, SMEM_CONV>>>(xh, xl, w3h, w3l, indexes, cb3, pre);
    ln_final<<<4096, 256>>>(pre, (float*)d_out);
}

// round 8
// speedup vs baseline: 2.6541x; 1.1672x over previous
#include <cuda_runtime.h>
#include <cuda_bf16.h>
#include <stdint.h>
#include <math.h>

// ------------------------------ scratch ------------------------------------
static __device__ __align__(16) float g_x1[4096 * 64];
static __device__ __align__(16) float g_x2[4096 * 256];
static __device__ __align__(16) float g_x3[4096 * 1024];
static __device__ __align__(16) float g_x4[4096 * 4096];
static __device__ __align__(16) float g_pre[4096 * 512 * 64];
static __device__ __align__(16) __nv_bfloat16 g_xh[4096 * 64 * 256];
static __device__ __align__(16) __nv_bfloat16 g_xl[4096 * 64 * 256];
static __device__ __align__(16) __nv_bfloat16 g_w1h[128 * 192], g_w1l[128 * 192];
static __device__ __align__(16) __nv_bfloat16 g_w2h[256 * 384], g_w2l[256 * 384];
static __device__ __align__(16) __nv_bfloat16 g_w3h[512 * 768], g_w3l[512 * 768];
// MLP tensor-path buffers
static __device__ __align__(16) __nv_bfloat16 g_ah[4096 * 1024], g_al[4096 * 1024];
static __device__ __align__(16) __nv_bfloat16 g_mw3h[1024 * 256], g_mw3l[1024 * 256];
static __device__ __align__(16) __nv_bfloat16 g_mw4h[4096 * 1024], g_mw4l[4096 * 1024];

__device__ __forceinline__ float leaky(float v) { return v > 0.f ? v : 0.01f * v; }

__device__ __forceinline__ uint32_t smem_u32(const void* p) {
    uint32_t a;
    asm("{ .reg .u64 t; cvta.to.shared.u64 t, %1; cvt.u32.u64 %0, t; }" : "=r"(a) : "l"(p));
    return a;
}
__device__ __forceinline__ void ldsm4(uint32_t& r0, uint32_t& r1, uint32_t& r2, uint32_t& r3,
                                      uint32_t addr) {
    asm volatile("ldmatrix.sync.aligned.m8n8.x4.shared.b16 {%0,%1,%2,%3}, [%4];"
                 : "=r"(r0), "=r"(r1), "=r"(r2), "=r"(r3) : "r"(addr));
}
#define MMA16816(d, a, b0_, b1_) \
    asm volatile("mma.sync.aligned.m16n8k16.row.col.f32.bf16.bf16.f32 " \
        "{%0,%1,%2,%3}, {%4,%5,%6,%7}, {%8,%9}, {%0,%1,%2,%3};" \
        : "+f"(d[0]), "+f"(d[1]), "+f"(d[2]), "+f"(d[3]) \
        : "r"(a[0]), "r"(a[1]), "r"(a[2]), "r"(a[3]), "r"(b0_), "r"(b1_))

// ------------------------------ small fp32 GEMM (L1, L2) -------------------
__global__ void __launch_bounds__(128)
gemm_bias_leaky(const float* __restrict__ A, const float* __restrict__ W,
                const float* __restrict__ bias, float* __restrict__ C, int K, int N)
{
    __shared__ __align__(16) float As[16][128];
    __shared__ __align__(16) float Ws[16][64];
    const int tid = threadIdx.x, mt = tid & 15, nt = tid >> 4;
    const float* Ab = A + (size_t)blockIdx.x * 128 * K;
    const float* Wb = W + (size_t)blockIdx.y * 64 * K;
    float acc[8][8] = {};
    for (int k0 = 0; k0 < K; k0 += 16) {
        #pragma unroll
        for (int i = 0; i < 4; i++) {
            int lin = tid + i * 128, r = lin >> 2, c4 = lin & 3;
            float4 v = *(const float4*)(Ab + (size_t)r * K + k0 + c4 * 4);
            As[c4*4+0][r]=v.x; As[c4*4+1][r]=v.y; As[c4*4+2][r]=v.z; As[c4*4+3][r]=v.w;
        }
        #pragma unroll
        for (int i = 0; i < 2; i++) {
            int lin = tid + i * 128, r = lin >> 2, c4 = lin & 3;
            float4 v = *(const float4*)(Wb + (size_t)r * K + k0 + c4 * 4);
            Ws[c4*4+0][r]=v.x; Ws[c4*4+1][r]=v.y; Ws[c4*4+2][r]=v.z; Ws[c4*4+3][r]=v.w;
        }
        __syncthreads();
        #pragma unroll
        for (int kk = 0; kk < 16; kk++) {
            float a[8], w[8];
            *(float4*)&a[0] = *(const float4*)&As[kk][mt*8];
            *(float4*)&a[4] = *(const float4*)&As[kk][mt*8+4];
            *(float4*)&w[0] = *(const float4*)&Ws[kk][nt*8];
            *(float4*)&w[4] = *(const float4*)&Ws[kk][nt*8+4];
            #pragma unroll
            for (int i = 0; i < 8; i++)
                #pragma unroll
                for (int j = 0; j < 8; j++) acc[i][j] = fmaf(a[i], w[j], acc[i][j]);
        }
        __syncthreads();
    }
    float bv[8];
    #pragma unroll
    for (int j = 0; j < 8; j++) bv[j] = __ldg(&bias[blockIdx.y * 64 + nt * 8 + j]);
    #pragma unroll
    for (int i = 0; i < 8; i++) {
        size_t row = (size_t)(blockIdx.x*128 + mt*8 + i) * N + blockIdx.y*64 + nt*8;
        float4 o0, o1;
        o0.x=leaky(acc[i][0]+bv[0]); o0.y=leaky(acc[i][1]+bv[1]);
        o0.z=leaky(acc[i][2]+bv[2]); o0.w=leaky(acc[i][3]+bv[3]);
        o1.x=leaky(acc[i][4]+bv[4]); o1.y=leaky(acc[i][5]+bv[5]);
        o1.z=leaky(acc[i][6]+bv[6]); o1.w=leaky(acc[i][7]+bv[7]);
        *(float4*)&C[row] = o0; *(float4*)&C[row+4] = o1;
    }
}

// ---- elementwise fp32 -> hi/lo bf16 split (layout preserved) --------------
__global__ void asplit(const float* __restrict__ x, __nv_bfloat16* __restrict__ h,
                       __nv_bfloat16* __restrict__ l, int n4)
{
    int i = blockIdx.x * 256 + threadIdx.x;
    if (i >= n4) return;
    float4 v = ((const float4*)x)[i];
    __nv_bfloat16 h0 = __float2bfloat16(v.x), h1 = __float2bfloat16(v.y);
    __nv_bfloat16 h2 = __float2bfloat16(v.z), h3 = __float2bfloat16(v.w);
    ((__nv_bfloat162*)h)[2*i]   = __nv_bfloat162(h0, h1);
    ((__nv_bfloat162*)h)[2*i+1] = __nv_bfloat162(h2, h3);
    ((__nv_bfloat162*)l)[2*i]   = __nv_bfloat162(__float2bfloat16(v.x - __bfloat162float(h0)),
                                                 __float2bfloat16(v.y - __bfloat162float(h1)));
    ((__nv_bfloat162*)l)[2*i+1] = __nv_bfloat162(__float2bfloat16(v.z - __bfloat162float(h2)),
                                                 __float2bfloat16(v.w - __bfloat162float(h3)));
}

// ---- conv W prep: w[o][c][kk] -> wA[o][kk*C+c], hi/lo split ---------------
__global__ void wsplit(const float* __restrict__ w, __nv_bfloat16* __restrict__ hi,
                       __nv_bfloat16* __restrict__ lo, int C, int O)
{
    int i = blockIdx.x * 256 + threadIdx.x;
    int K3 = 3 * C;
    if (i >= O * K3) return;
    int o = i / K3, rem = i % K3, c = rem / 3, kk = rem % 3;
    float v = w[i];
    __nv_bfloat16 h = __float2bfloat16(v);
    hi[o * K3 + kk * C + c] = h;
    lo[o * K3 + kk * C + c] = __float2bfloat16(v - __bfloat162float(h));
}

// ---- MLP out transpose+split: x4[b][c][n] -> xT[b][n][c] hi/lo (C=64) -----
__global__ void __launch_bounds__(64)
tsplit64(const float* __restrict__ x, __nv_bfloat16* __restrict__ hi,
         __nv_bfloat16* __restrict__ lo)
{
    __shared__ __align__(16) float s[64 * 64];
    const int b = blockIdx.x, t = threadIdx.x;
    const float4* src = (const float4*)(x + (size_t)b * 4096);
    float4* d4 = (float4*)s;
    for (int i = t; i < 1024; i += 64) d4[i] = src[i];
    __syncthreads();
    __align__(16) __nv_bfloat16 rh[64], rl[64];
    #pragma unroll
    for (int c = 0; c < 64; c++) {
        float v = s[c * 64 + t];
        rh[c] = __float2bfloat16(v);
        rl[c] = __float2bfloat16(v - __bfloat162float(rh[c]));
    }
    uint4* dh = (uint4*)(hi + (size_t)b * 4096 + t * 64);
    uint4* dl = (uint4*)(lo + (size_t)b * 4096 + t * 64);
    #pragma unroll
    for (int q = 0; q < 8; q++) { dh[q] = ((uint4*)rh)[q]; dl[q] = ((uint4*)rl)[q]; }
}

// ------------------- dense split-bf16 HMMA GEMM (MLP L3/L4) ----------------
// C(M,N) = leaky(A(M,K) * W(N,K)^T + bias); A,W as hi/lo bf16.
// CTA: 128x64 tile, 8 warps (wm = M 32-row strip, wh = N 32-col half).
__global__ void __launch_bounds__(256, 2)
gemm_hmma(const __nv_bfloat16* __restrict__ ah, const __nv_bfloat16* __restrict__ al,
          const __nv_bfloat16* __restrict__ wh_, const __nv_bfloat16* __restrict__ wl_,
          const float* __restrict__ bias, float* __restrict__ C, int K, int N)
{
    constexpr int GA = 9216, GW = 4608;   // halves per split buffer
    extern __shared__ __align__(16) __nv_bfloat16 smg[];
    const int tid = threadIdx.x, wid = tid >> 5, lane = tid & 31;
    const int g = lane >> 2, t = lane & 3;
    const int wm = wid & 3, wh = wid >> 2;
    const int m0 = blockIdx.x * 128, n0 = blockIdx.y * 64;

    const uint32_t sA = smem_u32(smg);
    const uint32_t sAl = sA + GA * 2, sW = sA + 2 * GA * 2, sWl = sW + GW * 2;
    const int lrowA = lane & 15, lcolA = (lane >> 4) * 8;
    const int tb = lane >> 3;
    const int lrowB = (tb >> 1) * 8 + (lane & 7), lcolB = (tb & 1) * 8;

    float acc[2][4][4] = {};

    for (int kc = 0; kc < K; kc += 64) {
        __syncthreads();
        #pragma unroll
        for (int it = 0; it < 8; it++) {
            int u = tid + it * 256;
            int sp = u >> 10, r = (u >> 3) & 127, q = u & 7;
            const __nv_bfloat16* src = (sp ? al : ah) + (size_t)(m0 + r) * K + kc + q * 8;
            *(uint4*)(smg + sp * GA + r * 72 + q * 8) = *(const uint4*)src;
        }
        #pragma unroll
        for (int it = 0; it < 4; it++) {
            int u = tid + it * 256;
            int sp = u >> 9, r = (u >> 3) & 63, q = u & 7;
            const __nv_bfloat16* src = (sp ? wl_ : wh_) + (size_t)(n0 + r) * K + kc + q * 8;
            *(uint4*)(smg + 2 * GA + sp * GW + r * 72 + q * 8) = *(const uint4*)src;
        }
        __syncthreads();

        #pragma unroll
        for (int ks = 0; ks < 4; ks++) {
            const int koff = ks * 16;
            uint32_t fah[2][4], fal[2][4];
            #pragma unroll
            for (int mt = 0; mt < 2; mt++) {
                uint32_t off = ((wm * 32 + mt * 16 + lrowA) * 72 + koff + lcolA) * 2;
                ldsm4(fah[mt][0], fah[mt][1], fah[mt][2], fah[mt][3], sA + off);
                ldsm4(fal[mt][0], fal[mt][1], fal[mt][2], fal[mt][3], sAl + off);
            }
            #pragma unroll
            for (int p = 0; p < 2; p++) {
                uint32_t off = ((wh * 32 + p * 16 + lrowB) * 72 + koff + lcolB) * 2;
                uint32_t bh0, bh1, bh2, bh3, bl0, bl1, bl2, bl3;
                ldsm4(bh0, bh1, bh2, bh3, sW + off);
                ldsm4(bl0, bl1, bl2, bl3, sWl + off);
                #pragma unroll
                for (int mt = 0; mt < 2; mt++) {
                    MMA16816(acc[mt][2*p],   fah[mt], bh0, bh1);
                    MMA16816(acc[mt][2*p],   fah[mt], bl0, bl1);
                    MMA16816(acc[mt][2*p],   fal[mt], bh0, bh1);
                    MMA16816(acc[mt][2*p+1], fah[mt], bh2, bh3);
                    MMA16816(acc[mt][2*p+1], fah[mt], bl2, bl3);
                    MMA16816(acc[mt][2*p+1], fal[mt], bh2, bh3);
                }
            }
        }
    }

    #pragma unroll
    for (int mt = 0; mt < 2; mt++) {
        #pragma unroll
        for (int nt = 0; nt < 4; nt++) {
            int col = n0 + wh * 32 + nt * 8 + 2 * t;
            float bv0 = __ldg(&bias[col]), bv1 = __ldg(&bias[col + 1]);
            int row0 = m0 + wm * 32 + mt * 16 + g;
            *(float2*)&C[(size_t)row0 * N + col] =
                make_float2(leaky(acc[mt][nt][0] + bv0), leaky(acc[mt][nt][1] + bv1));
            *(float2*)&C[(size_t)(row0 + 8) * N + col] =
                make_float2(leaky(acc[mt][nt][2] + bv0), leaky(acc[mt][nt][3] + bv1));
        }
    }
}

// --------------------- conv via mma.sync bf16 hi/lo split ------------------
template <int C, int O>
__global__ void __launch_bounds__(256, 2)
conv_hmma(const __nv_bfloat16* __restrict__ xhi, const __nv_bfloat16* __restrict__ xlo,
          const __nv_bfloat16* __restrict__ whi, const __nv_bfloat16* __restrict__ wlo,
          const int* __restrict__ idxg, const float* __restrict__ bias,
          float* __restrict__ pre)
{
    constexpr int K3 = 3 * C, NCH = K3 / 64, CB = C / 64;
    constexpr int AOFF = 9216, BOFF = 18432, BBLK = 4608;
    extern __shared__ __align__(16) __nv_bfloat16 smh[];
    int* idxs = (int*)(smh + BOFF + 4 * BBLK);

    const int tid = threadIdx.x, wid = tid >> 5, lane = tid & 31;
    const int g = lane >> 2, t = lane & 3;
    const int b0 = blockIdx.y * 2, obase = blockIdx.x * 128;
    const int s = wid >> 2, wm = wid & 3;

    const uint32_t sA = smem_u32(smh);
    const uint32_t sAl = sA + AOFF * 2;
    const uint32_t sB = sA + (BOFF + (s * 2) * BBLK) * 2;
    const uint32_t sBl = sB + BBLK * 2;
    const int lrowA = lane & 15, lcolA = (lane >> 4) * 8;
    const int tb = lane >> 3;
    const int lrowB = (tb >> 1) * 8 + (lane & 7), lcolB = (tb & 1) * 8;

    for (int i = tid; i < 2 * 192; i += 256) {
        int s2 = i / 192, j = i % 192;
        idxs[i] = (j < 189) ? idxg[(size_t)(b0 + s2) * 189 + j] : 0;
    }

    float acc[2][8][4] = {};

    for (int ci = 0; ci < NCH; ci++) {
        __syncthreads();
        #pragma unroll
        for (int it = 0; it < 8; it++) {
            int u = tid + it * 256;
            int sp = u >> 10, r = (u >> 3) & 127, q = u & 7;
            const __nv_bfloat16* src = (sp ? wlo : whi) + (size_t)(obase + r) * K3 + ci * 64 + q * 8;
            *(uint4*)(smh + sp * AOFF + r * 72 + q * 8) = *(const uint4*)src;
        }
        const int kk = ci / CB, c0 = (ci % CB) * 64;
        #pragma unroll
        for (int it = 0; it < 8; it++) {
            int u = tid + it * 256;
            int sp = u >> 10, ss = (u >> 9) & 1, n = (u >> 3) & 63, q = u & 7;
            uint4 v = make_uint4(0, 0, 0, 0);
            if (n > 0) {
                int slot = idxs[ss * 192 + (n - 1) * 3 + kk];
                v = *(const uint4*)((sp ? xlo : xhi)
                    + ((size_t)(b0 + ss) * 64 + slot) * C + c0 + q * 8);
            }
            *(uint4*)(smh + BOFF + (ss * 2 + sp) * BBLK + n * 72 + q * 8) = v;
        }
        __syncthreads();

        #pragma unroll
        for (int ks = 0; ks < 4; ks++) {
            const int koff = ks * 16;
            uint32_t fah[2][4], fal[2][4];
            #pragma unroll
            for (int mt = 0; mt < 2; mt++) {
                uint32_t off = ((wm * 32 + mt * 16 + lrowA) * 72 + koff + lcolA) * 2;
                ldsm4(fah[mt][0], fah[mt][1], fah[mt][2], fah[mt][3], sA + off);
                ldsm4(fal[mt][0], fal[mt][1], fal[mt][2], fal[mt][3], sAl + off);
            }
            #pragma unroll
            for (int p = 0; p < 4; p++) {
                uint32_t off = ((p * 16 + lrowB) * 72 + koff + lcolB) * 2;
                uint32_t bh0, bh1, bh2, bh3, bl0, bl1, bl2, bl3;
                ldsm4(bh0, bh1, bh2, bh3, sB + off);
                ldsm4(bl0, bl1, bl2, bl3, sBl + off);
                #pragma unroll
                for (int mt = 0; mt < 2; mt++) {
                    MMA16816(acc[mt][2*p],   fah[mt], bh0, bh1);
                    MMA16816(acc[mt][2*p],   fah[mt], bl0, bl1);
                    MMA16816(acc[mt][2*p],   fal[mt], bh0, bh1);
                    MMA16816(acc[mt][2*p+1], fah[mt], bh2, bh3);
                    MMA16816(acc[mt][2*p+1], fah[mt], bl2, bl3);
                    MMA16816(acc[mt][2*p+1], fal[mt], bh2, bh3);
                }
            }
        }
    }

    #pragma unroll
    for (int mt = 0; mt < 2; mt++) {
        int o0 = obase + wm * 32 + mt * 16 + g;
        float bv0 = __ldg(&bias[o0]), bv1 = __ldg(&bias[o0 + 8]);
        float* base0 = pre + ((size_t)(b0 + s) * O + o0) * 64;
        float* base1 = base0 + 8 * 64;
        #pragma unroll
        for (int nt = 0; nt < 8; nt++) {
            int n0 = nt * 8 + 2 * t;
            float m0 = (n0 == 0) ? 0.f : bv0;
            float m1 = (n0 == 0) ? 0.f : bv1;
            *(float2*)(base0 + n0) = make_float2(acc[mt][nt][0] + m0, acc[mt][nt][1] + bv0);
            *(float2*)(base1 + n0) = make_float2(acc[mt][nt][2] + m1, acc[mt][nt][3] + bv1);
        }
    }
}

// ------------- block reduce for LN -----------------------------------------
__device__ __forceinline__ void ln_stats(float s, float ss, float* red, int tid, float nn)
{
    const int lane = tid & 31, warp = tid >> 5;
    #pragma unroll
    for (int sh = 16; sh; sh >>= 1) {
        s  += __shfl_down_sync(0xffffffffu, s,  sh);
        ss += __shfl_down_sync(0xffffffffu, ss, sh);
    }
    if (lane == 0) { red[2 * warp] = s; red[2 * warp + 1] = ss; }
    __syncthreads();
    if (tid == 0) {
        float S = 0.f, SS = 0.f;
        for (int w = 0; w < 8; w++) { S += red[2 * w]; SS += red[2 * w + 1]; }
        float mean = S / nn;
        float var = fmaxf((SS - nn * mean * mean) / (nn - 1.f), 0.f);
        red[16] = mean; red[17] = 1.f / (sqrtf(var) + 1e-5f);
    }
    __syncthreads();
}

// -------- LN + leaky + transpose + split for next conv ---------------------
template <int O>
__global__ void __launch_bounds__(256)
ln_split(const float* __restrict__ pre, __nv_bfloat16* __restrict__ xh,
         __nv_bfloat16* __restrict__ xl)
{
    __shared__ float red[18];
    __shared__ __align__(16) __nv_bfloat16 sh[4096], sl[4096];
    const int b = blockIdx.x, tid = threadIdx.x;
    const float4* p4 = (const float4*)(pre + (size_t)b * O * 64);
    float s = 0.f, ss = 0.f;
    for (int i = tid; i < O * 16; i += 256) {
        float4 v = p4[i];
        s += v.x + v.y + v.z + v.w;
        ss += v.x*v.x + v.y*v.y + v.z*v.z + v.w*v.w;
    }
    ln_stats(s, ss, red, tid, (float)(O * 64));
    const float mean = red[16], scale = red[17];
    for (int ot = 0; ot < O / 64; ot++) {
        #pragma unroll 1
        for (int k = 0; k < 4; k++) {
            int u = tid + k * 256;
            int ol = u >> 4, n4 = u & 15;
            float4 v = p4[(ot * 64 + ol) * 16 + n4];
            float y[4] = { leaky((v.x - mean) * scale), leaky((v.y - mean) * scale),
                           leaky((v.z - mean) * scale), leaky((v.w - mean) * scale) };
            #pragma unroll
            for (int j = 0; j < 4; j++) {
                int n = n4 * 4 + j;
                __nv_bfloat16 h = __float2bfloat16(y[j]);
                sh[n * 64 + ol] = h;
                sl[n * 64 + ol] = __float2bfloat16(y[j] - __bfloat162float(h));
            }
        }
        __syncthreads();
        #pragma unroll 1
        for (int k = 0; k < 2; k++) {
            int u = tid + k * 256;
            int n = u >> 3, q = u & 7;
            size_t base = (size_t)b * 64 * O + (size_t)n * O + ot * 64 + q * 8;
            *(uint4*)(xh + base) = *(uint4*)(sh + n * 64 + q * 8);
            *(uint4*)(xl + base) = *(uint4*)(sl + n * 64 + q * 8);
        }
        __syncthreads();
    }
}

// ---------------- final LN + leaky -> d_out --------------------------------
__global__ void __launch_bounds__(256)
ln_final(const float* __restrict__ pre, float* __restrict__ out)
{
    constexpr int O = 512;
    __shared__ float red[18];
    const int b = blockIdx.x, tid = threadIdx.x;
    const float4* p4 = (const float4*)(pre + (size_t)b * O * 64);
    float4* o4 = (float4*)(out + (size_t)b * O * 64);
    float s = 0.f, ss = 0.f;
    for (int i = tid; i < O * 16; i += 256) {
        float4 v = p4[i];
        s += v.x + v.y + v.z + v.w;
        ss += v.x*v.x + v.y*v.y + v.z*v.z + v.w*v.w;
    }
    ln_stats(s, ss, red, tid, (float)(O * 64));
    const float mean = red[16], scale = red[17];
    for (int i = tid; i < O * 16; i += 256) {
        float4 v = p4[i];
        o4[i] = make_float4(leaky((v.x - mean) * scale), leaky((v.y - mean) * scale),
                            leaky((v.z - mean) * scale), leaky((v.w - mean) * scale));
    }
}

// ------------------------------ host launch --------------------------------
static constexpr int SMEM_CONV = (9216 * 2 + 4608 * 4) * 2 + 2 * 192 * 4;  // 75264 B
static constexpr int SMEM_GEMM = (9216 * 2 + 4608 * 2) * 2;                // 55296 B

extern "C" void kernel_launch(void* const* d_in, const int* in_sizes, int n_in,
                              void* d_out, int out_size)
{
    const float* trees   = (const float*)d_in[0];
    const int*   indexes = (const int*)  d_in[1];
    const float* W1 = (const float*)d_in[2];  const float* b1 = (const float*)d_in[3];
    const float* W2 = (const float*)d_in[4];  const float* b2 = (const float*)d_in[5];
    const float* W3 = (const float*)d_in[6];  const float* b3 = (const float*)d_in[7];
    const float* W4 = (const float*)d_in[8];  const float* b4 = (const float*)d_in[9];
    const float* cw1 = (const float*)d_in[10]; const float* cb1 = (const float*)d_in[11];
    const float* cw2 = (const float*)d_in[12]; const float* cb2 = (const float*)d_in[13];
    const float* cw3 = (const float*)d_in[14]; const float* cb3 = (const float*)d_in[15];

    float *x1, *x2, *x3, *x4, *pre;
    __nv_bfloat16 *xh, *xl, *w1h, *w1l, *w2h, *w2l, *w3h, *w3l;
    __nv_bfloat16 *ma_h, *ma_l, *mw3h, *mw3l, *mw4h, *mw4l;
    cudaGetSymbolAddress((void**)&x1, g_x1);
    cudaGetSymbolAddress((void**)&x2, g_x2);
    cudaGetSymbolAddress((void**)&x3, g_x3);
    cudaGetSymbolAddress((void**)&x4, g_x4);
    cudaGetSymbolAddress((void**)&pre, g_pre);
    cudaGetSymbolAddress((void**)&xh, g_xh);
    cudaGetSymbolAddress((void**)&xl, g_xl);
    cudaGetSymbolAddress((void**)&w1h, g_w1h); cudaGetSymbolAddress((void**)&w1l, g_w1l);
    cudaGetSymbolAddress((void**)&w2h, g_w2h); cudaGetSymbolAddress((void**)&w2l, g_w2l);
    cudaGetSymbolAddress((void**)&w3h, g_w3h); cudaGetSymbolAddress((void**)&w3l, g_w3l);
    cudaGetSymbolAddress((void**)&ma_h, g_ah); cudaGetSymbolAddress((void**)&ma_l, g_al);
    cudaGetSymbolAddress((void**)&mw3h, g_mw3h); cudaGetSymbolAddress((void**)&mw3l, g_mw3l);
    cudaGetSymbolAddress((void**)&mw4h, g_mw4h); cudaGetSymbolAddress((void**)&mw4l, g_mw4l);

    cudaFuncSetAttribute(conv_hmma<64, 128>,  cudaFuncAttributeMaxDynamicSharedMemorySize, SMEM_CONV);
    cudaFuncSetAttribute(conv_hmma<128, 256>, cudaFuncAttributeMaxDynamicSharedMemorySize, SMEM_CONV);
    cudaFuncSetAttribute(conv_hmma<256, 512>, cudaFuncAttributeMaxDynamicSharedMemorySize, SMEM_CONV);
    cudaFuncSetAttribute(gemm_hmma, cudaFuncAttributeMaxDynamicSharedMemorySize, SMEM_GEMM);

    // weight prep
    wsplit<<<96,   256>>>(cw1, w1h, w1l, 64, 128);
    wsplit<<<384,  256>>>(cw2, w2h, w2l, 128, 256);
    wsplit<<<1536, 256>>>(cw3, w3h, w3l, 256, 512);
    asplit<<<256,  256>>>(W3, mw3h, mw3l, 1024 * 256 / 4);
    asplit<<<4096, 256>>>(W4, mw4h, mw4l, 4096 * 1024 / 4);

    // MLP: L1, L2 fp32 (tiny); L3, L4 tensor
    gemm_bias_leaky<<<dim3(32, 1), 128>>>(trees, W1, b1, x1, 16, 64);
    gemm_bias_leaky<<<dim3(32, 4), 128>>>(x1,    W2, b2, x2, 64, 256);
    asplit<<<1024, 256>>>(x2, ma_h, ma_l, 4096 * 256 / 4);
    gemm_hmma<<<dim3(32, 16), 256, SMEM_GEMM>>>(ma_h, ma_l, mw3h, mw3l, b3, x3, 256, 1024);
    asplit<<<4096, 256>>>(x3, ma_h, ma_l, 4096 * 1024 / 4);
    gemm_hmma<<<dim3(32, 64), 256, SMEM_GEMM>>>(ma_h, ma_l, mw4h, mw4l, b4, x4, 1024, 4096);

    // transpose+split MLP output -> xT (C=64)
    tsplit64<<<4096, 64>>>(x4, xh, xl);

    // conv1 -> LN -> conv2 -> LN -> conv3 -> LN(final)
    conv_hmma<64, 128> <<<dim3(1, 2048), 256, SMEM_CONV>>>(xh, xl, w1h, w1l, indexes, cb1, pre);
    ln_split<128><<<4096, 256>>>(pre, xh, xl);
    conv_hmma<128, 256><<<dim3(2, 2048), 256, SMEM_CONV>>>(xh, xl, w2h, w2l, indexes, cb2, pre);
    ln_split<256><<<4096, 256>>>(pre, xh, xl);
    conv_hmma<256, 512><<<dim3(4, 2048), 256, SMEM_CONV>>>(xh, xl, w3h, w3l, indexes, cb3, pre);
    ln_final<<<4096, 256>>>(pre, (float*)d_out);
}

// round 12
// speedup vs baseline: 2.9934x; 1.1278x over previous
#include <cuda_runtime.h>
#include <cuda_bf16.h>
#include <stdint.h>
#include <math.h>

// ------------------------------ scratch ------------------------------------
static __device__ __align__(16) float g_x1[4096 * 64];
static __device__ __align__(16) float g_x2[4096 * 256];
static __device__ __align__(16) float g_x3[4096 * 1024];
static __device__ __align__(16) float g_x4[4096 * 4096];
static __device__ __align__(16) float g_pre[4096 * 512 * 64];
static __device__ __align__(16) __nv_bfloat16 g_xh[4096 * 64 * 256];
static __device__ __align__(16) __nv_bfloat16 g_xl[4096 * 64 * 256];
static __device__ __align__(16) __nv_bfloat16 g_w1h[128 * 192], g_w1l[128 * 192];
static __device__ __align__(16) __nv_bfloat16 g_w2h[256 * 384], g_w2l[256 * 384];
static __device__ __align__(16) __nv_bfloat16 g_w3h[512 * 768], g_w3l[512 * 768];
static __device__ __align__(16) __nv_bfloat16 g_ah[4096 * 1024], g_al[4096 * 1024];
static __device__ __align__(16) __nv_bfloat16 g_mw3h[1024 * 256], g_mw3l[1024 * 256];
static __device__ __align__(16) __nv_bfloat16 g_mw4h[4096 * 1024], g_mw4l[4096 * 1024];

__device__ __forceinline__ float leaky(float v) { return v > 0.f ? v : 0.01f * v; }

__device__ __forceinline__ uint32_t smem_u32(const void* p) {
    uint32_t a;
    asm("{ .reg .u64 t; cvta.to.shared.u64 t, %1; cvt.u32.u64 %0, t; }" : "=r"(a) : "l"(p));
    return a;
}
__device__ __forceinline__ void ldsm4(uint32_t& r0, uint32_t& r1, uint32_t& r2, uint32_t& r3,
                                      uint32_t addr) {
    asm volatile("ldmatrix.sync.aligned.m8n8.x4.shared.b16 {%0,%1,%2,%3}, [%4];"
                 : "=r"(r0), "=r"(r1), "=r"(r2), "=r"(r3) : "r"(addr));
}
__device__ __forceinline__ void cpasync16(uint32_t dst, const void* src) {
    asm volatile("cp.async.cg.shared.global [%0], [%1], 16;" :: "r"(dst), "l"(src));
}
__device__ __forceinline__ void cpasync16z(uint32_t dst, const void* src, int szz) {
    asm volatile("cp.async.cg.shared.global [%0], [%1], 16, %2;" :: "r"(dst), "l"(src), "r"(szz));
}
#define CP_COMMIT() asm volatile("cp.async.commit_group;")
#define MMA16816(d, a, b0_, b1_) \
    asm volatile("mma.sync.aligned.m16n8k16.row.col.f32.bf16.bf16.f32 " \
        "{%0,%1,%2,%3}, {%4,%5,%6,%7}, {%8,%9}, {%0,%1,%2,%3};" \
        : "+f"(d[0]), "+f"(d[1]), "+f"(d[2]), "+f"(d[3]) \
        : "r"(a[0]), "r"(a[1]), "r"(a[2]), "r"(a[3]), "r"(b0_), "r"(b1_))

// ------------------------------ small fp32 GEMM (L1, L2) -------------------
__global__ void __launch_bounds__(128)
gemm_bias_leaky(const float* __restrict__ A, const float* __restrict__ W,
                const float* __restrict__ bias, float* __restrict__ C, int K, int N)
{
    __shared__ __align__(16) float As[16][128];
    __shared__ __align__(16) float Ws[16][64];
    const int tid = threadIdx.x, mt = tid & 15, nt = tid >> 4;
    const float* Ab = A + (size_t)blockIdx.x * 128 * K;
    const float* Wb = W + (size_t)blockIdx.y * 64 * K;
    float acc[8][8] = {};
    for (int k0 = 0; k0 < K; k0 += 16) {
        #pragma unroll
        for (int i = 0; i < 4; i++) {
            int lin = tid + i * 128, r = lin >> 2, c4 = lin & 3;
            float4 v = *(const float4*)(Ab + (size_t)r * K + k0 + c4 * 4);
            As[c4*4+0][r]=v.x; As[c4*4+1][r]=v.y; As[c4*4+2][r]=v.z; As[c4*4+3][r]=v.w;
        }
        #pragma unroll
        for (int i = 0; i < 2; i++) {
            int lin = tid + i * 128, r = lin >> 2, c4 = lin & 3;
            float4 v = *(const float4*)(Wb + (size_t)r * K + k0 + c4 * 4);
            Ws[c4*4+0][r]=v.x; Ws[c4*4+1][r]=v.y; Ws[c4*4+2][r]=v.z; Ws[c4*4+3][r]=v.w;
        }
        __syncthreads();
        #pragma unroll
        for (int kk = 0; kk < 16; kk++) {
            float a[8], w[8];
            *(float4*)&a[0] = *(const float4*)&As[kk][mt*8];
            *(float4*)&a[4] = *(const float4*)&As[kk][mt*8+4];
            *(float4*)&w[0] = *(const float4*)&Ws[kk][nt*8];
            *(float4*)&w[4] = *(const float4*)&Ws[kk][nt*8+4];
            #pragma unroll
            for (int i = 0; i < 8; i++)
                #pragma unroll
                for (int j = 0; j < 8; j++) acc[i][j] = fmaf(a[i], w[j], acc[i][j]);
        }
        __syncthreads();
    }
    float bv[8];
    #pragma unroll
    for (int j = 0; j < 8; j++) bv[j] = __ldg(&bias[blockIdx.y * 64 + nt * 8 + j]);
    #pragma unroll
    for (int i = 0; i < 8; i++) {
        size_t row = (size_t)(blockIdx.x*128 + mt*8 + i) * N + blockIdx.y*64 + nt*8;
        float4 o0, o1;
        o0.x=leaky(acc[i][0]+bv[0]); o0.y=leaky(acc[i][1]+bv[1]);
        o0.z=leaky(acc[i][2]+bv[2]); o0.w=leaky(acc[i][3]+bv[3]);
        o1.x=leaky(acc[i][4]+bv[4]); o1.y=leaky(acc[i][5]+bv[5]);
        o1.z=leaky(acc[i][6]+bv[6]); o1.w=leaky(acc[i][7]+bv[7]);
        *(float4*)&C[row] = o0; *(float4*)&C[row+4] = o1;
    }
}

// ---- elementwise fp32 -> hi/lo bf16 split ---------------------------------
__global__ void asplit(const float* __restrict__ x, __nv_bfloat16* __restrict__ h,
                       __nv_bfloat16* __restrict__ l, int n4)
{
    int i = blockIdx.x * 256 + threadIdx.x;
    if (i >= n4) return;
    float4 v = ((const float4*)x)[i];
    __nv_bfloat16 h0 = __float2bfloat16(v.x), h1 = __float2bfloat16(v.y);
    __nv_bfloat16 h2 = __float2bfloat16(v.z), h3 = __float2bfloat16(v.w);
    ((__nv_bfloat162*)h)[2*i]   = __nv_bfloat162(h0, h1);
    ((__nv_bfloat162*)h)[2*i+1] = __nv_bfloat162(h2, h3);
    ((__nv_bfloat162*)l)[2*i]   = __nv_bfloat162(__float2bfloat16(v.x - __bfloat162float(h0)),
                                                 __float2bfloat16(v.y - __bfloat162float(h1)));
    ((__nv_bfloat162*)l)[2*i+1] = __nv_bfloat162(__float2bfloat16(v.z - __bfloat162float(h2)),
                                                 __float2bfloat16(v.w - __bfloat162float(h3)));
}

// ---- conv W prep: w[o][c][kk] -> wA[o][kk*C+c], hi/lo split ---------------
__global__ void wsplit(const float* __restrict__ w, __nv_bfloat16* __restrict__ hi,
                       __nv_bfloat16* __restrict__ lo, int C, int O)
{
    int i = blockIdx.x * 256 + threadIdx.x;
    int K3 = 3 * C;
    if (i >= O * K3) return;
    int o = i / K3, rem = i % K3, c = rem / 3, kk = rem % 3;
    float v = w[i];
    __nv_bfloat16 h = __float2bfloat16(v);
    hi[o * K3 + kk * C + c] = h;
    lo[o * K3 + kk * C + c] = __float2bfloat16(v - __bfloat162float(h));
}

// ---- MLP out transpose+split: x4[b][c][n] -> xT[b][n][c] hi/lo (C=64) -----
__global__ void __launch_bounds__(64)
tsplit64(const float* __restrict__ x, __nv_bfloat16* __restrict__ hi,
         __nv_bfloat16* __restrict__ lo)
{
    __shared__ __align__(16) float s[64 * 64];
    const int b = blockIdx.x, t = threadIdx.x;
    const float4* src = (const float4*)(x + (size_t)b * 4096);
    float4* d4 = (float4*)s;
    for (int i = t; i < 1024; i += 64) d4[i] = src[i];
    __syncthreads();
    __align__(16) __nv_bfloat16 rh[64], rl[64];
    #pragma unroll
    for (int c = 0; c < 64; c++) {
        float v = s[c * 64 + t];
        rh[c] = __float2bfloat16(v);
        rl[c] = __float2bfloat16(v - __bfloat162float(rh[c]));
    }
    uint4* dh = (uint4*)(hi + (size_t)b * 4096 + t * 64);
    uint4* dl = (uint4*)(lo + (size_t)b * 4096 + t * 64);
    #pragma unroll
    for (int q = 0; q < 8; q++) { dh[q] = ((uint4*)rh)[q]; dl[q] = ((uint4*)rl)[q]; }
}

// ------------------- dense split-bf16 HMMA GEMM (MLP L3/L4) ----------------
__global__ void __launch_bounds__(256, 2)
gemm_hmma(const __nv_bfloat16* __restrict__ ah, const __nv_bfloat16* __restrict__ al,
          const __nv_bfloat16* __restrict__ wh_, const __nv_bfloat16* __restrict__ wl_,
          const float* __restrict__ bias, float* __restrict__ C, int K, int N)
{
    constexpr int GA = 9216, GW = 4608;
    extern __shared__ __align__(16) __nv_bfloat16 smg[];
    const int tid = threadIdx.x, wid = tid >> 5, lane = tid & 31;
    const int g = lane >> 2, t = lane & 3;
    const int wm = wid & 3, wh = wid >> 2;
    const int m0 = blockIdx.x * 128, n0 = blockIdx.y * 64;

    const uint32_t sA = smem_u32(smg);
    const uint32_t sAl = sA + GA * 2, sW = sA + 2 * GA * 2, sWl = sW + GW * 2;
    const int lrowA = lane & 15, lcolA = (lane >> 4) * 8;
    const int tb = lane >> 3;
    const int lrowB = (tb >> 1) * 8 + (lane & 7), lcolB = (tb & 1) * 8;

    float acc[2][4][4] = {};

    for (int kc = 0; kc < K; kc += 64) {
        __syncthreads();
        #pragma unroll
        for (int it = 0; it < 8; it++) {
            int u = tid + it * 256;
            int sp = u >> 10, r = (u >> 3) & 127, q = u & 7;
            const __nv_bfloat16* src = (sp ? al : ah) + (size_t)(m0 + r) * K + kc + q * 8;
            *(uint4*)(smg + sp * GA + r * 72 + q * 8) = *(const uint4*)src;
        }
        #pragma unroll
        for (int it = 0; it < 4; it++) {
            int u = tid + it * 256;
            int sp = u >> 9, r = (u >> 3) & 63, q = u & 7;
            const __nv_bfloat16* src = (sp ? wl_ : wh_) + (size_t)(n0 + r) * K + kc + q * 8;
            *(uint4*)(smg + 2 * GA + sp * GW + r * 72 + q * 8) = *(const uint4*)src;
        }
        __syncthreads();

        #pragma unroll
        for (int ks = 0; ks < 4; ks++) {
            const int koff = ks * 16;
            uint32_t fah[2][4], fal[2][4];
            #pragma unroll
            for (int mt = 0; mt < 2; mt++) {
                uint32_t off = ((wm * 32 + mt * 16 + lrowA) * 72 + koff + lcolA) * 2;
                ldsm4(fah[mt][0], fah[mt][1], fah[mt][2], fah[mt][3], sA + off);
                ldsm4(fal[mt][0], fal[mt][1], fal[mt][2], fal[mt][3], sAl + off);
            }
            #pragma unroll
            for (int p = 0; p < 2; p++) {
                uint32_t off = ((wh * 32 + p * 16 + lrowB) * 72 + koff + lcolB) * 2;
                uint32_t bh0, bh1, bh2, bh3, bl0, bl1, bl2, bl3;
                ldsm4(bh0, bh1, bh2, bh3, sW + off);
                ldsm4(bl0, bl1, bl2, bl3, sWl + off);
                #pragma unroll
                for (int mt = 0; mt < 2; mt++) {
                    MMA16816(acc[mt][2*p],   fah[mt], bh0, bh1);
                    MMA16816(acc[mt][2*p],   fah[mt], bl0, bl1);
                    MMA16816(acc[mt][2*p],   fal[mt], bh0, bh1);
                    MMA16816(acc[mt][2*p+1], fah[mt], bh2, bh3);
                    MMA16816(acc[mt][2*p+1], fah[mt], bl2, bl3);
                    MMA16816(acc[mt][2*p+1], fal[mt], bh2, bh3);
                }
            }
        }
    }

    #pragma unroll
    for (int mt = 0; mt < 2; mt++) {
        #pragma unroll
        for (int nt = 0; nt < 4; nt++) {
            int col = n0 + wh * 32 + nt * 8 + 2 * t;
            float bv0 = __ldg(&bias[col]), bv1 = __ldg(&bias[col + 1]);
            int row0 = m0 + wm * 32 + mt * 16 + g;
            *(float2*)&C[(size_t)row0 * N + col] =
                make_float2(leaky(acc[mt][nt][0] + bv0), leaky(acc[mt][nt][1] + bv1));
            *(float2*)&C[(size_t)(row0 + 8) * N + col] =
                make_float2(leaky(acc[mt][nt][2] + bv0), leaky(acc[mt][nt][3] + bv1));
        }
    }
}

// --------- conv via mma.sync bf16 hi/lo split, cp.async double-buffer ------
template <int C, int O>
__global__ void __launch_bounds__(256, 1)
conv_hmma(const __nv_bfloat16* __restrict__ xhi, const __nv_bfloat16* __restrict__ xlo,
          const __nv_bfloat16* __restrict__ whi, const __nv_bfloat16* __restrict__ wlo,
          const int* __restrict__ idxg, const float* __restrict__ bias,
          float* __restrict__ pre)
{
    constexpr int K3 = 3 * C, NCH = K3 / 64, CB = C / 64;
    constexpr int BUFH = 36864;            // halves per buffer
    constexpr int BOFF = 18432, BBLK = 4608;
    extern __shared__ __align__(16) __nv_bfloat16 smh[];
    int* idxs = (int*)(smh + 2 * BUFH);

    const int tid = threadIdx.x, wid = tid >> 5, lane = tid & 31;
    const int g = lane >> 2, t = lane & 3;
    const int b0 = blockIdx.y * 2, obase = blockIdx.x * 128;
    const int s = wid >> 2, wm = wid & 3;
    const uint32_t sbase = smem_u32(smh);

    const int lrowA = lane & 15, lcolA = (lane >> 4) * 8;
    const int tb = lane >> 3;
    const int lrowB = (tb >> 1) * 8 + (lane & 7), lcolB = (tb & 1) * 8;

    for (int i = tid; i < 2 * 192; i += 256) {
        int s2 = i / 192, j = i % 192;
        idxs[i] = (j < 189) ? idxg[(size_t)(b0 + s2) * 189 + j] : 0;
    }
    __syncthreads();

    auto prefetch = [&](int ci, int buf) {
        const uint32_t base = sbase + buf * (BUFH * 2);
        #pragma unroll
        for (int it = 0; it < 8; it++) {
            int u = tid + it * 256;
            int sp = u >> 10, r = (u >> 3) & 127, q = u & 7;
            const __nv_bfloat16* src = (sp ? wlo : whi) + (size_t)(obase + r) * K3 + ci * 64 + q * 8;
            cpasync16(base + (sp * 9216 + r * 72 + q * 8) * 2, src);
        }
        const int kk = ci / CB, c0 = (ci % CB) * 64;
        #pragma unroll
        for (int it = 0; it < 8; it++) {
            int u = tid + it * 256;
            int sp = u >> 10, ss = (u >> 9) & 1, n = (u >> 3) & 63, q = u & 7;
            int slot = (n > 0) ? idxs[ss * 192 + (n - 1) * 3 + kk] : 0;
            const __nv_bfloat16* src = (sp ? xlo : xhi)
                + ((size_t)(b0 + ss) * 64 + slot) * C + c0 + q * 8;
            cpasync16z(base + (BOFF + (ss * 2 + sp) * BBLK + n * 72 + q * 8) * 2, src,
                       (n > 0) ? 16 : 0);
        }
        CP_COMMIT();
    };

    float acc[2][8][4] = {};
    prefetch(0, 0);

    for (int ci = 0; ci < NCH; ci++) {
        if (ci + 1 < NCH) {
            prefetch(ci + 1, (ci + 1) & 1);
            asm volatile("cp.async.wait_group 1;");
        } else {
            asm volatile("cp.async.wait_group 0;");
        }
        __syncthreads();

        const uint32_t base = sbase + (ci & 1) * (BUFH * 2);
        const uint32_t sA = base, sAl = base + 9216 * 2;
        const uint32_t sB = base + (BOFF + (s * 2) * BBLK) * 2;
        const uint32_t sBl = sB + BBLK * 2;

        #pragma unroll
        for (int ks = 0; ks < 4; ks++) {
            const int koff = ks * 16;
            uint32_t fah[2][4], fal[2][4];
            #pragma unroll
            for (int mt = 0; mt < 2; mt++) {
                uint32_t off = ((wm * 32 + mt * 16 + lrowA) * 72 + koff + lcolA) * 2;
                ldsm4(fah[mt][0], fah[mt][1], fah[mt][2], fah[mt][3], sA + off);
                ldsm4(fal[mt][0], fal[mt][1], fal[mt][2], fal[mt][3], sAl + off);
            }
            #pragma unroll
            for (int p = 0; p < 4; p++) {
                uint32_t off = ((p * 16 + lrowB) * 72 + koff + lcolB) * 2;
                uint32_t bh0, bh1, bh2, bh3, bl0, bl1, bl2, bl3;
                ldsm4(bh0, bh1, bh2, bh3, sB + off);
                ldsm4(bl0, bl1, bl2, bl3, sBl + off);
                #pragma unroll
                for (int mt = 0; mt < 2; mt++) {
                    MMA16816(acc[mt][2*p],   fah[mt], bh0, bh1);
                    MMA16816(acc[mt][2*p],   fah[mt], bl0, bl1);
                    MMA16816(acc[mt][2*p],   fal[mt], bh0, bh1);
                    MMA16816(acc[mt][2*p+1], fah[mt], bh2, bh3);
                    MMA16816(acc[mt][2*p+1], fah[mt], bl2, bl3);
                    MMA16816(acc[mt][2*p+1], fal[mt], bh2, bh3);
                }
            }
        }
        __syncthreads();
    }

    #pragma unroll
    for (int mt = 0; mt < 2; mt++) {
        int o0 = obase + wm * 32 + mt * 16 + g;
        float bv0 = __ldg(&bias[o0]), bv1 = __ldg(&bias[o0 + 8]);
        float* base0 = pre + ((size_t)(b0 + s) * O + o0) * 64;
        float* base1 = base0 + 8 * 64;
        #pragma unroll
        for (int nt = 0; nt < 8; nt++) {
            int n0 = nt * 8 + 2 * t;
            float m0 = (n0 == 0) ? 0.f : bv0;
            float m1 = (n0 == 0) ? 0.f : bv1;
            *(float2*)(base0 + n0) = make_float2(acc[mt][nt][0] + m0, acc[mt][nt][1] + bv0);
            *(float2*)(base1 + n0) = make_float2(acc[mt][nt][2] + m1, acc[mt][nt][3] + bv1);
        }
    }
}

// ------------- block reduce for LN -----------------------------------------
__device__ __forceinline__ void ln_stats(float s, float ss, float* red, int tid, float nn)
{
    const int lane = tid & 31, warp = tid >> 5;
    #pragma unroll
    for (int sh = 16; sh; sh >>= 1) {
        s  += __shfl_down_sync(0xffffffffu, s,  sh);
        ss += __shfl_down_sync(0xffffffffu, ss, sh);
    }
    if (lane == 0) { red[2 * warp] = s; red[2 * warp + 1] = ss; }
    __syncthreads();
    if (tid == 0) {
        float S = 0.f, SS = 0.f;
        for (int w = 0; w < 8; w++) { S += red[2 * w]; SS += red[2 * w + 1]; }
        float mean = S / nn;
        float var = fmaxf((SS - nn * mean * mean) / (nn - 1.f), 0.f);
        red[16] = mean; red[17] = 1.f / (sqrtf(var) + 1e-5f);
    }
    __syncthreads();
}

// -------- LN + leaky + transpose + split for next conv ---------------------
template <int O>
__global__ void __launch_bounds__(256)
ln_split(const float* __restrict__ pre, __nv_bfloat16* __restrict__ xh,
         __nv_bfloat16* __restrict__ xl)
{
    __shared__ float red[18];
    __shared__ __align__(16) __nv_bfloat16 sh[4096], sl[4096];
    const int b = blockIdx.x, tid = threadIdx.x;
    const float4* p4 = (const float4*)(pre + (size_t)b * O * 64);
    float s = 0.f, ss = 0.f;
    for (int i = tid; i < O * 16; i += 256) {
        float4 v = p4[i];
        s += v.x + v.y + v.z + v.w;
        ss += v.x*v.x + v.y*v.y + v.z*v.z + v.w*v.w;
    }
    ln_stats(s, ss, red, tid, (float)(O * 64));
    const float mean = red[16], scale = red[17];
    for (int ot = 0; ot < O / 64; ot++) {
        #pragma unroll 1
        for (int k = 0; k < 4; k++) {
            int u = tid + k * 256;
            int ol = u >> 4, n4 = u & 15;
            float4 v = p4[(ot * 64 + ol) * 16 + n4];
            float y[4] = { leaky((v.x - mean) * scale), leaky((v.y - mean) * scale),
                           leaky((v.z - mean) * scale), leaky((v.w - mean) * scale) };
            #pragma unroll
            for (int j = 0; j < 4; j++) {
                int n = n4 * 4 + j;
                __nv_bfloat16 h = __float2bfloat16(y[j]);
                sh[n * 64 + ol] = h;
                sl[n * 64 + ol] = __float2bfloat16(y[j] - __bfloat162float(h));
            }
        }
        __syncthreads();
        #pragma unroll 1
        for (int k = 0; k < 2; k++) {
            int u = tid + k * 256;
            int n = u >> 3, q = u & 7;
            size_t base = (size_t)b * 64 * O + (size_t)n * O + ot * 64 + q * 8;
            *(uint4*)(xh + base) = *(uint4*)(sh + n * 64 + q * 8);
            *(uint4*)(xl + base) = *(uint4*)(sl + n * 64 + q * 8);
        }
        __syncthreads();
    }
}

// ---------------- final LN + leaky -> d_out --------------------------------
__global__ void __launch_bounds__(256)
ln_final(const float* __restrict__ pre, float* __restrict__ out)
{
    constexpr int O = 512;
    __shared__ float red[18];
    const int b = blockIdx.x, tid = threadIdx.x;
    const float4* p4 = (const float4*)(pre + (size_t)b * O * 64);
    float4* o4 = (float4*)(out + (size_t)b * O * 64);
    float s = 0.f, ss = 0.f;
    for (int i = tid; i < O * 16; i += 256) {
        float4 v = p4[i];
        s += v.x + v.y + v.z + v.w;
        ss += v.x*v.x + v.y*v.y + v.z*v.z + v.w*v.w;
    }
    ln_stats(s, ss, red, tid, (float)(O * 64));
    const float mean = red[16], scale = red[17];
    for (int i = tid; i < O * 16; i += 256) {
        float4 v = p4[i];
        o4[i] = make_float4(leaky((v.x - mean) * scale), leaky((v.y - mean) * scale),
                            leaky((v.z - mean) * scale), leaky((v.w - mean) * scale));
    }
}

// ------------------------------ host launch --------------------------------
static constexpr int SMEM_CONV = 2 * 36864 * 2 + 2 * 192 * 4;   // 148992 B
static constexpr int SMEM_GEMM = (9216 * 2 + 4608 * 2) * 2;     // 55296 B

extern "C" void kernel_launch(void* const* d_in, const int* in_sizes, int n_in,
                              void* d_out, int out_size)
{
    const float* trees   = (const float*)d_in[0];
    const int*   indexes = (const int*)  d_in[1];
    const float* W1 = (const float*)d_in[2];  const float* b1 = (const float*)d_in[3];
    const float* W2 = (const float*)d_in[4];  const float* b2 = (const float*)d_in[5];
    const float* W3 = (const float*)d_in[6];  const float* b3 = (const float*)d_in[7];
    const float* W4 = (const float*)d_in[8];  const float* b4 = (const float*)d_in[9];
    const float* cw1 = (const float*)d_in[10]; const float* cb1 = (const float*)d_in[11];
    const float* cw2 = (const float*)d_in[12]; const float* cb2 = (const float*)d_in[13];
    const float* cw3 = (const float*)d_in[14]; const float* cb3 = (const float*)d_in[15];

    float *x1, *x2, *x3, *x4, *pre;
    __nv_bfloat16 *xh, *xl, *w1h, *w1l, *w2h, *w2l, *w3h, *w3l;
    __nv_bfloat16 *ma_h, *ma_l, *mw3h, *mw3l, *mw4h, *mw4l;
    cudaGetSymbolAddress((void**)&x1, g_x1);
    cudaGetSymbolAddress((void**)&x2, g_x2);
    cudaGetSymbolAddress((void**)&x3, g_x3);
    cudaGetSymbolAddress((void**)&x4, g_x4);
    cudaGetSymbolAddress((void**)&pre, g_pre);
    cudaGetSymbolAddress((void**)&xh, g_xh);
    cudaGetSymbolAddress((void**)&xl, g_xl);
    cudaGetSymbolAddress((void**)&w1h, g_w1h); cudaGetSymbolAddress((void**)&w1l, g_w1l);
    cudaGetSymbolAddress((void**)&w2h, g_w2h); cudaGetSymbolAddress((void**)&w2l, g_w2l);
    cudaGetSymbolAddress((void**)&w3h, g_w3h); cudaGetSymbolAddress((void**)&w3l, g_w3l);
    cudaGetSymbolAddress((void**)&ma_h, g_ah); cudaGetSymbolAddress((void**)&ma_l, g_al);
    cudaGetSymbolAddress((void**)&mw3h, g_mw3h); cudaGetSymbolAddress((void**)&mw3l, g_mw3l);
    cudaGetSymbolAddress((void**)&mw4h, g_mw4h); cudaGetSymbolAddress((void**)&mw4l, g_mw4l);

    cudaFuncSetAttribute(conv_hmma<64, 128>,  cudaFuncAttributeMaxDynamicSharedMemorySize, SMEM_CONV);
    cudaFuncSetAttribute(conv_hmma<128, 256>, cudaFuncAttributeMaxDynamicSharedMemorySize, SMEM_CONV);
    cudaFuncSetAttribute(conv_hmma<256, 512>, cudaFuncAttributeMaxDynamicSharedMemorySize, SMEM_CONV);
    cudaFuncSetAttribute(gemm_hmma, cudaFuncAttributeMaxDynamicSharedMemorySize, SMEM_GEMM);

    // weight prep
    wsplit<<<96,   256>>>(cw1, w1h, w1l, 64, 128);
    wsplit<<<384,  256>>>(cw2, w2h, w2l, 128, 256);
    wsplit<<<1536, 256>>>(cw3, w3h, w3l, 256, 512);
    asplit<<<256,  256>>>(W3, mw3h, mw3l, 1024 * 256 / 4);
    asplit<<<4096, 256>>>(W4, mw4h, mw4l, 4096 * 1024 / 4);

    // MLP: L1, L2 fp32 (tiny); L3, L4 tensor
    gemm_bias_leaky<<<dim3(32, 1), 128>>>(trees, W1, b1, x1, 16, 64);
    gemm_bias_leaky<<<dim3(32, 4), 128>>>(x1,    W2, b2, x2, 64, 256);
    asplit<<<1024, 256>>>(x2, ma_h, ma_l, 4096 * 256 / 4);
    gemm_hmma<<<dim3(32, 16), 256, SMEM_GEMM>>>(ma_h, ma_l, mw3h, mw3l, b3, x3, 256, 1024);
    asplit<<<4096, 256>>>(x3, ma_h, ma_l, 4096 * 1024 / 4);
    gemm_hmma<<<dim3(32, 64), 256, SMEM_GEMM>>>(ma_h, ma_l, mw4h, mw4l, b4, x4, 1024, 4096);

    // transpose+split MLP output -> xT (C=64)
    tsplit64<<<4096, 64>>>(x4, xh, xl);

    // conv1 -> LN -> conv2 -> LN -> conv3 -> LN(final)
    conv_hmma<64, 128> <<<dim3(1, 2048), 256, SMEM_CONV>>>(xh, xl, w1h, w1l, indexes, cb1, pre);
    ln_split<128><<<4096, 256>>>(pre, xh, xl);
    conv_hmma<128, 256><<<dim3(2, 2048), 256, SMEM_CONV>>>(xh, xl, w2h, w2l, indexes, cb2, pre);
    ln_split<256><<<4096, 256>>>(pre, xh, xl);
    conv_hmma<256, 512><<<dim3(4, 2048), 256, SMEM_CONV>>>(xh, xl, w3h, w3l, indexes, cb3, pre);
    ln_final<<<4096, 256>>>(pre, (float*)d_out);
}

// round 13
// speedup vs baseline: 3.1819x; 1.0630x over previous
#include <cuda_runtime.h>
#include <cuda_bf16.h>
#include <stdint.h>
#include <math.h>

// ------------------------------ scratch ------------------------------------
static __device__ __align__(16) float g_x1[4096 * 64];
static __device__ __align__(16) float g_x2[4096 * 256];
static __device__ __align__(16) float g_x3[4096 * 1024];
static __device__ __align__(16) float g_x4[4096 * 4096];
static __device__ __align__(16) float g_pre[4096 * 512 * 64];
static __device__ __align__(16) __nv_bfloat16 g_xh[4096 * 64 * 256];
static __device__ __align__(16) __nv_bfloat16 g_xl[4096 * 64 * 256];
static __device__ __align__(16) __nv_bfloat16 g_w1h[128 * 192], g_w1l[128 * 192];
static __device__ __align__(16) __nv_bfloat16 g_w2h[256 * 384], g_w2l[256 * 384];
static __device__ __align__(16) __nv_bfloat16 g_w3h[512 * 768], g_w3l[512 * 768];
static __device__ __align__(16) __nv_bfloat16 g_ah[4096 * 1024], g_al[4096 * 1024];
static __device__ __align__(16) __nv_bfloat16 g_mw3h[1024 * 256], g_mw3l[1024 * 256];
static __device__ __align__(16) __nv_bfloat16 g_mw4h[4096 * 1024], g_mw4l[4096 * 1024];

__device__ __forceinline__ float leaky(float v) { return v > 0.f ? v : 0.01f * v; }

__device__ __forceinline__ uint32_t smem_u32(const void* p) {
    uint32_t a;
    asm("{ .reg .u64 t; cvta.to.shared.u64 t, %1; cvt.u32.u64 %0, t; }" : "=r"(a) : "l"(p));
    return a;
}
__device__ __forceinline__ void ldsm4(uint32_t& r0, uint32_t& r1, uint32_t& r2, uint32_t& r3,
                                      uint32_t addr) {
    asm volatile("ldmatrix.sync.aligned.m8n8.x4.shared.b16 {%0,%1,%2,%3}, [%4];"
                 : "=r"(r0), "=r"(r1), "=r"(r2), "=r"(r3) : "r"(addr));
}
__device__ __forceinline__ void cpasync16(uint32_t dst, const void* src) {
    asm volatile("cp.async.cg.shared.global [%0], [%1], 16;" :: "r"(dst), "l"(src));
}
__device__ __forceinline__ void cpasync16z(uint32_t dst, const void* src, int szz) {
    asm volatile("cp.async.cg.shared.global [%0], [%1], 16, %2;" :: "r"(dst), "l"(src), "r"(szz));
}
#define CP_COMMIT() asm volatile("cp.async.commit_group;")
#define MMA16816(d, a, b0_, b1_) \
    asm volatile("mma.sync.aligned.m16n8k16.row.col.f32.bf16.bf16.f32 " \
        "{%0,%1,%2,%3}, {%4,%5,%6,%7}, {%8,%9}, {%0,%1,%2,%3};" \
        : "+f"(d[0]), "+f"(d[1]), "+f"(d[2]), "+f"(d[3]) \
        : "r"(a[0]), "r"(a[1]), "r"(a[2]), "r"(a[3]), "r"(b0_), "r"(b1_))

// ------------------------------ small fp32 GEMM (L1, L2) -------------------
__global__ void __launch_bounds__(128)
gemm_bias_leaky(const float* __restrict__ A, const float* __restrict__ W,
                const float* __restrict__ bias, float* __restrict__ C, int K, int N)
{
    __shared__ __align__(16) float As[16][128];
    __shared__ __align__(16) float Ws[16][64];
    const int tid = threadIdx.x, mt = tid & 15, nt = tid >> 4;
    const float* Ab = A + (size_t)blockIdx.x * 128 * K;
    const float* Wb = W + (size_t)blockIdx.y * 64 * K;
    float acc[8][8] = {};
    for (int k0 = 0; k0 < K; k0 += 16) {
        #pragma unroll
        for (int i = 0; i < 4; i++) {
            int lin = tid + i * 128, r = lin >> 2, c4 = lin & 3;
            float4 v = *(const float4*)(Ab + (size_t)r * K + k0 + c4 * 4);
            As[c4*4+0][r]=v.x; As[c4*4+1][r]=v.y; As[c4*4+2][r]=v.z; As[c4*4+3][r]=v.w;
        }
        #pragma unroll
        for (int i = 0; i < 2; i++) {
            int lin = tid + i * 128, r = lin >> 2, c4 = lin & 3;
            float4 v = *(const float4*)(Wb + (size_t)r * K + k0 + c4 * 4);
            Ws[c4*4+0][r]=v.x; Ws[c4*4+1][r]=v.y; Ws[c4*4+2][r]=v.z; Ws[c4*4+3][r]=v.w;
        }
        __syncthreads();
        #pragma unroll
        for (int kk = 0; kk < 16; kk++) {
            float a[8], w[8];
            *(float4*)&a[0] = *(const float4*)&As[kk][mt*8];
            *(float4*)&a[4] = *(const float4*)&As[kk][mt*8+4];
            *(float4*)&w[0] = *(const float4*)&Ws[kk][nt*8];
            *(float4*)&w[4] = *(const float4*)&Ws[kk][nt*8+4];
            #pragma unroll
            for (int i = 0; i < 8; i++)
                #pragma unroll
                for (int j = 0; j < 8; j++) acc[i][j] = fmaf(a[i], w[j], acc[i][j]);
        }
        __syncthreads();
    }
    float bv[8];
    #pragma unroll
    for (int j = 0; j < 8; j++) bv[j] = __ldg(&bias[blockIdx.y * 64 + nt * 8 + j]);
    #pragma unroll
    for (int i = 0; i < 8; i++) {
        size_t row = (size_t)(blockIdx.x*128 + mt*8 + i) * N + blockIdx.y*64 + nt*8;
        float4 o0, o1;
        o0.x=leaky(acc[i][0]+bv[0]); o0.y=leaky(acc[i][1]+bv[1]);
        o0.z=leaky(acc[i][2]+bv[2]); o0.w=leaky(acc[i][3]+bv[3]);
        o1.x=leaky(acc[i][4]+bv[4]); o1.y=leaky(acc[i][5]+bv[5]);
        o1.z=leaky(acc[i][6]+bv[6]); o1.w=leaky(acc[i][7]+bv[7]);
        *(float4*)&C[row] = o0; *(float4*)&C[row+4] = o1;
    }
}

// ---- elementwise fp32 -> hi/lo bf16 split ---------------------------------
__global__ void asplit(const float* __restrict__ x, __nv_bfloat16* __restrict__ h,
                       __nv_bfloat16* __restrict__ l, int n4)
{
    int i = blockIdx.x * 256 + threadIdx.x;
    if (i >= n4) return;
    float4 v = ((const float4*)x)[i];
    __nv_bfloat16 h0 = __float2bfloat16(v.x), h1 = __float2bfloat16(v.y);
    __nv_bfloat16 h2 = __float2bfloat16(v.z), h3 = __float2bfloat16(v.w);
    ((__nv_bfloat162*)h)[2*i]   = __nv_bfloat162(h0, h1);
    ((__nv_bfloat162*)h)[2*i+1] = __nv_bfloat162(h2, h3);
    ((__nv_bfloat162*)l)[2*i]   = __nv_bfloat162(__float2bfloat16(v.x - __bfloat162float(h0)),
                                                 __float2bfloat16(v.y - __bfloat162float(h1)));
    ((__nv_bfloat162*)l)[2*i+1] = __nv_bfloat162(__float2bfloat16(v.z - __bfloat162float(h2)),
                                                 __float2bfloat16(v.w - __bfloat162float(h3)));
}

// ---- conv W prep: w[o][c][kk] -> wA[o][kk*C+c], hi/lo split ---------------
__global__ void wsplit(const float* __restrict__ w, __nv_bfloat16* __restrict__ hi,
                       __nv_bfloat16* __restrict__ lo, int C, int O)
{
    int i = blockIdx.x * 256 + threadIdx.x;
    int K3 = 3 * C;
    if (i >= O * K3) return;
    int o = i / K3, rem = i % K3, c = rem / 3, kk = rem % 3;
    float v = w[i];
    __nv_bfloat16 h = __float2bfloat16(v);
    hi[o * K3 + kk * C + c] = h;
    lo[o * K3 + kk * C + c] = __float2bfloat16(v - __bfloat162float(h));
}

// ---- MLP out transpose+split: x4[b][c][n] -> xT[b][n][c] hi/lo (C=64) -----
__global__ void __launch_bounds__(64)
tsplit64(const float* __restrict__ x, __nv_bfloat16* __restrict__ hi,
         __nv_bfloat16* __restrict__ lo)
{
    __shared__ __align__(16) float s[64 * 64];
    const int b = blockIdx.x, t = threadIdx.x;
    const float4* src = (const float4*)(x + (size_t)b * 4096);
    float4* d4 = (float4*)s;
    for (int i = t; i < 1024; i += 64) d4[i] = src[i];
    __syncthreads();
    __align__(16) __nv_bfloat16 rh[64], rl[64];
    #pragma unroll
    for (int c = 0; c < 64; c++) {
        float v = s[c * 64 + t];
        rh[c] = __float2bfloat16(v);
        rl[c] = __float2bfloat16(v - __bfloat162float(rh[c]));
    }
    uint4* dh = (uint4*)(hi + (size_t)b * 4096 + t * 64);
    uint4* dl = (uint4*)(lo + (size_t)b * 4096 + t * 64);
    #pragma unroll
    for (int q = 0; q < 8; q++) { dh[q] = ((uint4*)rh)[q]; dl[q] = ((uint4*)rl)[q]; }
}

// ------------------- dense split-bf16 HMMA GEMM (MLP L3/L4) ----------------
__global__ void __launch_bounds__(256, 2)
gemm_hmma(const __nv_bfloat16* __restrict__ ah, const __nv_bfloat16* __restrict__ al,
          const __nv_bfloat16* __restrict__ wh_, const __nv_bfloat16* __restrict__ wl_,
          const float* __restrict__ bias, float* __restrict__ C, int K, int N)
{
    constexpr int GA = 9216, GW = 4608;
    extern __shared__ __align__(16) __nv_bfloat16 smg[];
    const int tid = threadIdx.x, wid = tid >> 5, lane = tid & 31;
    const int g = lane >> 2, t = lane & 3;
    const int wm = wid & 3, wh = wid >> 2;
    const int m0 = blockIdx.x * 128, n0 = blockIdx.y * 64;

    const uint32_t sA = smem_u32(smg);
    const uint32_t sAl = sA + GA * 2, sW = sA + 2 * GA * 2, sWl = sW + GW * 2;
    const int lrowA = lane & 15, lcolA = (lane >> 4) * 8;
    const int tb = lane >> 3;
    const int lrowB = (tb >> 1) * 8 + (lane & 7), lcolB = (tb & 1) * 8;

    float acc[2][4][4] = {};

    for (int kc = 0; kc < K; kc += 64) {
        __syncthreads();
        #pragma unroll
        for (int it = 0; it < 8; it++) {
            int u = tid + it * 256;
            int sp = u >> 10, r = (u >> 3) & 127, q = u & 7;
            const __nv_bfloat16* src = (sp ? al : ah) + (size_t)(m0 + r) * K + kc + q * 8;
            *(uint4*)(smg + sp * GA + r * 72 + q * 8) = *(const uint4*)src;
        }
        #pragma unroll
        for (int it = 0; it < 4; it++) {
            int u = tid + it * 256;
            int sp = u >> 9, r = (u >> 3) & 63, q = u & 7;
            const __nv_bfloat16* src = (sp ? wl_ : wh_) + (size_t)(n0 + r) * K + kc + q * 8;
            *(uint4*)(smg + 2 * GA + sp * GW + r * 72 + q * 8) = *(const uint4*)src;
        }
        __syncthreads();

        #pragma unroll
        for (int ks = 0; ks < 4; ks++) {
            const int koff = ks * 16;
            uint32_t fah[2][4], fal[2][4];
            #pragma unroll
            for (int mt = 0; mt < 2; mt++) {
                uint32_t off = ((wm * 32 + mt * 16 + lrowA) * 72 + koff + lcolA) * 2;
                ldsm4(fah[mt][0], fah[mt][1], fah[mt][2], fah[mt][3], sA + off);
                ldsm4(fal[mt][0], fal[mt][1], fal[mt][2], fal[mt][3], sAl + off);
            }
            #pragma unroll
            for (int p = 0; p < 2; p++) {
                uint32_t off = ((wh * 32 + p * 16 + lrowB) * 72 + koff + lcolB) * 2;
                uint32_t bh0, bh1, bh2, bh3, bl0, bl1, bl2, bl3;
                ldsm4(bh0, bh1, bh2, bh3, sW + off);
                ldsm4(bl0, bl1, bl2, bl3, sWl + off);
                #pragma unroll
                for (int mt = 0; mt < 2; mt++) {
                    MMA16816(acc[mt][2*p],   fah[mt], bh0, bh1);
                    MMA16816(acc[mt][2*p],   fah[mt], bl0, bl1);
                    MMA16816(acc[mt][2*p],   fal[mt], bh0, bh1);
                    MMA16816(acc[mt][2*p+1], fah[mt], bh2, bh3);
                    MMA16816(acc[mt][2*p+1], fah[mt], bl2, bl3);
                    MMA16816(acc[mt][2*p+1], fal[mt], bh2, bh3);
                }
            }
        }
    }

    #pragma unroll
    for (int mt = 0; mt < 2; mt++) {
        #pragma unroll
        for (int nt = 0; nt < 4; nt++) {
            int col = n0 + wh * 32 + nt * 8 + 2 * t;
            float bv0 = __ldg(&bias[col]), bv1 = __ldg(&bias[col + 1]);
            int row0 = m0 + wm * 32 + mt * 16 + g;
            *(float2*)&C[(size_t)row0 * N + col] =
                make_float2(leaky(acc[mt][nt][0] + bv0), leaky(acc[mt][nt][1] + bv1));
            *(float2*)&C[(size_t)(row0 + 8) * N + col] =
                make_float2(leaky(acc[mt][nt][2] + bv0), leaky(acc[mt][nt][3] + bv1));
        }
    }
}

// --- conv: mma.sync bf16 hi/lo split, cp.async double-buffer, 4 samples/CTA
// Buffer (halves): A hi/lo 2x9216 | B 4 samples x 2 splits x 4608. Two buffers.
template <int C, int O>
__global__ void __launch_bounds__(256, 1)
conv_hmma(const __nv_bfloat16* __restrict__ xhi, const __nv_bfloat16* __restrict__ xlo,
          const __nv_bfloat16* __restrict__ whi, const __nv_bfloat16* __restrict__ wlo,
          const int* __restrict__ idxg, const float* __restrict__ bias,
          float* __restrict__ pre)
{
    constexpr int K3 = 3 * C, NCH = K3 / 64, CB = C / 64;
    constexpr int BOFFH = 18432;            // halves: start of B region
    constexpr int BBLK = 4608;              // halves per (sample, split)
    constexpr int BUFH = BOFFH + 8 * BBLK;  // 55296 halves per buffer
    extern __shared__ __align__(16) __nv_bfloat16 smh[];
    int* idxs = (int*)(smh + 2 * BUFH);

    const int tid = threadIdx.x, wid = tid >> 5, lane = tid & 31;
    const int g = lane >> 2, t = lane & 3;
    const int b0 = blockIdx.y * 4, obase = blockIdx.x * 128;
    const int sp2 = wid >> 2, wm = wid & 3;   // sample-pair, M strip
    const uint32_t sbase = smem_u32(smh);

    const int lrowA = lane & 15, lcolA = (lane >> 4) * 8;
    const int tb = lane >> 3;
    const int lrowB = (tb >> 1) * 8 + (lane & 7), lcolB = (tb & 1) * 8;

    for (int i = tid; i < 4 * 192; i += 256) {
        int s2 = i / 192, j = i % 192;
        idxs[i] = (j < 189) ? idxg[(size_t)(b0 + s2) * 189 + j] : 0;
    }
    __syncthreads();

    auto prefetch = [&](int ci, int buf) {
        const uint32_t base = sbase + buf * (BUFH * 2);
        #pragma unroll
        for (int it = 0; it < 8; it++) {
            int u = tid + it * 256;
            int sp = u >> 10, r = (u >> 3) & 127, q = u & 7;
            const __nv_bfloat16* src = (sp ? wlo : whi) + (size_t)(obase + r) * K3 + ci * 64 + q * 8;
            cpasync16(base + (sp * 9216 + r * 72 + q * 8) * 2, src);
        }
        const int kk = ci / CB, c0 = (ci % CB) * 64;
        #pragma unroll
        for (int it = 0; it < 16; it++) {
            int u = tid + it * 256;
            int ss = u >> 10, sp = (u >> 9) & 1, n = (u >> 3) & 63, q = u & 7;
            int slot = (n > 0) ? idxs[ss * 192 + (n - 1) * 3 + kk] : 0;
            const __nv_bfloat16* src = (sp ? xlo : xhi)
                + ((size_t)(b0 + ss) * 64 + slot) * C + c0 + q * 8;
            cpasync16z(base + (BOFFH + (ss * 2 + sp) * BBLK + n * 72 + q * 8) * 2, src,
                       (n > 0) ? 16 : 0);
        }
        CP_COMMIT();
    };

    float acc[2][2][8][4] = {};   // [si][mt][nt][frag]
    prefetch(0, 0);

    for (int ci = 0; ci < NCH; ci++) {
        if (ci + 1 < NCH) {
            prefetch(ci + 1, (ci + 1) & 1);
            asm volatile("cp.async.wait_group 1;");
        } else {
            asm volatile("cp.async.wait_group 0;");
        }
        __syncthreads();

        const uint32_t base = sbase + (ci & 1) * (BUFH * 2);
        const uint32_t sA = base, sAl = base + 9216 * 2;

        #pragma unroll
        for (int ks = 0; ks < 4; ks++) {
            const int koff = ks * 16;
            uint32_t fah[2][4], fal[2][4];
            #pragma unroll
            for (int mt = 0; mt < 2; mt++) {
                uint32_t off = ((wm * 32 + mt * 16 + lrowA) * 72 + koff + lcolA) * 2;
                ldsm4(fah[mt][0], fah[mt][1], fah[mt][2], fah[mt][3], sA + off);
                ldsm4(fal[mt][0], fal[mt][1], fal[mt][2], fal[mt][3], sAl + off);
            }
            #pragma unroll
            for (int si = 0; si < 2; si++) {
                const uint32_t sB  = base + (BOFFH + ((sp2 * 2 + si) * 2) * BBLK) * 2;
                const uint32_t sBl = sB + BBLK * 2;
                #pragma unroll
                for (int p = 0; p < 4; p++) {
                    uint32_t off = ((p * 16 + lrowB) * 72 + koff + lcolB) * 2;
                    uint32_t bh0, bh1, bh2, bh3, bl0, bl1, bl2, bl3;
                    ldsm4(bh0, bh1, bh2, bh3, sB + off);
                    ldsm4(bl0, bl1, bl2, bl3, sBl + off);
                    #pragma unroll
                    for (int mt = 0; mt < 2; mt++) {
                        MMA16816(acc[si][mt][2*p],   fah[mt], bh0, bh1);
                        MMA16816(acc[si][mt][2*p],   fah[mt], bl0, bl1);
                        MMA16816(acc[si][mt][2*p],   fal[mt], bh0, bh1);
                        MMA16816(acc[si][mt][2*p+1], fah[mt], bh2, bh3);
                        MMA16816(acc[si][mt][2*p+1], fah[mt], bl2, bl3);
                        MMA16816(acc[si][mt][2*p+1], fal[mt], bh2, bh3);
                    }
                }
            }
        }
        __syncthreads();
    }

    #pragma unroll
    for (int si = 0; si < 2; si++) {
        #pragma unroll
        for (int mt = 0; mt < 2; mt++) {
            int o0 = obase + wm * 32 + mt * 16 + g;
            float bv0 = __ldg(&bias[o0]), bv1 = __ldg(&bias[o0 + 8]);
            float* base0 = pre + ((size_t)(b0 + sp2 * 2 + si) * O + o0) * 64;
            float* base1 = base0 + 8 * 64;
            #pragma unroll
            for (int nt = 0; nt < 8; nt++) {
                int n0 = nt * 8 + 2 * t;
                float m0 = (n0 == 0) ? 0.f : bv0;
                float m1 = (n0 == 0) ? 0.f : bv1;
                *(float2*)(base0 + n0) = make_float2(acc[si][mt][nt][0] + m0,
                                                     acc[si][mt][nt][1] + bv0);
                *(float2*)(base1 + n0) = make_float2(acc[si][mt][nt][2] + m1,
                                                     acc[si][mt][nt][3] + bv1);
            }
        }
    }
}

// ------------- block reduce for LN -----------------------------------------
__device__ __forceinline__ void ln_stats(float s, float ss, float* red, int tid, float nn)
{
    const int lane = tid & 31, warp = tid >> 5;
    #pragma unroll
    for (int sh = 16; sh; sh >>= 1) {
        s  += __shfl_down_sync(0xffffffffu, s,  sh);
        ss += __shfl_down_sync(0xffffffffu, ss, sh);
    }
    if (lane == 0) { red[2 * warp] = s; red[2 * warp + 1] = ss; }
    __syncthreads();
    if (tid == 0) {
        float S = 0.f, SS = 0.f;
        for (int w = 0; w < 8; w++) { S += red[2 * w]; SS += red[2 * w + 1]; }
        float mean = S / nn;
        float var = fmaxf((SS - nn * mean * mean) / (nn - 1.f), 0.f);
        red[16] = mean; red[17] = 1.f / (sqrtf(var) + 1e-5f);
    }
    __syncthreads();
}

// -------- LN + leaky + transpose + split for next conv ---------------------
template <int O>
__global__ void __launch_bounds__(256)
ln_split(const float* __restrict__ pre, __nv_bfloat16* __restrict__ xh,
         __nv_bfloat16* __restrict__ xl)
{
    __shared__ float red[18];
    __shared__ __align__(16) __nv_bfloat16 sh[4096], sl[4096];
    const int b = blockIdx.x, tid = threadIdx.x;
    const float4* p4 = (const float4*)(pre + (size_t)b * O * 64);
    float s = 0.f, ss = 0.f;
    for (int i = tid; i < O * 16; i += 256) {
        float4 v = p4[i];
        s += v.x + v.y + v.z + v.w;
        ss += v.x*v.x + v.y*v.y + v.z*v.z + v.w*v.w;
    }
    ln_stats(s, ss, red, tid, (float)(O * 64));
    const float mean = red[16], scale = red[17];
    for (int ot = 0; ot < O / 64; ot++) {
        #pragma unroll 1
        for (int k = 0; k < 4; k++) {
            int u = tid + k * 256;
            int ol = u >> 4, n4 = u & 15;
            float4 v = p4[(ot * 64 + ol) * 16 + n4];
            float y[4] = { leaky((v.x - mean) * scale), leaky((v.y - mean) * scale),
                           leaky((v.z - mean) * scale), leaky((v.w - mean) * scale) };
            #pragma unroll
            for (int j = 0; j < 4; j++) {
                int n = n4 * 4 + j;
                __nv_bfloat16 h = __float2bfloat16(y[j]);
                sh[n * 64 + ol] = h;
                sl[n * 64 + ol] = __float2bfloat16(y[j] - __bfloat162float(h));
            }
        }
        __syncthreads();
        #pragma unroll 1
        for (int k = 0; k < 2; k++) {
            int u = tid + k * 256;
            int n = u >> 3, q = u & 7;
            size_t base = (size_t)b * 64 * O + (size_t)n * O + ot * 64 + q * 8;
            *(uint4*)(xh + base) = *(uint4*)(sh + n * 64 + q * 8);
            *(uint4*)(xl + base) = *(uint4*)(sl + n * 64 + q * 8);
        }
        __syncthreads();
    }
}

// ---------------- final LN + leaky -> d_out --------------------------------
__global__ void __launch_bounds__(256)
ln_final(const float* __restrict__ pre, float* __restrict__ out)
{
    constexpr int O = 512;
    __shared__ float red[18];
    const int b = blockIdx.x, tid = threadIdx.x;
    const float4* p4 = (const float4*)(pre + (size_t)b * O * 64);
    float4* o4 = (float4*)(out + (size_t)b * O * 64);
    float s = 0.f, ss = 0.f;
    for (int i = tid; i < O * 16; i += 256) {
        float4 v = p4[i];
        s += v.x + v.y + v.z + v.w;
        ss += v.x*v.x + v.y*v.y + v.z*v.z + v.w*v.w;
    }
    ln_stats(s, ss, red, tid, (float)(O * 64));
    const float mean = red[16], scale = red[17];
    for (int i = tid; i < O * 16; i += 256) {
        float4 v = p4[i];
        o4[i] = make_float4(leaky((v.x - mean) * scale), leaky((v.y - mean) * scale),
                            leaky((v.z - mean) * scale), leaky((v.w - mean) * scale));
    }
}

// ------------------------------ host launch --------------------------------
static constexpr int SMEM_CONV = 2 * 55296 * 2 + 4 * 192 * 4;   // 224256 B
static constexpr int SMEM_GEMM = (9216 * 2 + 4608 * 2) * 2;     // 55296 B

extern "C" void kernel_launch(void* const* d_in, const int* in_sizes, int n_in,
                              void* d_out, int out_size)
{
    const float* trees   = (const float*)d_in[0];
    const int*   indexes = (const int*)  d_in[1];
    const float* W1 = (const float*)d_in[2];  const float* b1 = (const float*)d_in[3];
    const float* W2 = (const float*)d_in[4];  const float* b2 = (const float*)d_in[5];
    const float* W3 = (const float*)d_in[6];  const float* b3 = (const float*)d_in[7];
    const float* W4 = (const float*)d_in[8];  const float* b4 = (const float*)d_in[9];
    const float* cw1 = (const float*)d_in[10]; const float* cb1 = (const float*)d_in[11];
    const float* cw2 = (const float*)d_in[12]; const float* cb2 = (const float*)d_in[13];
    const float* cw3 = (const float*)d_in[14]; const float* cb3 = (const float*)d_in[15];

    float *x1, *x2, *x3, *x4, *pre;
    __nv_bfloat16 *xh, *xl, *w1h, *w1l, *w2h, *w2l, *w3h, *w3l;
    __nv_bfloat16 *ma_h, *ma_l, *mw3h, *mw3l, *mw4h, *mw4l;
    cudaGetSymbolAddress((void**)&x1, g_x1);
    cudaGetSymbolAddress((void**)&x2, g_x2);
    cudaGetSymbolAddress((void**)&x3, g_x3);
    cudaGetSymbolAddress((void**)&x4, g_x4);
    cudaGetSymbolAddress((void**)&pre, g_pre);
    cudaGetSymbolAddress((void**)&xh, g_xh);
    cudaGetSymbolAddress((void**)&xl, g_xl);
    cudaGetSymbolAddress((void**)&w1h, g_w1h); cudaGetSymbolAddress((void**)&w1l, g_w1l);
    cudaGetSymbolAddress((void**)&w2h, g_w2h); cudaGetSymbolAddress((void**)&w2l, g_w2l);
    cudaGetSymbolAddress((void**)&w3h, g_w3h); cudaGetSymbolAddress((void**)&w3l, g_w3l);
    cudaGetSymbolAddress((void**)&ma_h, g_ah); cudaGetSymbolAddress((void**)&ma_l, g_al);
    cudaGetSymbolAddress((void**)&mw3h, g_mw3h); cudaGetSymbolAddress((void**)&mw3l, g_mw3l);
    cudaGetSymbolAddress((void**)&mw4h, g_mw4h); cudaGetSymbolAddress((void**)&mw4l, g_mw4l);

    cudaFuncSetAttribute(conv_hmma<64, 128>,  cudaFuncAttributeMaxDynamicSharedMemorySize, SMEM_CONV);
    cudaFuncSetAttribute(conv_hmma<128, 256>, cudaFuncAttributeMaxDynamicSharedMemorySize, SMEM_CONV);
    cudaFuncSetAttribute(conv_hmma<256, 512>, cudaFuncAttributeMaxDynamicSharedMemorySize, SMEM_CONV);
    cudaFuncSetAttribute(gemm_hmma, cudaFuncAttributeMaxDynamicSharedMemorySize, SMEM_GEMM);

    // weight prep
    wsplit<<<96,   256>>>(cw1, w1h, w1l, 64, 128);
    wsplit<<<384,  256>>>(cw2, w2h, w2l, 128, 256);
    wsplit<<<1536, 256>>>(cw3, w3h, w3l, 256, 512);
    asplit<<<256,  256>>>(W3, mw3h, mw3l, 1024 * 256 / 4);
    asplit<<<4096, 256>>>(W4, mw4h, mw4l, 4096 * 1024 / 4);

    // MLP: L1, L2 fp32 (tiny); L3, L4 tensor
    gemm_bias_leaky<<<dim3(32, 1), 128>>>(trees, W1, b1, x1, 16, 64);
    gemm_bias_leaky<<<dim3(32, 4), 128>>>(x1,    W2, b2, x2, 64, 256);
    asplit<<<1024, 256>>>(x2, ma_h, ma_l, 4096 * 256 / 4);
    gemm_hmma<<<dim3(32, 16), 256, SMEM_GEMM>>>(ma_h, ma_l, mw3h, mw3l, b3, x3, 256, 1024);
    asplit<<<4096, 256>>>(x3, ma_h, ma_l, 4096 * 1024 / 4);
    gemm_hmma<<<dim3(32, 64), 256, SMEM_GEMM>>>(ma_h, ma_l, mw4h, mw4l, b4, x4, 1024, 4096);

    // transpose+split MLP output -> xT (C=64)
    tsplit64<<<4096, 64>>>(x4, xh, xl);

    // conv1 -> LN -> conv2 -> LN -> conv3 -> LN(final); 4 samples per CTA
    conv_hmma<64, 128> <<<dim3(1, 1024), 256, SMEM_CONV>>>(xh, xl, w1h, w1l, indexes, cb1, pre);
    ln_split<128><<<4096, 256>>>(pre, xh, xl);
    conv_hmma<128, 256><<<dim3(2, 1024), 256, SMEM_CONV>>>(xh, xl, w2h, w2l, indexes, cb2, pre);
    ln_split<256><<<4096, 256>>>(pre, xh, xl);
    conv_hmma<256, 512><<<dim3(4, 1024), 256, SMEM_CONV>>>(xh, xl, w3h, w3l, indexes, cb3, pre);
    ln_final<<<4096, 256>>>(pre, (float*)d_out);
}

// round 14
// speedup vs baseline: 3.2724x; 1.0284x over previous
#include <cuda_runtime.h>
#include <cuda_bf16.h>
#include <stdint.h>
#include <math.h>

// ------------------------------ scratch ------------------------------------
static __device__ __align__(16) float g_x1[4096 * 64];
static __device__ __align__(16) float g_x2[4096 * 256];
static __device__ __align__(16) float g_x3[4096 * 1024];
static __device__ __align__(16) float g_x4[4096 * 4096];
static __device__ __align__(16) float g_pre[4096 * 512 * 64];
static __device__ __align__(16) float2 g_part[4096 * 4];            // per (sample, mtile) sum/ss
static __device__ __align__(16) __nv_bfloat16 g_xh[4096 * 64 * 256];
static __device__ __align__(16) __nv_bfloat16 g_xl[4096 * 64 * 256];
static __device__ __align__(16) __nv_bfloat16 g_w1h[128 * 192], g_w1l[128 * 192];
static __device__ __align__(16) __nv_bfloat16 g_w2h[256 * 384], g_w2l[256 * 384];
static __device__ __align__(16) __nv_bfloat16 g_w3h[512 * 768], g_w3l[512 * 768];
static __device__ __align__(16) __nv_bfloat16 g_ah[4096 * 1024], g_al[4096 * 1024];
static __device__ __align__(16) __nv_bfloat16 g_mw3h[1024 * 256], g_mw3l[1024 * 256];
static __device__ __align__(16) __nv_bfloat16 g_mw4h[4096 * 1024], g_mw4l[4096 * 1024];

__device__ __forceinline__ float leaky(float v) { return v > 0.f ? v : 0.01f * v; }

__device__ __forceinline__ uint32_t smem_u32(const void* p) {
    uint32_t a;
    asm("{ .reg .u64 t; cvta.to.shared.u64 t, %1; cvt.u32.u64 %0, t; }" : "=r"(a) : "l"(p));
    return a;
}
__device__ __forceinline__ void ldsm4(uint32_t& r0, uint32_t& r1, uint32_t& r2, uint32_t& r3,
                                      uint32_t addr) {
    asm volatile("ldmatrix.sync.aligned.m8n8.x4.shared.b16 {%0,%1,%2,%3}, [%4];"
                 : "=r"(r0), "=r"(r1), "=r"(r2), "=r"(r3) : "r"(addr));
}
__device__ __forceinline__ void cpasync16(uint32_t dst, const void* src) {
    asm volatile("cp.async.cg.shared.global [%0], [%1], 16;" :: "r"(dst), "l"(src));
}
__device__ __forceinline__ void cpasync16z(uint32_t dst, const void* src, int szz) {
    asm volatile("cp.async.cg.shared.global [%0], [%1], 16, %2;" :: "r"(dst), "l"(src), "r"(szz));
}
#define CP_COMMIT() asm volatile("cp.async.commit_group;")
#define MMA16816(d, a, b0_, b1_) \
    asm volatile("mma.sync.aligned.m16n8k16.row.col.f32.bf16.bf16.f32 " \
        "{%0,%1,%2,%3}, {%4,%5,%6,%7}, {%8,%9}, {%0,%1,%2,%3};" \
        : "+f"(d[0]), "+f"(d[1]), "+f"(d[2]), "+f"(d[3]) \
        : "r"(a[0]), "r"(a[1]), "r"(a[2]), "r"(a[3]), "r"(b0_), "r"(b1_))

// ------------------------------ small fp32 GEMM (L1, L2) -------------------
__global__ void __launch_bounds__(128)
gemm_bias_leaky(const float* __restrict__ A, const float* __restrict__ W,
                const float* __restrict__ bias, float* __restrict__ C, int K, int N)
{
    __shared__ __align__(16) float As[16][128];
    __shared__ __align__(16) float Ws[16][64];
    const int tid = threadIdx.x, mt = tid & 15, nt = tid >> 4;
    const float* Ab = A + (size_t)blockIdx.x * 128 * K;
    const float* Wb = W + (size_t)blockIdx.y * 64 * K;
    float acc[8][8] = {};
    for (int k0 = 0; k0 < K; k0 += 16) {
        #pragma unroll
        for (int i = 0; i < 4; i++) {
            int lin = tid + i * 128, r = lin >> 2, c4 = lin & 3;
            float4 v = *(const float4*)(Ab + (size_t)r * K + k0 + c4 * 4);
            As[c4*4+0][r]=v.x; As[c4*4+1][r]=v.y; As[c4*4+2][r]=v.z; As[c4*4+3][r]=v.w;
        }
        #pragma unroll
        for (int i = 0; i < 2; i++) {
            int lin = tid + i * 128, r = lin >> 2, c4 = lin & 3;
            float4 v = *(const float4*)(Wb + (size_t)r * K + k0 + c4 * 4);
            Ws[c4*4+0][r]=v.x; Ws[c4*4+1][r]=v.y; Ws[c4*4+2][r]=v.z; Ws[c4*4+3][r]=v.w;
        }
        __syncthreads();
        #pragma unroll
        for (int kk = 0; kk < 16; kk++) {
            float a[8], w[8];
            *(float4*)&a[0] = *(const float4*)&As[kk][mt*8];
            *(float4*)&a[4] = *(const float4*)&As[kk][mt*8+4];
            *(float4*)&w[0] = *(const float4*)&Ws[kk][nt*8];
            *(float4*)&w[4] = *(const float4*)&Ws[kk][nt*8+4];
            #pragma unroll
            for (int i = 0; i < 8; i++)
                #pragma unroll
                for (int j = 0; j < 8; j++) acc[i][j] = fmaf(a[i], w[j], acc[i][j]);
        }
        __syncthreads();
    }
    float bv[8];
    #pragma unroll
    for (int j = 0; j < 8; j++) bv[j] = __ldg(&bias[blockIdx.y * 64 + nt * 8 + j]);
    #pragma unroll
    for (int i = 0; i < 8; i++) {
        size_t row = (size_t)(blockIdx.x*128 + mt*8 + i) * N + blockIdx.y*64 + nt*8;
        float4 o0, o1;
        o0.x=leaky(acc[i][0]+bv[0]); o0.y=leaky(acc[i][1]+bv[1]);
        o0.z=leaky(acc[i][2]+bv[2]); o0.w=leaky(acc[i][3]+bv[3]);
        o1.x=leaky(acc[i][4]+bv[4]); o1.y=leaky(acc[i][5]+bv[5]);
        o1.z=leaky(acc[i][6]+bv[6]); o1.w=leaky(acc[i][7]+bv[7]);
        *(float4*)&C[row] = o0; *(float4*)&C[row+4] = o1;
    }
}

// ---- elementwise fp32 -> hi/lo bf16 split ---------------------------------
__global__ void asplit(const float* __restrict__ x, __nv_bfloat16* __restrict__ h,
                       __nv_bfloat16* __restrict__ l, int n4)
{
    int i = blockIdx.x * 256 + threadIdx.x;
    if (i >= n4) return;
    float4 v = ((const float4*)x)[i];
    __nv_bfloat16 h0 = __float2bfloat16(v.x), h1 = __float2bfloat16(v.y);
    __nv_bfloat16 h2 = __float2bfloat16(v.z), h3 = __float2bfloat16(v.w);
    ((__nv_bfloat162*)h)[2*i]   = __nv_bfloat162(h0, h1);
    ((__nv_bfloat162*)h)[2*i+1] = __nv_bfloat162(h2, h3);
    ((__nv_bfloat162*)l)[2*i]   = __nv_bfloat162(__float2bfloat16(v.x - __bfloat162float(h0)),
                                                 __float2bfloat16(v.y - __bfloat162float(h1)));
    ((__nv_bfloat162*)l)[2*i+1] = __nv_bfloat162(__float2bfloat16(v.z - __bfloat162float(h2)),
                                                 __float2bfloat16(v.w - __bfloat162float(h3)));
}

// ---- conv W prep: w[o][c][kk] -> wA[o][kk*C+c], hi/lo split ---------------
__global__ void wsplit(const float* __restrict__ w, __nv_bfloat16* __restrict__ hi,
                       __nv_bfloat16* __restrict__ lo, int C, int O)
{
    int i = blockIdx.x * 256 + threadIdx.x;
    int K3 = 3 * C;
    if (i >= O * K3) return;
    int o = i / K3, rem = i % K3, c = rem / 3, kk = rem % 3;
    float v = w[i];
    __nv_bfloat16 h = __float2bfloat16(v);
    hi[o * K3 + kk * C + c] = h;
    lo[o * K3 + kk * C + c] = __float2bfloat16(v - __bfloat162float(h));
}

// ---- MLP out transpose+split: x4[b][c][n] -> xT[b][n][c] hi/lo (C=64) -----
__global__ void __launch_bounds__(64)
tsplit64(const float* __restrict__ x, __nv_bfloat16* __restrict__ hi,
         __nv_bfloat16* __restrict__ lo)
{
    __shared__ __align__(16) float s[64 * 64];
    const int b = blockIdx.x, t = threadIdx.x;
    const float4* src = (const float4*)(x + (size_t)b * 4096);
    float4* d4 = (float4*)s;
    for (int i = t; i < 1024; i += 64) d4[i] = src[i];
    __syncthreads();
    __align__(16) __nv_bfloat16 rh[64], rl[64];
    #pragma unroll
    for (int c = 0; c < 64; c++) {
        float v = s[c * 64 + t];
        rh[c] = __float2bfloat16(v);
        rl[c] = __float2bfloat16(v - __bfloat162float(rh[c]));
    }
    uint4* dh = (uint4*)(hi + (size_t)b * 4096 + t * 64);
    uint4* dl = (uint4*)(lo + (size_t)b * 4096 + t * 64);
    #pragma unroll
    for (int q = 0; q < 8; q++) { dh[q] = ((uint4*)rh)[q]; dl[q] = ((uint4*)rl)[q]; }
}

// ------------------- dense split-bf16 HMMA GEMM (MLP L3/L4) ----------------
__global__ void __launch_bounds__(256, 2)
gemm_hmma(const __nv_bfloat16* __restrict__ ah, const __nv_bfloat16* __restrict__ al,
          const __nv_bfloat16* __restrict__ wh_, const __nv_bfloat16* __restrict__ wl_,
          const float* __restrict__ bias, float* __restrict__ C, int K, int N)
{
    constexpr int GA = 9216, GW = 4608;
    extern __shared__ __align__(16) __nv_bfloat16 smg[];
    const int tid = threadIdx.x, wid = tid >> 5, lane = tid & 31;
    const int g = lane >> 2, t = lane & 3;
    const int wm = wid & 3, wh = wid >> 2;
    const int m0 = blockIdx.x * 128, n0 = blockIdx.y * 64;

    const uint32_t sA = smem_u32(smg);
    const uint32_t sAl = sA + GA * 2, sW = sA + 2 * GA * 2, sWl = sW + GW * 2;
    const int lrowA = lane & 15, lcolA = (lane >> 4) * 8;
    const int tb = lane >> 3;
    const int lrowB = (tb >> 1) * 8 + (lane & 7), lcolB = (tb & 1) * 8;

    float acc[2][4][4] = {};

    for (int kc = 0; kc < K; kc += 64) {
        __syncthreads();
        #pragma unroll
        for (int it = 0; it < 8; it++) {
            int u = tid + it * 256;
            int sp = u >> 10, r = (u >> 3) & 127, q = u & 7;
            const __nv_bfloat16* src = (sp ? al : ah) + (size_t)(m0 + r) * K + kc + q * 8;
            *(uint4*)(smg + sp * GA + r * 72 + q * 8) = *(const uint4*)src;
        }
        #pragma unroll
        for (int it = 0; it < 4; it++) {
            int u = tid + it * 256;
            int sp = u >> 9, r = (u >> 3) & 63, q = u & 7;
            const __nv_bfloat16* src = (sp ? wl_ : wh_) + (size_t)(n0 + r) * K + kc + q * 8;
            *(uint4*)(smg + 2 * GA + sp * GW + r * 72 + q * 8) = *(const uint4*)src;
        }
        __syncthreads();

        #pragma unroll
        for (int ks = 0; ks < 4; ks++) {
            const int koff = ks * 16;
            uint32_t fah[2][4], fal[2][4];
            #pragma unroll
            for (int mt = 0; mt < 2; mt++) {
                uint32_t off = ((wm * 32 + mt * 16 + lrowA) * 72 + koff + lcolA) * 2;
                ldsm4(fah[mt][0], fah[mt][1], fah[mt][2], fah[mt][3], sA + off);
                ldsm4(fal[mt][0], fal[mt][1], fal[mt][2], fal[mt][3], sAl + off);
            }
            #pragma unroll
            for (int p = 0; p < 2; p++) {
                uint32_t off = ((wh * 32 + p * 16 + lrowB) * 72 + koff + lcolB) * 2;
                uint32_t bh0, bh1, bh2, bh3, bl0, bl1, bl2, bl3;
                ldsm4(bh0, bh1, bh2, bh3, sW + off);
                ldsm4(bl0, bl1, bl2, bl3, sWl + off);
                #pragma unroll
                for (int mt = 0; mt < 2; mt++) {
                    MMA16816(acc[mt][2*p],   fah[mt], bh0, bh1);
                    MMA16816(acc[mt][2*p],   fah[mt], bl0, bl1);
                    MMA16816(acc[mt][2*p],   fal[mt], bh0, bh1);
                    MMA16816(acc[mt][2*p+1], fah[mt], bh2, bh3);
                    MMA16816(acc[mt][2*p+1], fah[mt], bl2, bl3);
                    MMA16816(acc[mt][2*p+1], fal[mt], bh2, bh3);
                }
            }
        }
    }

    #pragma unroll
    for (int mt = 0; mt < 2; mt++) {
        #pragma unroll
        for (int nt = 0; nt < 4; nt++) {
            int col = n0 + wh * 32 + nt * 8 + 2 * t;
            float bv0 = __ldg(&bias[col]), bv1 = __ldg(&bias[col + 1]);
            int row0 = m0 + wm * 32 + mt * 16 + g;
            *(float2*)&C[(size_t)row0 * N + col] =
                make_float2(leaky(acc[mt][nt][0] + bv0), leaky(acc[mt][nt][1] + bv1));
            *(float2*)&C[(size_t)(row0 + 8) * N + col] =
                make_float2(leaky(acc[mt][nt][2] + bv0), leaky(acc[mt][nt][3] + bv1));
        }
    }
}

// --- conv: split-bf16 HMMA, cp.async double-buffer, 4 samples/CTA ----------
// Epilogue also emits per-(sample, mtile) LN partial stats into g_part.
template <int C, int O>
__global__ void __launch_bounds__(256, 1)
conv_hmma(const __nv_bfloat16* __restrict__ xhi, const __nv_bfloat16* __restrict__ xlo,
          const __nv_bfloat16* __restrict__ whi, const __nv_bfloat16* __restrict__ wlo,
          const int* __restrict__ idxg, const float* __restrict__ bias,
          float* __restrict__ pre, float2* __restrict__ part)
{
    constexpr int K3 = 3 * C, NCH = K3 / 64, CB = C / 64;
    constexpr int MTILES = O / 128;
    constexpr int BOFFH = 18432;            // halves: start of B region
    constexpr int BBLK = 4608;              // halves per (sample, split)
    constexpr int BUFH = BOFFH + 8 * BBLK;  // 55296 halves per buffer
    extern __shared__ __align__(16) __nv_bfloat16 smh[];
    int* idxs = (int*)(smh + 2 * BUFH);
    float2* spart = (float2*)(idxs + 4 * 192);   // 8 warps x 2 samples

    const int tid = threadIdx.x, wid = tid >> 5, lane = tid & 31;
    const int g = lane >> 2, t = lane & 3;
    const int b0 = blockIdx.y * 4, obase = blockIdx.x * 128;
    const int sp2 = wid >> 2, wm = wid & 3;   // sample-pair, M strip
    const uint32_t sbase = smem_u32(smh);

    const int lrowA = lane & 15, lcolA = (lane >> 4) * 8;
    const int tb = lane >> 3;
    const int lrowB = (tb >> 1) * 8 + (lane & 7), lcolB = (tb & 1) * 8;

    for (int i = tid; i < 4 * 192; i += 256) {
        int s2 = i / 192, j = i % 192;
        idxs[i] = (j < 189) ? idxg[(size_t)(b0 + s2) * 189 + j] : 0;
    }
    __syncthreads();

    auto prefetch = [&](int ci, int buf) {
        const uint32_t base = sbase + buf * (BUFH * 2);
        #pragma unroll
        for (int it = 0; it < 8; it++) {
            int u = tid + it * 256;
            int sp = u >> 10, r = (u >> 3) & 127, q = u & 7;
            const __nv_bfloat16* src = (sp ? wlo : whi) + (size_t)(obase + r) * K3 + ci * 64 + q * 8;
            cpasync16(base + (sp * 9216 + r * 72 + q * 8) * 2, src);
        }
        const int kk = ci / CB, c0 = (ci % CB) * 64;
        #pragma unroll
        for (int it = 0; it < 16; it++) {
            int u = tid + it * 256;
            int ss = u >> 10, sp = (u >> 9) & 1, n = (u >> 3) & 63, q = u & 7;
            int slot = (n > 0) ? idxs[ss * 192 + (n - 1) * 3 + kk] : 0;
            const __nv_bfloat16* src = (sp ? xlo : xhi)
                + ((size_t)(b0 + ss) * 64 + slot) * C + c0 + q * 8;
            cpasync16z(base + (BOFFH + (ss * 2 + sp) * BBLK + n * 72 + q * 8) * 2, src,
                       (n > 0) ? 16 : 0);
        }
        CP_COMMIT();
    };

    float acc[2][2][8][4] = {};   // [si][mt][nt][frag]
    prefetch(0, 0);

    for (int ci = 0; ci < NCH; ci++) {
        if (ci + 1 < NCH) {
            prefetch(ci + 1, (ci + 1) & 1);
            asm volatile("cp.async.wait_group 1;");
        } else {
            asm volatile("cp.async.wait_group 0;");
        }
        __syncthreads();

        const uint32_t base = sbase + (ci & 1) * (BUFH * 2);
        const uint32_t sA = base, sAl = base + 9216 * 2;

        #pragma unroll
        for (int ks = 0; ks < 4; ks++) {
            const int koff = ks * 16;
            uint32_t fah[2][4], fal[2][4];
            #pragma unroll
            for (int mt = 0; mt < 2; mt++) {
                uint32_t off = ((wm * 32 + mt * 16 + lrowA) * 72 + koff + lcolA) * 2;
                ldsm4(fah[mt][0], fah[mt][1], fah[mt][2], fah[mt][3], sA + off);
                ldsm4(fal[mt][0], fal[mt][1], fal[mt][2], fal[mt][3], sAl + off);
            }
            #pragma unroll
            for (int si = 0; si < 2; si++) {
                const uint32_t sB  = base + (BOFFH + ((sp2 * 2 + si) * 2) * BBLK) * 2;
                const uint32_t sBl = sB + BBLK * 2;
                #pragma unroll
                for (int p = 0; p < 4; p++) {
                    uint32_t off = ((p * 16 + lrowB) * 72 + koff + lcolB) * 2;
                    uint32_t bh0, bh1, bh2, bh3, bl0, bl1, bl2, bl3;
                    ldsm4(bh0, bh1, bh2, bh3, sB + off);
                    ldsm4(bl0, bl1, bl2, bl3, sBl + off);
                    #pragma unroll
                    for (int mt = 0; mt < 2; mt++) {
                        MMA16816(acc[si][mt][2*p],   fah[mt], bh0, bh1);
                        MMA16816(acc[si][mt][2*p],   fah[mt], bl0, bl1);
                        MMA16816(acc[si][mt][2*p],   fal[mt], bh0, bh1);
                        MMA16816(acc[si][mt][2*p+1], fah[mt], bh2, bh3);
                        MMA16816(acc[si][mt][2*p+1], fah[mt], bl2, bl3);
                        MMA16816(acc[si][mt][2*p+1], fal[mt], bh2, bh3);
                    }
                }
            }
        }
        __syncthreads();
    }

    // Epilogue: bias, stores, and per-warp LN partial stats (fused).
    #pragma unroll
    for (int si = 0; si < 2; si++) {
        float s = 0.f, ss = 0.f;
        #pragma unroll
        for (int mt = 0; mt < 2; mt++) {
            int o0 = obase + wm * 32 + mt * 16 + g;
            float bv0 = __ldg(&bias[o0]), bv1 = __ldg(&bias[o0 + 8]);
            float* base0 = pre + ((size_t)(b0 + sp2 * 2 + si) * O + o0) * 64;
            float* base1 = base0 + 8 * 64;
            #pragma unroll
            for (int nt = 0; nt < 8; nt++) {
                int n0 = nt * 8 + 2 * t;
                float m0 = (n0 == 0) ? 0.f : bv0;
                float m1 = (n0 == 0) ? 0.f : bv1;
                float v0 = acc[si][mt][nt][0] + m0, v1 = acc[si][mt][nt][1] + bv0;
                float v2 = acc[si][mt][nt][2] + m1, v3 = acc[si][mt][nt][3] + bv1;
                s  += (v0 + v1) + (v2 + v3);
                ss += (v0 * v0 + v1 * v1) + (v2 * v2 + v3 * v3);
                *(float2*)(base0 + n0) = make_float2(v0, v1);
                *(float2*)(base1 + n0) = make_float2(v2, v3);
            }
        }
        #pragma unroll
        for (int sh = 16; sh; sh >>= 1) {
            s  += __shfl_down_sync(0xffffffffu, s,  sh);
            ss += __shfl_down_sync(0xffffffffu, ss, sh);
        }
        if (lane == 0) spart[wid * 2 + si] = make_float2(s, ss);
    }
    __syncthreads();
    if (tid < 4) {
        int sp2_ = tid >> 1, si_ = tid & 1;
        float S = 0.f, SS = 0.f;
        #pragma unroll
        for (int w = 0; w < 4; w++) {
            float2 p = spart[(sp2_ * 4 + w) * 2 + si_];
            S += p.x; SS += p.y;
        }
        part[(size_t)(b0 + sp2_ * 2 + si_) * MTILES + blockIdx.x] = make_float2(S, SS);
    }
}

// ---- LN from precomputed partials + leaky + transpose + split -------------
template <int O>
__global__ void __launch_bounds__(256)
ln_split(const float* __restrict__ pre, const float2* __restrict__ part,
         __nv_bfloat16* __restrict__ xh, __nv_bfloat16* __restrict__ xl)
{
    constexpr int MT = O / 128;
    __shared__ __align__(16) __nv_bfloat16 sh[4096], sl[4096];
    const int b = blockIdx.x, tid = threadIdx.x;
    const float4* p4 = (const float4*)(pre + (size_t)b * O * 64);
    float S = 0.f, SS = 0.f;
    #pragma unroll
    for (int m = 0; m < MT; m++) {
        float2 p = __ldg(&part[(size_t)b * MT + m]);
        S += p.x; SS += p.y;
    }
    const float nn = (float)(O * 64);
    const float mean = S / nn;
    const float var = fmaxf((SS - nn * mean * mean) / (nn - 1.f), 0.f);
    const float scale = 1.f / (sqrtf(var) + 1e-5f);

    for (int ot = 0; ot < O / 64; ot++) {
        #pragma unroll 1
        for (int k = 0; k < 4; k++) {
            int u = tid + k * 256;
            int ol = u >> 4, n4 = u & 15;
            float4 v = p4[(ot * 64 + ol) * 16 + n4];
            float y[4] = { leaky((v.x - mean) * scale), leaky((v.y - mean) * scale),
                           leaky((v.z - mean) * scale), leaky((v.w - mean) * scale) };
            #pragma unroll
            for (int j = 0; j < 4; j++) {
                int n = n4 * 4 + j;
                __nv_bfloat16 h = __float2bfloat16(y[j]);
                sh[n * 64 + ol] = h;
                sl[n * 64 + ol] = __float2bfloat16(y[j] - __bfloat162float(h));
            }
        }
        __syncthreads();
        #pragma unroll 1
        for (int k = 0; k < 2; k++) {
            int u = tid + k * 256;
            int n = u >> 3, q = u & 7;
            size_t base = (size_t)b * 64 * O + (size_t)n * O + ot * 64 + q * 8;
            *(uint4*)(xh + base) = *(uint4*)(sh + n * 64 + q * 8);
            *(uint4*)(xl + base) = *(uint4*)(sl + n * 64 + q * 8);
        }
        __syncthreads();
    }
}

// ---------------- final LN (from partials) + leaky -> d_out ----------------
__global__ void __launch_bounds__(256)
ln_final(const float* __restrict__ pre, const float2* __restrict__ part,
         float* __restrict__ out)
{
    constexpr int O = 512, MT = 4;
    const int b = blockIdx.x, tid = threadIdx.x;
    const float4* p4 = (const float4*)(pre + (size_t)b * O * 64);
    float4* o4 = (float4*)(out + (size_t)b * O * 64);
    float S = 0.f, SS = 0.f;
    #pragma unroll
    for (int m = 0; m < MT; m++) {
        float2 p = __ldg(&part[(size_t)b * MT + m]);
        S += p.x; SS += p.y;
    }
    const float nn = (float)(O * 64);
    const float mean = S / nn;
    const float var = fmaxf((SS - nn * mean * mean) / (nn - 1.f), 0.f);
    const float scale = 1.f / (sqrtf(var) + 1e-5f);
    for (int i = tid; i < O * 16; i += 256) {
        float4 v = p4[i];
        o4[i] = make_float4(leaky((v.x - mean) * scale), leaky((v.y - mean) * scale),
                            leaky((v.z - mean) * scale), leaky((v.w - mean) * scale));
    }
}

// ------------------------------ host launch --------------------------------
static constexpr int SMEM_CONV = 2 * 55296 * 2 + 4 * 192 * 4 + 8 * 2 * 8;  // 224512 B
static constexpr int SMEM_GEMM = (9216 * 2 + 4608 * 2) * 2;                // 55296 B

extern "C" void kernel_launch(void* const* d_in, const int* in_sizes, int n_in,
                              void* d_out, int out_size)
{
    const float* trees   = (const float*)d_in[0];
    const int*   indexes = (const int*)  d_in[1];
    const float* W1 = (const float*)d_in[2];  const float* b1 = (const float*)d_in[3];
    const float* W2 = (const float*)d_in[4];  const float* b2 = (const float*)d_in[5];
    const float* W3 = (const float*)d_in[6];  const float* b3 = (const float*)d_in[7];
    const float* W4 = (const float*)d_in[8];  const float* b4 = (const float*)d_in[9];
    const float* cw1 = (const float*)d_in[10]; const float* cb1 = (const float*)d_in[11];
    const float* cw2 = (const float*)d_in[12]; const float* cb2 = (const float*)d_in[13];
    const float* cw3 = (const float*)d_in[14]; const float* cb3 = (const float*)d_in[15];

    float *x1, *x2, *x3, *x4, *pre;
    float2* part;
    __nv_bfloat16 *xh, *xl, *w1h, *w1l, *w2h, *w2l, *w3h, *w3l;
    __nv_bfloat16 *ma_h, *ma_l, *mw3h, *mw3l, *mw4h, *mw4l;
    cudaGetSymbolAddress((void**)&x1, g_x1);
    cudaGetSymbolAddress((void**)&x2, g_x2);
    cudaGetSymbolAddress((void**)&x3, g_x3);
    cudaGetSymbolAddress((void**)&x4, g_x4);
    cudaGetSymbolAddress((void**)&pre, g_pre);
    cudaGetSymbolAddress((void**)&part, g_part);
    cudaGetSymbolAddress((void**)&xh, g_xh);
    cudaGetSymbolAddress((void**)&xl, g_xl);
    cudaGetSymbolAddress((void**)&w1h, g_w1h); cudaGetSymbolAddress((void**)&w1l, g_w1l);
    cudaGetSymbolAddress((void**)&w2h, g_w2h); cudaGetSymbolAddress((void**)&w2l, g_w2l);
    cudaGetSymbolAddress((void**)&w3h, g_w3h); cudaGetSymbolAddress((void**)&w3l, g_w3l);
    cudaGetSymbolAddress((void**)&ma_h, g_ah); cudaGetSymbolAddress((void**)&ma_l, g_al);
    cudaGetSymbolAddress((void**)&mw3h, g_mw3h); cudaGetSymbolAddress((void**)&mw3l, g_mw3l);
    cudaGetSymbolAddress((void**)&mw4h, g_mw4h); cudaGetSymbolAddress((void**)&mw4l, g_mw4l);

    cudaFuncSetAttribute(conv_hmma<64, 128>,  cudaFuncAttributeMaxDynamicSharedMemorySize, SMEM_CONV);
    cudaFuncSetAttribute(conv_hmma<128, 256>, cudaFuncAttributeMaxDynamicSharedMemorySize, SMEM_CONV);
    cudaFuncSetAttribute(conv_hmma<256, 512>, cudaFuncAttributeMaxDynamicSharedMemorySize, SMEM_CONV);
    cudaFuncSetAttribute(gemm_hmma, cudaFuncAttributeMaxDynamicSharedMemorySize, SMEM_GEMM);

    // weight prep
    wsplit<<<96,   256>>>(cw1, w1h, w1l, 64, 128);
    wsplit<<<384,  256>>>(cw2, w2h, w2l, 128, 256);
    wsplit<<<1536, 256>>>(cw3, w3h, w3l, 256, 512);
    asplit<<<256,  256>>>(W3, mw3h, mw3l, 1024 * 256 / 4);
    asplit<<<4096, 256>>>(W4, mw4h, mw4l, 4096 * 1024 / 4);

    // MLP: L1, L2 fp32 (tiny); L3, L4 tensor
    gemm_bias_leaky<<<dim3(32, 1), 128>>>(trees, W1, b1, x1, 16, 64);
    gemm_bias_leaky<<<dim3(32, 4), 128>>>(x1,    W2, b2, x2, 64, 256);
    asplit<<<1024, 256>>>(x2, ma_h, ma_l, 4096 * 256 / 4);
    gemm_hmma<<<dim3(32, 16), 256, SMEM_GEMM>>>(ma_h, ma_l, mw3h, mw3l, b3, x3, 256, 1024);
    asplit<<<4096, 256>>>(x3, ma_h, ma_l, 4096 * 1024 / 4);
    gemm_hmma<<<dim3(32, 64), 256, SMEM_GEMM>>>(ma_h, ma_l, mw4h, mw4l, b4, x4, 1024, 4096);

    // transpose+split MLP output -> xT (C=64)
    tsplit64<<<4096, 64>>>(x4, xh, xl);

    // conv1 -> LN -> conv2 -> LN -> conv3 -> LN(final); stats fused into convs
    conv_hmma<64, 128> <<<dim3(1, 1024), 256, SMEM_CONV>>>(xh, xl, w1h, w1l, indexes, cb1, pre, part);
    ln_split<128><<<4096, 256>>>(pre, part, xh, xl);
    conv_hmma<128, 256><<<dim3(2, 1024), 256, SMEM_CONV>>>(xh, xl, w2h, w2l, indexes, cb2, pre, part);
    ln_split<256><<<4096, 256>>>(pre, part, xh, xl);
    conv_hmma<256, 512><<<dim3(4, 1024), 256, SMEM_CONV>>>(xh, xl, w3h, w3l, indexes, cb3, pre, part);
    ln_final<<<4096, 256>>>(pre, part, (float*)d_out);
}

// round 16
// speedup vs baseline: 3.2809x; 1.0026x over previous
#include <cuda_runtime.h>
#include <cuda_bf16.h>
#include <stdint.h>
#include <math.h>

// ------------------------------ scratch ------------------------------------
static __device__ __align__(16) float g_x1[4096 * 64];
static __device__ __align__(16) float g_x2[4096 * 256];
static __device__ __align__(16) float g_x3[4096 * 1024];
static __device__ __align__(16) float g_x4[4096 * 4096];
static __device__ __align__(16) float g_pre[4096 * 512 * 64];
static __device__ __align__(16) float2 g_part[4096 * 4];
static __device__ __align__(16) __nv_bfloat16 g_xh[4096 * 64 * 256];
static __device__ __align__(16) __nv_bfloat16 g_xl[4096 * 64 * 256];
static __device__ __align__(16) __nv_bfloat16 g_w1h[128 * 192], g_w1l[128 * 192];
static __device__ __align__(16) __nv_bfloat16 g_w2h[256 * 384], g_w2l[256 * 384];
static __device__ __align__(16) __nv_bfloat16 g_w3h[512 * 768], g_w3l[512 * 768];
static __device__ __align__(16) __nv_bfloat16 g_ah[4096 * 1024], g_al[4096 * 1024];
static __device__ __align__(16) __nv_bfloat16 g_mw3h[1024 * 256], g_mw3l[1024 * 256];
static __device__ __align__(16) __nv_bfloat16 g_mw4h[4096 * 1024], g_mw4l[4096 * 1024];

__device__ __forceinline__ float leaky(float v) { return v > 0.f ? v : 0.01f * v; }

__device__ __forceinline__ uint32_t smem_u32(const void* p) {
    uint32_t a;
    asm("{ .reg .u64 t; cvta.to.shared.u64 t, %1; cvt.u32.u64 %0, t; }" : "=r"(a) : "l"(p));
    return a;
}
__device__ __forceinline__ void ldsm4(uint32_t& r0, uint32_t& r1, uint32_t& r2, uint32_t& r3,
                                      uint32_t addr) {
    asm volatile("ldmatrix.sync.aligned.m8n8.x4.shared.b16 {%0,%1,%2,%3}, [%4];"
                 : "=r"(r0), "=r"(r1), "=r"(r2), "=r"(r3) : "r"(addr));
}
__device__ __forceinline__ void cpasync16(uint32_t dst, const void* src) {
    asm volatile("cp.async.cg.shared.global [%0], [%1], 16;" :: "r"(dst), "l"(src));
}
__device__ __forceinline__ void cpasync16z(uint32_t dst, const void* src, int szz) {
    asm volatile("cp.async.cg.shared.global [%0], [%1], 16, %2;" :: "r"(dst), "l"(src), "r"(szz));
}
#define CP_COMMIT() asm volatile("cp.async.commit_group;")
#define MMA16816(d, a, b0_, b1_) \
    asm volatile("mma.sync.aligned.m16n8k16.row.col.f32.bf16.bf16.f32 " \
        "{%0,%1,%2,%3}, {%4,%5,%6,%7}, {%8,%9}, {%0,%1,%2,%3};" \
        : "+f"(d[0]), "+f"(d[1]), "+f"(d[2]), "+f"(d[3]) \
        : "r"(a[0]), "r"(a[1]), "r"(a[2]), "r"(a[3]), "r"(b0_), "r"(b1_))

// ------------------------------ small fp32 GEMM (L1, L2) -------------------
__global__ void __launch_bounds__(128)
gemm_bias_leaky(const float* __restrict__ A, const float* __restrict__ W,
                const float* __restrict__ bias, float* __restrict__ C, int K, int N)
{
    __shared__ __align__(16) float As[16][128];
    __shared__ __align__(16) float Ws[16][64];
    const int tid = threadIdx.x, mt = tid & 15, nt = tid >> 4;
    const float* Ab = A + (size_t)blockIdx.x * 128 * K;
    const float* Wb = W + (size_t)blockIdx.y * 64 * K;
    float acc[8][8] = {};
    for (int k0 = 0; k0 < K; k0 += 16) {
        #pragma unroll
        for (int i = 0; i < 4; i++) {
            int lin = tid + i * 128, r = lin >> 2, c4 = lin & 3;
            float4 v = *(const float4*)(Ab + (size_t)r * K + k0 + c4 * 4);
            As[c4*4+0][r]=v.x; As[c4*4+1][r]=v.y; As[c4*4+2][r]=v.z; As[c4*4+3][r]=v.w;
        }
        #pragma unroll
        for (int i = 0; i < 2; i++) {
            int lin = tid + i * 128, r = lin >> 2, c4 = lin & 3;
            float4 v = *(const float4*)(Wb + (size_t)r * K + k0 + c4 * 4);
            Ws[c4*4+0][r]=v.x; Ws[c4*4+1][r]=v.y; Ws[c4*4+2][r]=v.z; Ws[c4*4+3][r]=v.w;
        }
        __syncthreads();
        #pragma unroll
        for (int kk = 0; kk < 16; kk++) {
            float a[8], w[8];
            *(float4*)&a[0] = *(const float4*)&As[kk][mt*8];
            *(float4*)&a[4] = *(const float4*)&As[kk][mt*8+4];
            *(float4*)&w[0] = *(const float4*)&Ws[kk][nt*8];
            *(float4*)&w[4] = *(const float4*)&Ws[kk][nt*8+4];
            #pragma unroll
            for (int i = 0; i < 8; i++)
                #pragma unroll
                for (int j = 0; j < 8; j++) acc[i][j] = fmaf(a[i], w[j], acc[i][j]);
        }
        __syncthreads();
    }
    float bv[8];
    #pragma unroll
    for (int j = 0; j < 8; j++) bv[j] = __ldg(&bias[blockIdx.y * 64 + nt * 8 + j]);
    #pragma unroll
    for (int i = 0; i < 8; i++) {
        size_t row = (size_t)(blockIdx.x*128 + mt*8 + i) * N + blockIdx.y*64 + nt*8;
        float4 o0, o1;
        o0.x=leaky(acc[i][0]+bv[0]); o0.y=leaky(acc[i][1]+bv[1]);
        o0.z=leaky(acc[i][2]+bv[2]); o0.w=leaky(acc[i][3]+bv[3]);
        o1.x=leaky(acc[i][4]+bv[4]); o1.y=leaky(acc[i][5]+bv[5]);
        o1.z=leaky(acc[i][6]+bv[6]); o1.w=leaky(acc[i][7]+bv[7]);
        *(float4*)&C[row] = o0; *(float4*)&C[row+4] = o1;
    }
}

// ---- elementwise fp32 -> hi/lo bf16 split ---------------------------------
__global__ void asplit(const float* __restrict__ x, __nv_bfloat16* __restrict__ h,
                       __nv_bfloat16* __restrict__ l, int n4)
{
    int i = blockIdx.x * 256 + threadIdx.x;
    if (i >= n4) return;
    float4 v = ((const float4*)x)[i];
    __nv_bfloat16 h0 = __float2bfloat16(v.x), h1 = __float2bfloat16(v.y);
    __nv_bfloat16 h2 = __float2bfloat16(v.z), h3 = __float2bfloat16(v.w);
    ((__nv_bfloat162*)h)[2*i]   = __nv_bfloat162(h0, h1);
    ((__nv_bfloat162*)h)[2*i+1] = __nv_bfloat162(h2, h3);
    ((__nv_bfloat162*)l)[2*i]   = __nv_bfloat162(__float2bfloat16(v.x - __bfloat162float(h0)),
                                                 __float2bfloat16(v.y - __bfloat162float(h1)));
    ((__nv_bfloat162*)l)[2*i+1] = __nv_bfloat162(__float2bfloat16(v.z - __bfloat162float(h2)),
                                                 __float2bfloat16(v.w - __bfloat162float(h3)));
}

// ---- conv W prep: w[o][c][kk] -> wA[o][kk*C+c], hi/lo split ---------------
__global__ void wsplit(const float* __restrict__ w, __nv_bfloat16* __restrict__ hi,
                       __nv_bfloat16* __restrict__ lo, int C, int O)
{
    int i = blockIdx.x * 256 + threadIdx.x;
    int K3 = 3 * C;
    if (i >= O * K3) return;
    int o = i / K3, rem = i % K3, c = rem / 3, kk = rem % 3;
    float v = w[i];
    __nv_bfloat16 h = __float2bfloat16(v);
    hi[o * K3 + kk * C + c] = h;
    lo[o * K3 + kk * C + c] = __float2bfloat16(v - __bfloat162float(h));
}

// ---- MLP out transpose+split: x4[b][c][n] -> xT[b][n][c] hi/lo (C=64) -----
__global__ void __launch_bounds__(64)
tsplit64(const float* __restrict__ x, __nv_bfloat16* __restrict__ hi,
         __nv_bfloat16* __restrict__ lo)
{
    __shared__ __align__(16) float s[64 * 64];
    const int b = blockIdx.x, t = threadIdx.x;
    const float4* src = (const float4*)(x + (size_t)b * 4096);
    float4* d4 = (float4*)s;
    for (int i = t; i < 1024; i += 64) d4[i] = src[i];
    __syncthreads();
    __align__(16) __nv_bfloat16 rh[64], rl[64];
    #pragma unroll
    for (int c = 0; c < 64; c++) {
        float v = s[c * 64 + t];
        rh[c] = __float2bfloat16(v);
        rl[c] = __float2bfloat16(v - __bfloat162float(rh[c]));
    }
    uint4* dh = (uint4*)(hi + (size_t)b * 4096 + t * 64);
    uint4* dl = (uint4*)(lo + (size_t)b * 4096 + t * 64);
    #pragma unroll
    for (int q = 0; q < 8; q++) { dh[q] = ((uint4*)rh)[q]; dl[q] = ((uint4*)rl)[q]; }
}

// ------------------- dense split-bf16 HMMA GEMM (MLP L3/L4) ----------------
__global__ void __launch_bounds__(256, 2)
gemm_hmma(const __nv_bfloat16* __restrict__ ah, const __nv_bfloat16* __restrict__ al,
          const __nv_bfloat16* __restrict__ wh_, const __nv_bfloat16* __restrict__ wl_,
          const float* __restrict__ bias, float* __restrict__ C, int K, int N)
{
    constexpr int GA = 9216, GW = 4608;
    extern __shared__ __align__(16) __nv_bfloat16 smg[];
    const int tid = threadIdx.x, wid = tid >> 5, lane = tid & 31;
    const int g = lane >> 2, t = lane & 3;
    const int wm = wid & 3, wh = wid >> 2;
    const int m0 = blockIdx.x * 128, n0 = blockIdx.y * 64;

    const uint32_t sA = smem_u32(smg);
    const uint32_t sAl = sA + GA * 2, sW = sA + 2 * GA * 2, sWl = sW + GW * 2;
    const int lrowA = lane & 15, lcolA = (lane >> 4) * 8;
    const int tb = lane >> 3;
    const int lrowB = (tb >> 1) * 8 + (lane & 7), lcolB = (tb & 1) * 8;

    float acc[2][4][4] = {};

    for (int kc = 0; kc < K; kc += 64) {
        __syncthreads();
        #pragma unroll
        for (int it = 0; it < 8; it++) {
            int u = tid + it * 256;
            int sp = u >> 10, r = (u >> 3) & 127, q = u & 7;
            const __nv_bfloat16* src = (sp ? al : ah) + (size_t)(m0 + r) * K + kc + q * 8;
            *(uint4*)(smg + sp * GA + r * 72 + q * 8) = *(const uint4*)src;
        }
        #pragma unroll
        for (int it = 0; it < 4; it++) {
            int u = tid + it * 256;
            int sp = u >> 9, r = (u >> 3) & 63, q = u & 7;
            const __nv_bfloat16* src = (sp ? wl_ : wh_) + (size_t)(n0 + r) * K + kc + q * 8;
            *(uint4*)(smg + 2 * GA + sp * GW + r * 72 + q * 8) = *(const uint4*)src;
        }
        __syncthreads();

        #pragma unroll
        for (int ks = 0; ks < 4; ks++) {
            const int koff = ks * 16;
            uint32_t fah[2][4], fal[2][4];
            #pragma unroll
            for (int mt = 0; mt < 2; mt++) {
                uint32_t off = ((wm * 32 + mt * 16 + lrowA) * 72 + koff + lcolA) * 2;
                ldsm4(fah[mt][0], fah[mt][1], fah[mt][2], fah[mt][3], sA + off);
                ldsm4(fal[mt][0], fal[mt][1], fal[mt][2], fal[mt][3], sAl + off);
            }
            #pragma unroll
            for (int p = 0; p < 2; p++) {
                uint32_t off = ((wh * 32 + p * 16 + lrowB) * 72 + koff + lcolB) * 2;
                uint32_t bh0, bh1, bh2, bh3, bl0, bl1, bl2, bl3;
                ldsm4(bh0, bh1, bh2, bh3, sW + off);
                ldsm4(bl0, bl1, bl2, bl3, sWl + off);
                // pass-major ordering: same-acc reuse distance 4
                #pragma unroll
                for (int mt = 0; mt < 2; mt++) {
                    MMA16816(acc[mt][2*p],   fah[mt], bh0, bh1);
                    MMA16816(acc[mt][2*p+1], fah[mt], bh2, bh3);
                }
                #pragma unroll
                for (int mt = 0; mt < 2; mt++) {
                    MMA16816(acc[mt][2*p],   fah[mt], bl0, bl1);
                    MMA16816(acc[mt][2*p+1], fah[mt], bl2, bl3);
                }
                #pragma unroll
                for (int mt = 0; mt < 2; mt++) {
                    MMA16816(acc[mt][2*p],   fal[mt], bh0, bh1);
                    MMA16816(acc[mt][2*p+1], fal[mt], bh2, bh3);
                }
            }
        }
    }

    #pragma unroll
    for (int mt = 0; mt < 2; mt++) {
        #pragma unroll
        for (int nt = 0; nt < 4; nt++) {
            int col = n0 + wh * 32 + nt * 8 + 2 * t;
            float bv0 = __ldg(&bias[col]), bv1 = __ldg(&bias[col + 1]);
            int row0 = m0 + wm * 32 + mt * 16 + g;
            *(float2*)&C[(size_t)row0 * N + col] =
                make_float2(leaky(acc[mt][nt][0] + bv0), leaky(acc[mt][nt][1] + bv1));
            *(float2*)&C[(size_t)(row0 + 8) * N + col] =
                make_float2(leaky(acc[mt][nt][2] + bv0), leaky(acc[mt][nt][3] + bv1));
        }
    }
}

// --- conv: split-bf16 HMMA, cp.async double-buffer, 4 samples/CTA ----------
// Warp = 64 M-rows x 64 N (one sample): si = wid>>1, mh = wid&1.
// Fragments loaded up front per ks; 3 pass-major sweeps -> no acc RAW chains.
template <int C, int O>
__global__ void __launch_bounds__(256, 1)
conv_hmma(const __nv_bfloat16* __restrict__ xhi, const __nv_bfloat16* __restrict__ xlo,
          const __nv_bfloat16* __restrict__ whi, const __nv_bfloat16* __restrict__ wlo,
          const int* __restrict__ idxg, const float* __restrict__ bias,
          float* __restrict__ pre, float2* __restrict__ part)
{
    constexpr int K3 = 3 * C, NCH = K3 / 64, CB = C / 64;
    constexpr int MTILES = O / 128;
    constexpr int BOFFH = 18432;
    constexpr int BBLK = 4608;
    constexpr int BUFH = BOFFH + 8 * BBLK;   // 55296 halves per buffer
    extern __shared__ __align__(16) __nv_bfloat16 smh[];
    int* idxs = (int*)(smh + 2 * BUFH);
    float2* spart = (float2*)(idxs + 4 * 192);   // 8 warps

    const int tid = threadIdx.x, wid = tid >> 5, lane = tid & 31;
    const int g = lane >> 2, t = lane & 3;
    const int b0 = blockIdx.y * 4, obase = blockIdx.x * 128;
    const int si = wid >> 1, mh = wid & 1;
    const uint32_t sbase = smem_u32(smh);

    const int lrowA = lane & 15, lcolA = (lane >> 4) * 8;
    const int tb = lane >> 3;
    const int lrowB = (tb >> 1) * 8 + (lane & 7), lcolB = (tb & 1) * 8;

    for (int i = tid; i < 4 * 192; i += 256) {
        int s2 = i / 192, j = i % 192;
        idxs[i] = (j < 189) ? idxg[(size_t)(b0 + s2) * 189 + j] : 0;
    }
    __syncthreads();

    auto prefetch = [&](int ci, int buf) {
        const uint32_t base = sbase + buf * (BUFH * 2);
        #pragma unroll
        for (int it = 0; it < 8; it++) {
            int u = tid + it * 256;
            int sp = u >> 10, r = (u >> 3) & 127, q = u & 7;
            const __nv_bfloat16* src = (sp ? wlo : whi) + (size_t)(obase + r) * K3 + ci * 64 + q * 8;
            cpasync16(base + (sp * 9216 + r * 72 + q * 8) * 2, src);
        }
        const int kk = ci / CB, c0 = (ci % CB) * 64;
        #pragma unroll
        for (int it = 0; it < 16; it++) {
            int u = tid + it * 256;
            int ss = u >> 10, sp = (u >> 9) & 1, n = (u >> 3) & 63, q = u & 7;
            int slot = (n > 0) ? idxs[ss * 192 + (n - 1) * 3 + kk] : 0;
            const __nv_bfloat16* src = (sp ? xlo : xhi)
                + ((size_t)(b0 + ss) * 64 + slot) * C + c0 + q * 8;
            cpasync16z(base + (BOFFH + (ss * 2 + sp) * BBLK + n * 72 + q * 8) * 2, src,
                       (n > 0) ? 16 : 0);
        }
        CP_COMMIT();
    };

    float acc[4][8][4] = {};   // [mt][nt][frag], warp tile 64x64
    prefetch(0, 0);

    for (int ci = 0; ci < NCH; ci++) {
        if (ci + 1 < NCH) {
            prefetch(ci + 1, (ci + 1) & 1);
            asm volatile("cp.async.wait_group 1;");
        } else {
            asm volatile("cp.async.wait_group 0;");
        }
        __syncthreads();

        const uint32_t base = sbase + (ci & 1) * (BUFH * 2);
        const uint32_t sA = base, sAl = base + 9216 * 2;
        const uint32_t sB = base + (BOFFH + (si * 2) * BBLK) * 2;
        const uint32_t sBl = sB + BBLK * 2;

        #pragma unroll
        for (int ks = 0; ks < 4; ks++) {
            const int koff = ks * 16;
            uint32_t fah[4][4], fal[4][4], bh[4][4], bl[4][4];
            #pragma unroll
            for (int mt = 0; mt < 4; mt++) {
                uint32_t off = ((mh * 64 + mt * 16 + lrowA) * 72 + koff + lcolA) * 2;
                ldsm4(fah[mt][0], fah[mt][1], fah[mt][2], fah[mt][3], sA + off);
                ldsm4(fal[mt][0], fal[mt][1], fal[mt][2], fal[mt][3], sAl + off);
            }
            #pragma unroll
            for (int p = 0; p < 4; p++) {
                uint32_t off = ((p * 16 + lrowB) * 72 + koff + lcolB) * 2;
                ldsm4(bh[p][0], bh[p][1], bh[p][2], bh[p][3], sB + off);
                ldsm4(bl[p][0], bl[p][1], bl[p][2], bl[p][3], sBl + off);
            }
            // pass 1: Ah * Bh   (32 distinct accs -> no RAW chains)
            #pragma unroll
            for (int p = 0; p < 4; p++)
                #pragma unroll
                for (int mt = 0; mt < 4; mt++) {
                    MMA16816(acc[mt][2*p],   fah[mt], bh[p][0], bh[p][1]);
                    MMA16816(acc[mt][2*p+1], fah[mt], bh[p][2], bh[p][3]);
                }
            // pass 2: Ah * Bl
            #pragma unroll
            for (int p = 0; p < 4; p++)
                #pragma unroll
                for (int mt = 0; mt < 4; mt++) {
                    MMA16816(acc[mt][2*p],   fah[mt], bl[p][0], bl[p][1]);
                    MMA16816(acc[mt][2*p+1], fah[mt], bl[p][2], bl[p][3]);
                }
            // pass 3: Al * Bh
            #pragma unroll
            for (int p = 0; p < 4; p++)
                #pragma unroll
                for (int mt = 0; mt < 4; mt++) {
                    MMA16816(acc[mt][2*p],   fal[mt], bh[p][0], bh[p][1]);
                    MMA16816(acc[mt][2*p+1], fal[mt], bh[p][2], bh[p][3]);
                }
        }
        __syncthreads();
    }

    // Epilogue: bias, stores, per-warp LN partial stats (warp = sample si, 64 rows)
    float s = 0.f, ss = 0.f;
    #pragma unroll
    for (int mt = 0; mt < 4; mt++) {
        int o0 = obase + mh * 64 + mt * 16 + g;
        float bv0 = __ldg(&bias[o0]), bv1 = __ldg(&bias[o0 + 8]);
        float* base0 = pre + ((size_t)(b0 + si) * O + o0) * 64;
        float* base1 = base0 + 8 * 64;
        #pragma unroll
        for (int nt = 0; nt < 8; nt++) {
            int n0 = nt * 8 + 2 * t;
            float m0 = (n0 == 0) ? 0.f : bv0;
            float m1 = (n0 == 0) ? 0.f : bv1;
            float v0 = acc[mt][nt][0] + m0, v1 = acc[mt][nt][1] + bv0;
            float v2 = acc[mt][nt][2] + m1, v3 = acc[mt][nt][3] + bv1;
            s  += (v0 + v1) + (v2 + v3);
            ss += (v0 * v0 + v1 * v1) + (v2 * v2 + v3 * v3);
            *(float2*)(base0 + n0) = make_float2(v0, v1);
            *(float2*)(base1 + n0) = make_float2(v2, v3);
        }
    }
    #pragma unroll
    for (int sh = 16; sh; sh >>= 1) {
        s  += __shfl_down_sync(0xffffffffu, s,  sh);
        ss += __shfl_down_sync(0xffffffffu, ss, sh);
    }
    if (lane == 0) spart[wid] = make_float2(s, ss);
    __syncthreads();
    if (tid < 4) {
        float2 p0 = spart[tid * 2], p1 = spart[tid * 2 + 1];
        part[(size_t)(b0 + tid) * MTILES + blockIdx.x] =
            make_float2(p0.x + p1.x, p0.y + p1.y);
    }
}

// ---- LN from precomputed partials + leaky + transpose + split -------------
template <int O>
__global__ void __launch_bounds__(256)
ln_split(const float* __restrict__ pre, const float2* __restrict__ part,
         __nv_bfloat16* __restrict__ xh, __nv_bfloat16* __restrict__ xl)
{
    constexpr int MT = O / 128;
    __shared__ __align__(16) __nv_bfloat16 sh[4096], sl[4096];
    const int b = blockIdx.x, tid = threadIdx.x;
    const float4* p4 = (const float4*)(pre + (size_t)b * O * 64);
    float S = 0.f, SS = 0.f;
    #pragma unroll
    for (int m = 0; m < MT; m++) {
        float2 p = __ldg(&part[(size_t)b * MT + m]);
        S += p.x; SS += p.y;
    }
    const float nn = (float)(O * 64);
    const float mean = S / nn;
    const float var = fmaxf((SS - nn * mean * mean) / (nn - 1.f), 0.f);
    const float scale = 1.f / (sqrtf(var) + 1e-5f);

    for (int ot = 0; ot < O / 64; ot++) {
        #pragma unroll 1
        for (int k = 0; k < 4; k++) {
            int u = tid + k * 256;
            int ol = u >> 4, n4 = u & 15;
            float4 v = p4[(ot * 64 + ol) * 16 + n4];
            float y[4] = { leaky((v.x - mean) * scale), leaky((v.y - mean) * scale),
                           leaky((v.z - mean) * scale), leaky((v.w - mean) * scale) };
            #pragma unroll
            for (int j = 0; j < 4; j++) {
                int n = n4 * 4 + j;
                __nv_bfloat16 h = __float2bfloat16(y[j]);
                sh[n * 64 + ol] = h;
                sl[n * 64 + ol] = __float2bfloat16(y[j] - __bfloat162float(h));
            }
        }
        __syncthreads();
        #pragma unroll 1
        for (int k = 0; k < 2; k++) {
            int u = tid + k * 256;
            int n = u >> 3, q = u & 7;
            size_t base = (size_t)b * 64 * O + (size_t)n * O + ot * 64 + q * 8;
            *(uint4*)(xh + base) = *(uint4*)(sh + n * 64 + q * 8);
            *(uint4*)(xl + base) = *(uint4*)(sl + n * 64 + q * 8);
        }
        __syncthreads();
    }
}

// ---------------- final LN (from partials) + leaky -> d_out ----------------
__global__ void __launch_bounds__(256)
ln_final(const float* __restrict__ pre, const float2* __restrict__ part,
         float* __restrict__ out)
{
    constexpr int O = 512, MT = 4;
    const int b = blockIdx.x, tid = threadIdx.x;
    const float4* p4 = (const float4*)(pre + (size_t)b * O * 64);
    float4* o4 = (float4*)(out + (size_t)b * O * 64);
    float S = 0.f, SS = 0.f;
    #pragma unroll
    for (int m = 0; m < MT; m++) {
        float2 p = __ldg(&part[(size_t)b * MT + m]);
        S += p.x; SS += p.y;
    }
    const float nn = (float)(O * 64);
    const float mean = S / nn;
    const float var = fmaxf((SS - nn * mean * mean) / (nn - 1.f), 0.f);
    const float scale = 1.f / (sqrtf(var) + 1e-5f);
    for (int i = tid; i < O * 16; i += 256) {
        float4 v = p4[i];
        o4[i] = make_float4(leaky((v.x - mean) * scale), leaky((v.y - mean) * scale),
                            leaky((v.z - mean) * scale), leaky((v.w - mean) * scale));
    }
}

// ------------------------------ host launch --------------------------------
static constexpr int SMEM_CONV = 2 * 55296 * 2 + 4 * 192 * 4 + 8 * 8;      // 224384 B
static constexpr int SMEM_GEMM = (9216 * 2 + 4608 * 2) * 2;                // 55296 B

extern "C" void kernel_launch(void* const* d_in, const int* in_sizes, int n_in,
                              void* d_out, int out_size)
{
    const float* trees   = (const float*)d_in[0];
    const int*   indexes = (const int*)  d_in[1];
    const float* W1 = (const float*)d_in[2];  const float* b1 = (const float*)d_in[3];
    const float* W2 = (const float*)d_in[4];  const float* b2 = (const float*)d_in[5];
    const float* W3 = (const float*)d_in[6];  const float* b3 = (const float*)d_in[7];
    const float* W4 = (const float*)d_in[8];  const float* b4 = (const float*)d_in[9];
    const float* cw1 = (const float*)d_in[10]; const float* cb1 = (const float*)d_in[11];
    const float* cw2 = (const float*)d_in[12]; const float* cb2 = (const float*)d_in[13];
    const float* cw3 = (const float*)d_in[14]; const float* cb3 = (const float*)d_in[15];

    float *x1, *x2, *x3, *x4, *pre;
    float2* part;
    __nv_bfloat16 *xh, *xl, *w1h, *w1l, *w2h, *w2l, *w3h, *w3l;
    __nv_bfloat16 *ma_h, *ma_l, *mw3h, *mw3l, *mw4h, *mw4l;
    cudaGetSymbolAddress((void**)&x1, g_x1);
    cudaGetSymbolAddress((void**)&x2, g_x2);
    cudaGetSymbolAddress((void**)&x3, g_x3);
    cudaGetSymbolAddress((void**)&x4, g_x4);
    cudaGetSymbolAddress((void**)&pre, g_pre);
    cudaGetSymbolAddress((void**)&part, g_part);
    cudaGetSymbolAddress((void**)&xh, g_xh);
    cudaGetSymbolAddress((void**)&xl, g_xl);
    cudaGetSymbolAddress((void**)&w1h, g_w1h); cudaGetSymbolAddress((void**)&w1l, g_w1l);
    cudaGetSymbolAddress((void**)&w2h, g_w2h); cudaGetSymbolAddress((void**)&w2l, g_w2l);
    cudaGetSymbolAddress((void**)&w3h, g_w3h); cudaGetSymbolAddress((void**)&w3l, g_w3l);
    cudaGetSymbolAddress((void**)&ma_h, g_ah); cudaGetSymbolAddress((void**)&ma_l, g_al);
    cudaGetSymbolAddress((void**)&mw3h, g_mw3h); cudaGetSymbolAddress((void**)&mw3l, g_mw3l);
    cudaGetSymbolAddress((void**)&mw4h, g_mw4h); cudaGetSymbolAddress((void**)&mw4l, g_mw4l);

    cudaFuncSetAttribute(conv_hmma<64, 128>,  cudaFuncAttributeMaxDynamicSharedMemorySize, SMEM_CONV);
    cudaFuncSetAttribute(conv_hmma<128, 256>, cudaFuncAttributeMaxDynamicSharedMemorySize, SMEM_CONV);
    cudaFuncSetAttribute(conv_hmma<256, 512>, cudaFuncAttributeMaxDynamicSharedMemorySize, SMEM_CONV);
    cudaFuncSetAttribute(gemm_hmma, cudaFuncAttributeMaxDynamicSharedMemorySize, SMEM_GEMM);

    // weight prep
    wsplit<<<96,   256>>>(cw1, w1h, w1l, 64, 128);
    wsplit<<<384,  256>>>(cw2, w2h, w2l, 128, 256);
    wsplit<<<1536, 256>>>(cw3, w3h, w3l, 256, 512);
    asplit<<<256,  256>>>(W3, mw3h, mw3l, 1024 * 256 / 4);
    asplit<<<4096, 256>>>(W4, mw4h, mw4l, 4096 * 1024 / 4);

    // MLP: L1, L2 fp32 (tiny); L3, L4 tensor
    gemm_bias_leaky<<<dim3(32, 1), 128>>>(trees, W1, b1, x1, 16, 64);
    gemm_bias_leaky<<<dim3(32, 4), 128>>>(x1,    W2, b2, x2, 64, 256);
    asplit<<<1024, 256>>>(x2, ma_h, ma_l, 4096 * 256 / 4);
    gemm_hmma<<<dim3(32, 16), 256, SMEM_GEMM>>>(ma_h, ma_l, mw3h, mw3l, b3, x3, 256, 1024);
    asplit<<<4096, 256>>>(x3, ma_h, ma_l, 4096 * 1024 / 4);
    gemm_hmma<<<dim3(32, 64), 256, SMEM_GEMM>>>(ma_h, ma_l, mw4h, mw4l, b4, x4, 1024, 4096);

    // transpose+split MLP output -> xT (C=64)
    tsplit64<<<4096, 64>>>(x4, xh, xl);

    // conv1 -> LN -> conv2 -> LN -> conv3 -> LN(final); stats fused into convs
    conv_hmma<64, 128> <<<dim3(1, 1024), 256, SMEM_CONV>>>(xh, xl, w1h, w1l, indexes, cb1, pre, part);
    ln_split<128><<<4096, 256>>>(pre, part, xh, xl);
    conv_hmma<128, 256><<<dim3(2, 1024), 256, SMEM_CONV>>>(xh, xl, w2h, w2l, indexes, cb2, pre, part);
    ln_split<256><<<4096, 256>>>(pre, part, xh, xl);
    conv_hmma<256, 512><<<dim3(4, 1024), 256, SMEM_CONV>>>(xh, xl, w3h, w3l, indexes, cb3, pre, part);
    ln_final<<<4096, 256>>>(pre, part, (float*)d_out);
}

// round 17
// speedup vs baseline: 4.3995x; 1.3409x over previous
#include <cuda_runtime.h>
#include <cuda_bf16.h>
#include <cuda_fp16.h>
#include <stdint.h>
#include <math.h>

// ------------------------------ scratch ------------------------------------
static __device__ __align__(16) float g_x1[4096 * 64];
static __device__ __align__(16) float g_x2[4096 * 256];
static __device__ __align__(16) float g_x3[4096 * 1024];
static __device__ __align__(16) float g_x4[4096 * 4096];
static __device__ __align__(16) float g_pre[4096 * 512 * 64];
static __device__ __align__(16) float2 g_part[4096 * 4];
static __device__ __align__(16) __half g_xf[4096 * 64 * 256];        // fp16 activations (transposed)
static __device__ __align__(16) __half g_w1h[128 * 192], g_w1l[128 * 192];
static __device__ __align__(16) __half g_w2h[256 * 384], g_w2l[256 * 384];
static __device__ __align__(16) __half g_w3h[512 * 768], g_w3l[512 * 768];
static __device__ __align__(16) __nv_bfloat16 g_ah[4096 * 1024], g_al[4096 * 1024];
static __device__ __align__(16) __nv_bfloat16 g_mw3h[1024 * 256], g_mw3l[1024 * 256];
static __device__ __align__(16) __nv_bfloat16 g_mw4h[4096 * 1024], g_mw4l[4096 * 1024];

__device__ __forceinline__ float leaky(float v) { return v > 0.f ? v : 0.01f * v; }

__device__ __forceinline__ uint32_t smem_u32(const void* p) {
    uint32_t a;
    asm("{ .reg .u64 t; cvta.to.shared.u64 t, %1; cvt.u32.u64 %0, t; }" : "=r"(a) : "l"(p));
    return a;
}
__device__ __forceinline__ void ldsm4(uint32_t& r0, uint32_t& r1, uint32_t& r2, uint32_t& r3,
                                      uint32_t addr) {
    asm volatile("ldmatrix.sync.aligned.m8n8.x4.shared.b16 {%0,%1,%2,%3}, [%4];"
                 : "=r"(r0), "=r"(r1), "=r"(r2), "=r"(r3) : "r"(addr));
}
__device__ __forceinline__ void cpasync16(uint32_t dst, const void* src) {
    asm volatile("cp.async.cg.shared.global [%0], [%1], 16;" :: "r"(dst), "l"(src));
}
__device__ __forceinline__ void cpasync16z(uint32_t dst, const void* src, int szz) {
    asm volatile("cp.async.cg.shared.global [%0], [%1], 16, %2;" :: "r"(dst), "l"(src), "r"(szz));
}
#define CP_COMMIT() asm volatile("cp.async.commit_group;")
#define MMA16816(d, a, b0_, b1_) \
    asm volatile("mma.sync.aligned.m16n8k16.row.col.f32.bf16.bf16.f32 " \
        "{%0,%1,%2,%3}, {%4,%5,%6,%7}, {%8,%9}, {%0,%1,%2,%3};" \
        : "+f"(d[0]), "+f"(d[1]), "+f"(d[2]), "+f"(d[3]) \
        : "r"(a[0]), "r"(a[1]), "r"(a[2]), "r"(a[3]), "r"(b0_), "r"(b1_))
#define MMAH16816(d, a, b0_, b1_) \
    asm volatile("mma.sync.aligned.m16n8k16.row.col.f32.f16.f16.f32 " \
        "{%0,%1,%2,%3}, {%4,%5,%6,%7}, {%8,%9}, {%0,%1,%2,%3};" \
        : "+f"(d[0]), "+f"(d[1]), "+f"(d[2]), "+f"(d[3]) \
        : "r"(a[0]), "r"(a[1]), "r"(a[2]), "r"(a[3]), "r"(b0_), "r"(b1_))

// ------------------------------ small fp32 GEMM (L1, L2) -------------------
__global__ void __launch_bounds__(128)
gemm_bias_leaky(const float* __restrict__ A, const float* __restrict__ W,
                const float* __restrict__ bias, float* __restrict__ C, int K, int N)
{
    __shared__ __align__(16) float As[16][128];
    __shared__ __align__(16) float Ws[16][64];
    const int tid = threadIdx.x, mt = tid & 15, nt = tid >> 4;
    const float* Ab = A + (size_t)blockIdx.x * 128 * K;
    const float* Wb = W + (size_t)blockIdx.y * 64 * K;
    float acc[8][8] = {};
    for (int k0 = 0; k0 < K; k0 += 16) {
        #pragma unroll
        for (int i = 0; i < 4; i++) {
            int lin = tid + i * 128, r = lin >> 2, c4 = lin & 3;
            float4 v = *(const float4*)(Ab + (size_t)r * K + k0 + c4 * 4);
            As[c4*4+0][r]=v.x; As[c4*4+1][r]=v.y; As[c4*4+2][r]=v.z; As[c4*4+3][r]=v.w;
        }
        #pragma unroll
        for (int i = 0; i < 2; i++) {
            int lin = tid + i * 128, r = lin >> 2, c4 = lin & 3;
            float4 v = *(const float4*)(Wb + (size_t)r * K + k0 + c4 * 4);
            Ws[c4*4+0][r]=v.x; Ws[c4*4+1][r]=v.y; Ws[c4*4+2][r]=v.z; Ws[c4*4+3][r]=v.w;
        }
        __syncthreads();
        #pragma unroll
        for (int kk = 0; kk < 16; kk++) {
            float a[8], w[8];
            *(float4*)&a[0] = *(const float4*)&As[kk][mt*8];
            *(float4*)&a[4] = *(const float4*)&As[kk][mt*8+4];
            *(float4*)&w[0] = *(const float4*)&Ws[kk][nt*8];
            *(float4*)&w[4] = *(const float4*)&Ws[kk][nt*8+4];
            #pragma unroll
            for (int i = 0; i < 8; i++)
                #pragma unroll
                for (int j = 0; j < 8; j++) acc[i][j] = fmaf(a[i], w[j], acc[i][j]);
        }
        __syncthreads();
    }
    float bv[8];
    #pragma unroll
    for (int j = 0; j < 8; j++) bv[j] = __ldg(&bias[blockIdx.y * 64 + nt * 8 + j]);
    #pragma unroll
    for (int i = 0; i < 8; i++) {
        size_t row = (size_t)(blockIdx.x*128 + mt*8 + i) * N + blockIdx.y*64 + nt*8;
        float4 o0, o1;
        o0.x=leaky(acc[i][0]+bv[0]); o0.y=leaky(acc[i][1]+bv[1]);
        o0.z=leaky(acc[i][2]+bv[2]); o0.w=leaky(acc[i][3]+bv[3]);
        o1.x=leaky(acc[i][4]+bv[4]); o1.y=leaky(acc[i][5]+bv[5]);
        o1.z=leaky(acc[i][6]+bv[6]); o1.w=leaky(acc[i][7]+bv[7]);
        *(float4*)&C[row] = o0; *(float4*)&C[row+4] = o1;
    }
}

// ---- elementwise fp32 -> hi/lo bf16 split (MLP operands) ------------------
__global__ void asplit(const float* __restrict__ x, __nv_bfloat16* __restrict__ h,
                       __nv_bfloat16* __restrict__ l, int n4)
{
    int i = blockIdx.x * 256 + threadIdx.x;
    if (i >= n4) return;
    float4 v = ((const float4*)x)[i];
    __nv_bfloat16 h0 = __float2bfloat16(v.x), h1 = __float2bfloat16(v.y);
    __nv_bfloat16 h2 = __float2bfloat16(v.z), h3 = __float2bfloat16(v.w);
    ((__nv_bfloat162*)h)[2*i]   = __nv_bfloat162(h0, h1);
    ((__nv_bfloat162*)h)[2*i+1] = __nv_bfloat162(h2, h3);
    ((__nv_bfloat162*)l)[2*i]   = __nv_bfloat162(__float2bfloat16(v.x - __bfloat162float(h0)),
                                                 __float2bfloat16(v.y - __bfloat162float(h1)));
    ((__nv_bfloat162*)l)[2*i+1] = __nv_bfloat162(__float2bfloat16(v.z - __bfloat162float(h2)),
                                                 __float2bfloat16(v.w - __bfloat162float(h3)));
}

// ---- conv W prep: w[o][c][kk] -> wA[o][kk*C+c], fp16 hi/lo split ----------
__global__ void wsplit(const float* __restrict__ w, __half* __restrict__ hi,
                       __half* __restrict__ lo, int C, int O)
{
    int i = blockIdx.x * 256 + threadIdx.x;
    int K3 = 3 * C;
    if (i >= O * K3) return;
    int o = i / K3, rem = i % K3, c = rem / 3, kk = rem % 3;
    float v = w[i];
    __half h = __float2half_rn(v);
    hi[o * K3 + kk * C + c] = h;
    lo[o * K3 + kk * C + c] = __float2half_rn(v - __half2float(h));
}

// ---- MLP out transpose -> fp16: x4[b][c][n] -> xf[b][n][c] (C=64) ---------
__global__ void __launch_bounds__(64)
thalf64(const float* __restrict__ x, __half* __restrict__ xf)
{
    __shared__ __align__(16) float s[64 * 64];
    const int b = blockIdx.x, t = threadIdx.x;
    const float4* src = (const float4*)(x + (size_t)b * 4096);
    float4* d4 = (float4*)s;
    for (int i = t; i < 1024; i += 64) d4[i] = src[i];
    __syncthreads();
    __align__(16) __half rh[64];
    #pragma unroll
    for (int c = 0; c < 64; c++) rh[c] = __float2half_rn(s[c * 64 + t]);
    uint4* dh = (uint4*)(xf + (size_t)b * 4096 + t * 64);
    #pragma unroll
    for (int q = 0; q < 8; q++) dh[q] = ((uint4*)rh)[q];
}

// ------------------- dense split-bf16 HMMA GEMM (MLP L3/L4) ----------------
__global__ void __launch_bounds__(256, 2)
gemm_hmma(const __nv_bfloat16* __restrict__ ah, const __nv_bfloat16* __restrict__ al,
          const __nv_bfloat16* __restrict__ wh_, const __nv_bfloat16* __restrict__ wl_,
          const float* __restrict__ bias, float* __restrict__ C, int K, int N)
{
    constexpr int GA = 9216, GW = 4608;
    extern __shared__ __align__(16) __nv_bfloat16 smg[];
    const int tid = threadIdx.x, wid = tid >> 5, lane = tid & 31;
    const int g = lane >> 2, t = lane & 3;
    const int wm = wid & 3, wh = wid >> 2;
    const int m0 = blockIdx.x * 128, n0 = blockIdx.y * 64;

    const uint32_t sA = smem_u32(smg);
    const uint32_t sAl = sA + GA * 2, sW = sA + 2 * GA * 2, sWl = sW + GW * 2;
    const int lrowA = lane & 15, lcolA = (lane >> 4) * 8;
    const int tb = lane >> 3;
    const int lrowB = (tb >> 1) * 8 + (lane & 7), lcolB = (tb & 1) * 8;

    float acc[2][4][4] = {};

    for (int kc = 0; kc < K; kc += 64) {
        __syncthreads();
        #pragma unroll
        for (int it = 0; it < 8; it++) {
            int u = tid + it * 256;
            int sp = u >> 10, r = (u >> 3) & 127, q = u & 7;
            const __nv_bfloat16* src = (sp ? al : ah) + (size_t)(m0 + r) * K + kc + q * 8;
            *(uint4*)(smg + sp * GA + r * 72 + q * 8) = *(const uint4*)src;
        }
        #pragma unroll
        for (int it = 0; it < 4; it++) {
            int u = tid + it * 256;
            int sp = u >> 9, r = (u >> 3) & 63, q = u & 7;
            const __nv_bfloat16* src = (sp ? wl_ : wh_) + (size_t)(n0 + r) * K + kc + q * 8;
            *(uint4*)(smg + 2 * GA + sp * GW + r * 72 + q * 8) = *(const uint4*)src;
        }
        __syncthreads();

        #pragma unroll
        for (int ks = 0; ks < 4; ks++) {
            const int koff = ks * 16;
            uint32_t fah[2][4], fal[2][4];
            #pragma unroll
            for (int mt = 0; mt < 2; mt++) {
                uint32_t off = ((wm * 32 + mt * 16 + lrowA) * 72 + koff + lcolA) * 2;
                ldsm4(fah[mt][0], fah[mt][1], fah[mt][2], fah[mt][3], sA + off);
                ldsm4(fal[mt][0], fal[mt][1], fal[mt][2], fal[mt][3], sAl + off);
            }
            #pragma unroll
            for (int p = 0; p < 2; p++) {
                uint32_t off = ((wh * 32 + p * 16 + lrowB) * 72 + koff + lcolB) * 2;
                uint32_t bh0, bh1, bh2, bh3, bl0, bl1, bl2, bl3;
                ldsm4(bh0, bh1, bh2, bh3, sW + off);
                ldsm4(bl0, bl1, bl2, bl3, sWl + off);
                #pragma unroll
                for (int mt = 0; mt < 2; mt++) {
                    MMA16816(acc[mt][2*p],   fah[mt], bh0, bh1);
                    MMA16816(acc[mt][2*p+1], fah[mt], bh2, bh3);
                }
                #pragma unroll
                for (int mt = 0; mt < 2; mt++) {
                    MMA16816(acc[mt][2*p],   fah[mt], bl0, bl1);
                    MMA16816(acc[mt][2*p+1], fah[mt], bl2, bl3);
                }
                #pragma unroll
                for (int mt = 0; mt < 2; mt++) {
                    MMA16816(acc[mt][2*p],   fal[mt], bh0, bh1);
                    MMA16816(acc[mt][2*p+1], fal[mt], bh2, bh3);
                }
            }
        }
    }

    #pragma unroll
    for (int mt = 0; mt < 2; mt++) {
        #pragma unroll
        for (int nt = 0; nt < 4; nt++) {
            int col = n0 + wh * 32 + nt * 8 + 2 * t;
            float bv0 = __ldg(&bias[col]), bv1 = __ldg(&bias[col + 1]);
            int row0 = m0 + wm * 32 + mt * 16 + g;
            *(float2*)&C[(size_t)row0 * N + col] =
                make_float2(leaky(acc[mt][nt][0] + bv0), leaky(acc[mt][nt][1] + bv1));
            *(float2*)&C[(size_t)(row0 + 8) * N + col] =
                make_float2(leaky(acc[mt][nt][2] + bv0), leaky(acc[mt][nt][3] + bv1));
        }
    }
}

// --- conv: fp16 2-pass HMMA ((Wh+Wl) x Bfp16), cp.async, 4 samples/CTA -----
// Warp = 64 M-rows x 64 N of one sample: si = wid>>1, mh = wid&1.
template <int C, int O>
__global__ void __launch_bounds__(256, 1)
conv_hmma(const __half* __restrict__ xf,
          const __half* __restrict__ whi, const __half* __restrict__ wlo,
          const int* __restrict__ idxg, const float* __restrict__ bias,
          float* __restrict__ pre, float2* __restrict__ part)
{
    constexpr int K3 = 3 * C, NCH = K3 / 64, CB = C / 64;
    constexpr int MTILES = O / 128;
    constexpr int BOFFH = 18432;             // halves: A hi(9216) + A lo(9216)
    constexpr int BBLK = 4608;               // halves per sample (fp16, hi only)
    constexpr int BUFH = BOFFH + 4 * BBLK;   // 36864 halves per buffer
    extern __shared__ __align__(16) __half smh[];
    int* idxs = (int*)(smh + 2 * BUFH);
    float2* spart = (float2*)(idxs + 4 * 192);

    const int tid = threadIdx.x, wid = tid >> 5, lane = tid & 31;
    const int g = lane >> 2, t = lane & 3;
    const int b0 = blockIdx.y * 4, obase = blockIdx.x * 128;
    const int si = wid >> 1, mh = wid & 1;
    const uint32_t sbase = smem_u32(smh);

    const int lrowA = lane & 15, lcolA = (lane >> 4) * 8;
    const int tb = lane >> 3;
    const int lrowB = (tb >> 1) * 8 + (lane & 7), lcolB = (tb & 1) * 8;

    for (int i = tid; i < 4 * 192; i += 256) {
        int s2 = i / 192, j = i % 192;
        idxs[i] = (j < 189) ? idxg[(size_t)(b0 + s2) * 189 + j] : 0;
    }
    __syncthreads();

    auto prefetch = [&](int ci, int buf) {
        const uint32_t base = sbase + buf * (BUFH * 2);
        #pragma unroll
        for (int it = 0; it < 8; it++) {
            int u = tid + it * 256;
            int sp = u >> 10, r = (u >> 3) & 127, q = u & 7;
            const __half* src = (sp ? wlo : whi) + (size_t)(obase + r) * K3 + ci * 64 + q * 8;
            cpasync16(base + (sp * 9216 + r * 72 + q * 8) * 2, src);
        }
        const int kk = ci / CB, c0 = (ci % CB) * 64;
        #pragma unroll
        for (int it = 0; it < 8; it++) {
            int u = tid + it * 256;
            int ss = u >> 9, n = (u >> 3) & 63, q = u & 7;
            int slot = (n > 0) ? idxs[ss * 192 + (n - 1) * 3 + kk] : 0;
            const __half* src = xf + ((size_t)(b0 + ss) * 64 + slot) * C + c0 + q * 8;
            cpasync16z(base + (BOFFH + ss * BBLK + n * 72 + q * 8) * 2, src,
                       (n > 0) ? 16 : 0);
        }
        CP_COMMIT();
    };

    float acc[4][8][4] = {};   // [mt][nt][frag], warp tile 64x64
    prefetch(0, 0);

    for (int ci = 0; ci < NCH; ci++) {
        if (ci + 1 < NCH) {
            prefetch(ci + 1, (ci + 1) & 1);
            asm volatile("cp.async.wait_group 1;");
        } else {
            asm volatile("cp.async.wait_group 0;");
        }
        __syncthreads();

        const uint32_t base = sbase + (ci & 1) * (BUFH * 2);
        const uint32_t sA = base, sAl = base + 9216 * 2;
        const uint32_t sB = base + (BOFFH + si * BBLK) * 2;

        #pragma unroll
        for (int ks = 0; ks < 4; ks++) {
            const int koff = ks * 16;
            uint32_t fah[4][4], fal[4][4], bh[4][4];
            #pragma unroll
            for (int mt = 0; mt < 4; mt++) {
                uint32_t off = ((mh * 64 + mt * 16 + lrowA) * 72 + koff + lcolA) * 2;
                ldsm4(fah[mt][0], fah[mt][1], fah[mt][2], fah[mt][3], sA + off);
                ldsm4(fal[mt][0], fal[mt][1], fal[mt][2], fal[mt][3], sAl + off);
            }
            #pragma unroll
            for (int p = 0; p < 4; p++) {
                uint32_t off = ((p * 16 + lrowB) * 72 + koff + lcolB) * 2;
                ldsm4(bh[p][0], bh[p][1], bh[p][2], bh[p][3], sB + off);
            }
            // pass 1: Wh * B
            #pragma unroll
            for (int p = 0; p < 4; p++)
                #pragma unroll
                for (int mt = 0; mt < 4; mt++) {
                    MMAH16816(acc[mt][2*p],   fah[mt], bh[p][0], bh[p][1]);
                    MMAH16816(acc[mt][2*p+1], fah[mt], bh[p][2], bh[p][3]);
                }
            // pass 2: Wl * B
            #pragma unroll
            for (int p = 0; p < 4; p++)
                #pragma unroll
                for (int mt = 0; mt < 4; mt++) {
                    MMAH16816(acc[mt][2*p],   fal[mt], bh[p][0], bh[p][1]);
                    MMAH16816(acc[mt][2*p+1], fal[mt], bh[p][2], bh[p][3]);
                }
        }
        __syncthreads();
    }

    // Epilogue: bias, stores, per-warp LN partial stats
    float s = 0.f, ss = 0.f;
    #pragma unroll
    for (int mt = 0; mt < 4; mt++) {
        int o0 = obase + mh * 64 + mt * 16 + g;
        float bv0 = __ldg(&bias[o0]), bv1 = __ldg(&bias[o0 + 8]);
        float* base0 = pre + ((size_t)(b0 + si) * O + o0) * 64;
        float* base1 = base0 + 8 * 64;
        #pragma unroll
        for (int nt = 0; nt < 8; nt++) {
            int n0 = nt * 8 + 2 * t;
            float m0 = (n0 == 0) ? 0.f : bv0;
            float m1 = (n0 == 0) ? 0.f : bv1;
            float v0 = acc[mt][nt][0] + m0, v1 = acc[mt][nt][1] + bv0;
            float v2 = acc[mt][nt][2] + m1, v3 = acc[mt][nt][3] + bv1;
            s  += (v0 + v1) + (v2 + v3);
            ss += (v0 * v0 + v1 * v1) + (v2 * v2 + v3 * v3);
            *(float2*)(base0 + n0) = make_float2(v0, v1);
            *(float2*)(base1 + n0) = make_float2(v2, v3);
        }
    }
    #pragma unroll
    for (int sh = 16; sh; sh >>= 1) {
        s  += __shfl_down_sync(0xffffffffu, s,  sh);
        ss += __shfl_down_sync(0xffffffffu, ss, sh);
    }
    if (lane == 0) spart[wid] = make_float2(s, ss);
    __syncthreads();
    if (tid < 4) {
        float2 p0 = spart[tid * 2], p1 = spart[tid * 2 + 1];
        part[(size_t)(b0 + tid) * MTILES + blockIdx.x] =
            make_float2(p0.x + p1.x, p0.y + p1.y);
    }
}

// ---- LN from partials + leaky + transpose -> fp16 activations -------------
template <int O>
__global__ void __launch_bounds__(256)
ln_split(const float* __restrict__ pre, const float2* __restrict__ part,
         __half* __restrict__ xf)
{
    constexpr int MT = O / 128;
    __shared__ __align__(16) __half sh[4096];
    const int b = blockIdx.x, tid = threadIdx.x;
    const float4* p4 = (const float4*)(pre + (size_t)b * O * 64);
    float S = 0.f, SS = 0.f;
    #pragma unroll
    for (int m = 0; m < MT; m++) {
        float2 p = __ldg(&part[(size_t)b * MT + m]);
        S += p.x; SS += p.y;
    }
    const float nn = (float)(O * 64);
    const float mean = S / nn;
    const float var = fmaxf((SS - nn * mean * mean) / (nn - 1.f), 0.f);
    const float scale = 1.f / (sqrtf(var) + 1e-5f);

    for (int ot = 0; ot < O / 64; ot++) {
        #pragma unroll 1
        for (int k = 0; k < 4; k++) {
            int u = tid + k * 256;
            int ol = u >> 4, n4 = u & 15;
            float4 v = p4[(ot * 64 + ol) * 16 + n4];
            #pragma unroll
            for (int j = 0; j < 4; j++) {
                float y = leaky(((&v.x)[j] - mean) * scale);
                sh[(n4 * 4 + j) * 64 + ol] = __float2half_rn(y);
            }
        }
        __syncthreads();
        #pragma unroll 1
        for (int k = 0; k < 2; k++) {
            int u = tid + k * 256;
            int n = u >> 3, q = u & 7;
            size_t base = (size_t)b * 64 * O + (size_t)n * O + ot * 64 + q * 8;
            *(uint4*)(xf + base) = *(uint4*)(sh + n * 64 + q * 8);
        }
        __syncthreads();
    }
}

// ---------------- final LN (from partials) + leaky -> d_out ----------------
__global__ void __launch_bounds__(256)
ln_final(const float* __restrict__ pre, const float2* __restrict__ part,
         float* __restrict__ out)
{
    constexpr int O = 512, MT = 4;
    const int b = blockIdx.x, tid = threadIdx.x;
    const float4* p4 = (const float4*)(pre + (size_t)b * O * 64);
    float4* o4 = (float4*)(out + (size_t)b * O * 64);
    float S = 0.f, SS = 0.f;
    #pragma unroll
    for (int m = 0; m < MT; m++) {
        float2 p = __ldg(&part[(size_t)b * MT + m]);
        S += p.x; SS += p.y;
    }
    const float nn = (float)(O * 64);
    const float mean = S / nn;
    const float var = fmaxf((SS - nn * mean * mean) / (nn - 1.f), 0.f);
    const float scale = 1.f / (sqrtf(var) + 1e-5f);
    for (int i = tid; i < O * 16; i += 256) {
        float4 v = p4[i];
        o4[i] = make_float4(leaky((v.x - mean) * scale), leaky((v.y - mean) * scale),
                            leaky((v.z - mean) * scale), leaky((v.w - mean) * scale));
    }
}

// ------------------------------ host launch --------------------------------
static constexpr int SMEM_CONV = 2 * 36864 * 2 + 4 * 192 * 4 + 8 * 8;      // 150592 B
static constexpr int SMEM_GEMM = (9216 * 2 + 4608 * 2) * 2;                // 55296 B

extern "C" void kernel_launch(void* const* d_in, const int* in_sizes, int n_in,
                              void* d_out, int out_size)
{
    const float* trees   = (const float*)d_in[0];
    const int*   indexes = (const int*)  d_in[1];
    const float* W1 = (const float*)d_in[2];  const float* b1 = (const float*)d_in[3];
    const float* W2 = (const float*)d_in[4];  const float* b2 = (const float*)d_in[5];
    const float* W3 = (const float*)d_in[6];  const float* b3 = (const float*)d_in[7];
    const float* W4 = (const float*)d_in[8];  const float* b4 = (const float*)d_in[9];
    const float* cw1 = (const float*)d_in[10]; const float* cb1 = (const float*)d_in[11];
    const float* cw2 = (const float*)d_in[12]; const float* cb2 = (const float*)d_in[13];
    const float* cw3 = (const float*)d_in[14]; const float* cb3 = (const float*)d_in[15];

    float *x1, *x2, *x3, *x4, *pre;
    float2* part;
    __half *xf, *w1h, *w1l, *w2h, *w2l, *w3h, *w3l;
    __nv_bfloat16 *ma_h, *ma_l, *mw3h, *mw3l, *mw4h, *mw4l;
    cudaGetSymbolAddress((void**)&x1, g_x1);
    cudaGetSymbolAddress((void**)&x2, g_x2);
    cudaGetSymbolAddress((void**)&x3, g_x3);
    cudaGetSymbolAddress((void**)&x4, g_x4);
    cudaGetSymbolAddress((void**)&pre, g_pre);
    cudaGetSymbolAddress((void**)&part, g_part);
    cudaGetSymbolAddress((void**)&xf, g_xf);
    cudaGetSymbolAddress((void**)&w1h, g_w1h); cudaGetSymbolAddress((void**)&w1l, g_w1l);
    cudaGetSymbolAddress((void**)&w2h, g_w2h); cudaGetSymbolAddress((void**)&w2l, g_w2l);
    cudaGetSymbolAddress((void**)&w3h, g_w3h); cudaGetSymbolAddress((void**)&w3l, g_w3l);
    cudaGetSymbolAddress((void**)&ma_h, g_ah); cudaGetSymbolAddress((void**)&ma_l, g_al);
    cudaGetSymbolAddress((void**)&mw3h, g_mw3h); cudaGetSymbolAddress((void**)&mw3l, g_mw3l);
    cudaGetSymbolAddress((void**)&mw4h, g_mw4h); cudaGetSymbolAddress((void**)&mw4l, g_mw4l);

    cudaFuncSetAttribute(conv_hmma<64, 128>,  cudaFuncAttributeMaxDynamicSharedMemorySize, SMEM_CONV);
    cudaFuncSetAttribute(conv_hmma<128, 256>, cudaFuncAttributeMaxDynamicSharedMemorySize, SMEM_CONV);
    cudaFuncSetAttribute(conv_hmma<256, 512>, cudaFuncAttributeMaxDynamicSharedMemorySize, SMEM_CONV);
    cudaFuncSetAttribute(gemm_hmma, cudaFuncAttributeMaxDynamicSharedMemorySize, SMEM_GEMM);

    // weight prep
    wsplit<<<96,   256>>>(cw1, w1h, w1l, 64, 128);
    wsplit<<<384,  256>>>(cw2, w2h, w2l, 128, 256);
    wsplit<<<1536, 256>>>(cw3, w3h, w3l, 256, 512);
    asplit<<<256,  256>>>(W3, mw3h, mw3l, 1024 * 256 / 4);
    asplit<<<4096, 256>>>(W4, mw4h, mw4l, 4096 * 1024 / 4);

    // MLP: L1, L2 fp32 (tiny); L3, L4 tensor (bf16 3-pass)
    gemm_bias_leaky<<<dim3(32, 1), 128>>>(trees, W1, b1, x1, 16, 64);
    gemm_bias_leaky<<<dim3(32, 4), 128>>>(x1,    W2, b2, x2, 64, 256);
    asplit<<<1024, 256>>>(x2, ma_h, ma_l, 4096 * 256 / 4);
    gemm_hmma<<<dim3(32, 16), 256, SMEM_GEMM>>>(ma_h, ma_l, mw3h, mw3l, b3, x3, 256, 1024);
    asplit<<<4096, 256>>>(x3, ma_h, ma_l, 4096 * 1024 / 4);
    gemm_hmma<<<dim3(32, 64), 256, SMEM_GEMM>>>(ma_h, ma_l, mw4h, mw4l, b4, x4, 1024, 4096);

    // transpose MLP output -> fp16 activations (C=64)
    thalf64<<<4096, 64>>>(x4, xf);

    // conv1 -> LN -> conv2 -> LN -> conv3 -> LN(final); fp16 2-pass convs
    conv_hmma<64, 128> <<<dim3(1, 1024), 256, SMEM_CONV>>>(xf, w1h, w1l, indexes, cb1, pre, part);
    ln_split<128><<<4096, 256>>>(pre, part, xf);
    conv_hmma<128, 256><<<dim3(2, 1024), 256, SMEM_CONV>>>(xf, w2h, w2l, indexes, cb2, pre, part);
    ln_split<256><<<4096, 256>>>(pre, part, xf);
    conv_hmma<256, 512><<<dim3(4, 1024), 256, SMEM_CONV>>>(xf, w3h, w3l, indexes, cb3, pre, part);
    ln_final<<<4096, 256>>>(pre, part, (float*)d_out);
}